// round 7
// baseline (speedup 1.0000x reference)
#include <cuda_runtime.h>

#define BI   256
#define TT   1632
#define T1   816
#define T2   408
#define HIDD 64
#define CBD  512
#define NTOK 1024
#define NTOKEN (BI*T2)   /* 104448 */
#define M1     (BI*T1)   /* 208896 */

#define OUT_N   (BI*TT)                 /* 417792 */
#define IDX_OFF (OUT_N + 3)             /* 417795 */
#define QOFF    (IDX_OFF + NTOKEN*2)    /* 626691 */

// ---------------- scratch (__device__ globals; no runtime allocation) ----------
__device__ float g_H1[(size_t)M1 * HIDD];        // 53.5 MB : h1 [b][t1][i]; reused as D1
__device__ float g_H2[(size_t)NTOKEN * HIDD];    // 26.7 MB : h2 [tok][i]
__device__ float g_X [(size_t)NTOKEN * CBD];     // 214 MB  : encoded tokens; reused as D2
__device__ float g_R2[(size_t)NTOKEN * CBD];     // 214 MB  : residual2; reused as Qt
__device__ unsigned long long g_best0[NTOKEN];
__device__ unsigned long long g_best1[NTOKEN];
__device__ float  g_cnorm[2 * NTOK];
__device__ float  g_W2m [64 * 128];
__device__ float  g_Wd1m[128 * 512];
__device__ float  g_Wd2m[128 * 64];
__device__ float  g_bd1x[128];
__device__ float  g_bd2x[128];
__device__ double g_acc[3];   // loss0, loss1, recon

// ---------------- init ---------------------------------------------------------
__global__ void k_init() {
    int i = blockIdx.x * 256 + threadIdx.x;
    if (i < NTOKEN) { g_best0[i] = ~0ULL; g_best1[i] = ~0ULL; }
    if (i < 3) g_acc[i] = 0.0;
}

// ---------------- weight repack -------------------------------------------------
__global__ void k_repack(const float* __restrict__ W_e2,
                         const float* __restrict__ Wt_d1,
                         const float* __restrict__ Wt_d2,
                         const float* __restrict__ b_d1,
                         const float* __restrict__ b_d2) {
    int i = blockIdx.x * 256 + threadIdx.x;      // 0..65535
    if (i < 64 * 128) {                          // W2m[o][k*64+ii] = W_e2[o][ii][k]
        int o = i >> 7, c = i & 127, k = c >> 6, ii = c & 63;
        g_W2m[i] = W_e2[(o * 64 + ii) * 2 + k];
    }
    if (i < 128 * 512) {                         // Wd1m[k*64+o][d] = Wt_d1[d][o][k]
        int n = i >> 9, d = i & 511;
        int k = n >> 6, o = n & 63;
        g_Wd1m[i] = Wt_d1[(d * 64 + o) * 2 + k];
    }
    if (i < 128 * 64) {                          // Wd2m[k*64+o][d] = Wt_d2[d][o][k]
        int n = i >> 6, d = i & 63;
        int k = n >> 6, o = n & 63;
        g_Wd2m[i] = Wt_d2[(d * 64 + o) * 2 + k];
    }
    if (i < 128) { g_bd1x[i] = b_d1[i & 63]; g_bd2x[i] = b_d2[i & 63]; }
}

// ---------------- codebook row norms --------------------------------------------
__global__ void k_cnorm(const float* __restrict__ cb) {
    int row = blockIdx.x * 8 + (threadIdx.x >> 5);
    int lane = threadIdx.x & 31;
    if (row >= 2 * NTOK) return;
    const float* r = cb + (size_t)row * CBD;
    float s = 0.f;
    for (int d = lane; d < CBD; d += 32) { float v = r[d]; s = fmaf(v, v, s); }
    #pragma unroll
    for (int o = 16; o; o >>= 1) s += __shfl_xor_sync(0xffffffffu, s, o);
    if (!lane) g_cnorm[row] = s;
}

// ---------------- encoder conv1 (k=2,s=2), channel-contiguous output ------------
__global__ void k_enc1(const float* __restrict__ img,
                       const float* __restrict__ W,
                       const float* __restrict__ bias) {
    int idx = blockIdx.x * 256 + threadIdx.x;    // over M1*64, exact
    int tok = idx >> 6, i = idx & 63;
    int b = tok / T1, t = tok % T1;
    float x0 = img[(size_t)b * TT + 2 * t];
    float x1 = img[(size_t)b * TT + 2 * t + 1];
    float v = fmaf(W[i * 2], x0, fmaf(W[i * 2 + 1], x1, bias[i]));
    g_H1[idx] = fmaxf(v, 0.f);
}

// ---------------- generic 128x128x(K) SGEMM; epilogue = store(+bias,+relu) or argmin
// A [M x K] row-major, Bm [N x K] row-major (dot of rows). grid=(nTilesN, nTilesM).
template<int ARGMIN, int RELU>
__global__ void __launch_bounds__(256) k_gemm(
    const float* __restrict__ A, const float* __restrict__ Bm,
    float* __restrict__ C, unsigned long long* __restrict__ best,
    const float* __restrict__ aux,   // bias[N] (store) or cnorm[N] (argmin)
    int N, int K)
{
    __shared__ float As[8][132];
    __shared__ float Bs[8][132];
    __shared__ unsigned long long sb[128];
    const int tid = threadIdx.x;
    const int tx = tid & 15, ty = tid >> 4;
    const int bn = blockIdx.x, bm = blockIdx.y;

    float acc[8][8];
    #pragma unroll
    for (int i = 0; i < 8; i++)
        #pragma unroll
        for (int j = 0; j < 8; j++) acc[i][j] = 0.f;

    const int lr = tid >> 1;
    const int lc = (tid & 1) * 4;
    const float* Ap = A + (size_t)(bm * 128 + lr) * K + lc;
    const float* Bp = Bm + (size_t)(bn * 128 + lr) * K + lc;
    const bool bvalid = (bn * 128 + lr) < N;

    for (int k0 = 0; k0 < K; k0 += 8) {
        float4 av = *(const float4*)(Ap + k0);
        float4 bv = bvalid ? *(const float4*)(Bp + k0) : make_float4(0.f, 0.f, 0.f, 0.f);
        As[lc + 0][lr] = av.x; As[lc + 1][lr] = av.y; As[lc + 2][lr] = av.z; As[lc + 3][lr] = av.w;
        Bs[lc + 0][lr] = bv.x; Bs[lc + 1][lr] = bv.y; Bs[lc + 2][lr] = bv.z; Bs[lc + 3][lr] = bv.w;
        __syncthreads();
        #pragma unroll
        for (int kk = 0; kk < 8; kk++) {
            float4 a0 = *(const float4*)&As[kk][ty * 4];
            float4 a1 = *(const float4*)&As[kk][64 + ty * 4];
            float4 b0 = *(const float4*)&Bs[kk][tx * 4];
            float4 b1 = *(const float4*)&Bs[kk][64 + tx * 4];
            float a[8] = {a0.x, a0.y, a0.z, a0.w, a1.x, a1.y, a1.z, a1.w};
            float b[8] = {b0.x, b0.y, b0.z, b0.w, b1.x, b1.y, b1.z, b1.w};
            #pragma unroll
            for (int i = 0; i < 8; i++)
                #pragma unroll
                for (int j = 0; j < 8; j++)
                    acc[i][j] = fmaf(a[i], b[j], acc[i][j]);
        }
        __syncthreads();
    }

    if (ARGMIN) {
        if (tid < 128) sb[tid] = ~0ULL;
        __syncthreads();
        #pragma unroll
        for (int i = 0; i < 8; i++) {
            int rloc = (i < 4) ? (ty * 4 + i) : (64 + ty * 4 + i - 4);
            unsigned long long bk = ~0ULL;
            #pragma unroll
            for (int j = 0; j < 8; j++) {
                int c = bn * 128 + ((j < 4) ? (tx * 4 + j) : (64 + tx * 4 + j - 4));
                float s = fmaf(-2.f, acc[i][j], aux[c]);   // ||c||^2 - 2 r.c
                unsigned u = __float_as_uint(s);
                u = (u & 0x80000000u) ? ~u : (u | 0x80000000u);
                unsigned long long key = ((unsigned long long)u << 32) | (unsigned)c;
                bk = key < bk ? key : bk;
            }
            atomicMin(&sb[rloc], bk);
        }
        __syncthreads();
        if (tid < 128) atomicMin(&best[bm * 128 + tid], sb[tid]);
    } else {
        #pragma unroll
        for (int i = 0; i < 8; i++) {
            int r = bm * 128 + ((i < 4) ? (ty * 4 + i) : (64 + ty * 4 + i - 4));
            #pragma unroll
            for (int jj = 0; jj < 2; jj++) {
                int c0 = (jj == 0) ? (tx * 4) : (64 + tx * 4);
                if (bn * 128 + c0 < N) {
                    int cg = bn * 128 + c0;
                    float4 v;
                    v.x = acc[i][jj * 4 + 0] + aux[cg + 0];
                    v.y = acc[i][jj * 4 + 1] + aux[cg + 1];
                    v.z = acc[i][jj * 4 + 2] + aux[cg + 2];
                    v.w = acc[i][jj * 4 + 3] + aux[cg + 3];
                    if (RELU) {
                        v.x = fmaxf(v.x, 0.f); v.y = fmaxf(v.y, 0.f);
                        v.z = fmaxf(v.z, 0.f); v.w = fmaxf(v.w, 0.f);
                    }
                    *(float4*)(C + (size_t)r * N + cg) = v;
                }
            }
        }
    }
}

// ---------------- residual2 = x - cb0[idx0] --------------------------------------
__global__ void k_r2(const float* __restrict__ cb0) {
    size_t idx = (size_t)blockIdx.x * 256 + threadIdx.x;  // over NTOKEN*128 float4, exact
    int t = (int)(idx >> 7), d4 = (int)(idx & 127);
    int i0 = (int)(g_best0[t] & 0xFFFFFFFFULL);
    float4 x = ((const float4*)g_X)[idx];
    float4 c = ((const float4*)(cb0 + (size_t)i0 * CBD))[d4];
    float4 r; r.x = x.x - c.x; r.y = x.y - c.y; r.z = x.z - c.z; r.w = x.w - c.w;
    ((float4*)g_R2)[idx] = r;
}

// ---------------- quantized (straight-through), commit losses, indices ----------
__global__ void __launch_bounds__(256) k_finalize(const float* __restrict__ cb,
                                                  float* __restrict__ dout) {
    int tid = threadIdx.x;
    double l0 = 0.0, l1 = 0.0;
    float* didx = dout + IDX_OFF;
    int t0 = blockIdx.x * 128;
    for (int tt = 0; tt < 128; tt++) {
        int t = t0 + tt;
        int i0 = (int)(g_best0[t] & 0xFFFFFFFFULL);
        int i1 = (int)(g_best1[t] & 0xFFFFFFFFULL);
        if (tid == 0) { didx[2 * t] = (float)i0; didx[2 * t + 1] = (float)i1; }
        float2 x  = ((const float2*)(g_X + (size_t)t * CBD))[tid];
        float2 q0 = ((const float2*)(cb + (size_t)i0 * CBD))[tid];
        float2 q1 = ((const float2*)(cb + ((size_t)NTOK + i1) * CBD))[tid];
        float r2x = x.x - q0.x, r2y = x.y - q0.y;
        float qsx = (x.x + (q0.x - x.x)) + (r2x + (q1.x - r2x));
        float qsy = (x.y + (q0.y - x.y)) + (r2y + (q1.y - r2y));
        ((float2*)(g_R2 + (size_t)t * CBD))[tid] = make_float2(qsx, qsy);
        float e0x = q0.x - x.x, e0y = q0.y - x.y;
        float e1x = q1.x - r2x, e1y = q1.y - r2y;
        l0 += (double)e0x * e0x + (double)e0y * e0y;
        l1 += (double)e1x * e1x + (double)e1y * e1y;
    }
    __shared__ double s0[256], s1[256];
    s0[tid] = l0; s1[tid] = l1; __syncthreads();
    for (int o = 128; o; o >>= 1) {
        if (tid < o) { s0[tid] += s0[tid + o]; s1[tid] += s1[tid + o]; }
        __syncthreads();
    }
    if (!tid) { atomicAdd(&g_acc[0], s0[0]); atomicAdd(&g_acc[1], s1[0]); }
}

// ---------------- quantized output transpose [tok][d] -> [b][d][t] --------------
__global__ void k_transpose(float* __restrict__ outq) {
    __shared__ float tile[32][33];
    int b = blockIdx.z;
    int t0 = blockIdx.x * 32, d0 = blockIdx.y * 32;
    int tx = threadIdx.x, ty = threadIdx.y;        // 32 x 8
    #pragma unroll
    for (int i = 0; i < 4; i++) {
        int t = t0 + ty + i * 8;
        if (t < T2) tile[ty + i * 8][tx] = g_R2[((size_t)b * T2 + t) * CBD + d0 + tx];
    }
    __syncthreads();
    #pragma unroll
    for (int i = 0; i < 4; i++) {
        int d = d0 + ty + i * 8;
        int t = t0 + tx;
        if (t < T2) outq[((size_t)b * CBD + d) * T2 + t] = tile[tx][ty + i * 8];
    }
}

// ---------------- final 1x1 conv + recon loss ------------------------------------
__global__ void __launch_bounds__(256) k_final(const float* __restrict__ img,
                                               const float* __restrict__ W3,
                                               const float* __restrict__ b3,
                                               float* __restrict__ dout) {
    __shared__ float w[64];
    int tid = threadIdx.x;
    if (tid < 64) w[tid] = W3[tid];
    __syncthreads();
    size_t idx = (size_t)blockIdx.x * 256 + tid;   // over B*TT, exact
    const float* row = g_X + idx * 64;             // D2 lives in g_X
    float s = b3[0];
    #pragma unroll
    for (int i = 0; i < 64; i += 4) {
        float4 v = *(const float4*)(row + i);
        s = fmaf(v.x, w[i], s);     s = fmaf(v.y, w[i + 1], s);
        s = fmaf(v.z, w[i + 2], s); s = fmaf(v.w, w[i + 3], s);
    }
    dout[idx] = s;
    float e = img[idx] - s;
    __shared__ double sd[256];
    sd[tid] = (double)e * e; __syncthreads();
    for (int o = 128; o; o >>= 1) { if (tid < o) sd[tid] += sd[tid + o]; __syncthreads(); }
    if (!tid) atomicAdd(&g_acc[2], sd[0]);
}

__global__ void k_scalars(float* __restrict__ dout) {
    dout[OUT_N + 0] = (float)(g_acc[2] / (double)OUT_N);
    dout[OUT_N + 1] = (float)(g_acc[0] / ((double)NTOKEN * CBD));
    dout[OUT_N + 2] = (float)(g_acc[1] / ((double)NTOKEN * CBD));
}

// ---------------- launch ----------------------------------------------------------
extern "C" void kernel_launch(void* const* d_in, const int* in_sizes, int n_in,
                              void* d_out, int out_size) {
    const float* img   = (const float*)d_in[0];
    const float* W_e1  = (const float*)d_in[1];
    const float* b_e1  = (const float*)d_in[2];
    const float* W_e2  = (const float*)d_in[3];
    const float* b_e2  = (const float*)d_in[4];
    const float* W_e3  = (const float*)d_in[5];
    const float* b_e3  = (const float*)d_in[6];
    const float* cb    = (const float*)d_in[7];
    const float* Wt_d1 = (const float*)d_in[8];
    const float* b_d1  = (const float*)d_in[9];
    const float* Wt_d2 = (const float*)d_in[10];
    const float* b_d2  = (const float*)d_in[11];
    const float* W_d3  = (const float*)d_in[12];
    const float* b_d3  = (const float*)d_in[13];
    float* out = (float*)d_out;

    float *pH1, *pH2, *pX, *pR2, *pW2m, *pWd1m, *pWd2m, *pbd1, *pbd2, *pcn;
    unsigned long long *pb0, *pb1;
    cudaGetSymbolAddress((void**)&pH1,   g_H1);
    cudaGetSymbolAddress((void**)&pH2,   g_H2);
    cudaGetSymbolAddress((void**)&pX,    g_X);
    cudaGetSymbolAddress((void**)&pR2,   g_R2);
    cudaGetSymbolAddress((void**)&pW2m,  g_W2m);
    cudaGetSymbolAddress((void**)&pWd1m, g_Wd1m);
    cudaGetSymbolAddress((void**)&pWd2m, g_Wd2m);
    cudaGetSymbolAddress((void**)&pbd1,  g_bd1x);
    cudaGetSymbolAddress((void**)&pbd2,  g_bd2x);
    cudaGetSymbolAddress((void**)&pcn,   g_cnorm);
    cudaGetSymbolAddress((void**)&pb0,   g_best0);
    cudaGetSymbolAddress((void**)&pb1,   g_best1);

    k_init  <<<(NTOKEN + 255) / 256, 256>>>();
    k_repack<<<256, 256>>>(W_e2, Wt_d1, Wt_d2, b_d1, b_d2);
    k_cnorm <<<256, 256>>>(cb);
    k_enc1  <<<M1 * HIDD / 256, 256>>>(img, W_e1, b_e1);

    // encoder conv2 as GEMM: [104448 x 128] x [128 x 64], relu
    k_gemm<0, 1><<<dim3(1, 816), 256>>>(pH1, pW2m, pH2, nullptr, b_e2, 64, 128);
    // encoder 1x1: [104448 x 64] x [64 x 512] -> X
    k_gemm<0, 0><<<dim3(4, 816), 256>>>(pH2, W_e3, pX, nullptr, b_e3, 512, 64);
    // VQ stage 0: argmin over codebook 0
    k_gemm<1, 0><<<dim3(8, 816), 256>>>(pX, cb, nullptr, pb0, pcn, 1024, 512);
    // residual2
    k_r2<<<NTOKEN * 128 / 256, 256>>>(cb);
    // VQ stage 1: argmin over codebook 1
    k_gemm<1, 0><<<dim3(8, 816), 256>>>(pR2, cb + (size_t)NTOK * CBD, nullptr, pb1,
                                        pcn + NTOK, 1024, 512);
    // quantized tokens (into g_R2), indices, commit losses
    k_finalize<<<816, 256>>>(cb, out);
    // quantized output, transposed to [b][c][t]
    k_transpose<<<dim3(13, 16, 256), dim3(32, 8)>>>(out + QOFF);
    // decoder convT1: [104448 x 512] x [512 x 128], relu -> D1 (in g_H1)
    k_gemm<0, 1><<<dim3(1, 816), 256>>>(pR2, pWd1m, pH1, nullptr, pbd1, 128, 512);
    // decoder convT2: [208896 x 64] x [64 x 128], relu -> D2 (in g_X)
    k_gemm<0, 1><<<dim3(1, 1632), 256>>>(pH1, pWd2m, pX, nullptr, pbd2, 128, 64);
    // final 1x1 conv + recon loss
    k_final<<<OUT_N / 256, 256>>>(img, W_d3, b_d3, out);
    k_scalars<<<1, 1>>>(out);
}

// round 8
// speedup vs baseline: 2.7742x; 2.7742x over previous
#include <cuda_runtime.h>

#define BI   256
#define TT   1632
#define T1   816
#define T2   408
#define HIDD 64
#define CBD  512
#define NTOK 1024
#define NTOKEN (BI*T2)   /* 104448 */
#define M1     (BI*T1)   /* 208896 */

#define OUT_N   (BI*TT)                 /* 417792 */
#define IDX_OFF (OUT_N + 3)             /* 417795 */
#define QOFF    (IDX_OFF + NTOKEN*2)    /* 626691 */

// ---------------- scratch (__device__ globals; no runtime allocation) ----------
__device__ float g_H1[(size_t)M1 * HIDD];        // h1 [b][t1][i]; reused as D1
__device__ float g_H2[(size_t)NTOKEN * HIDD];    // h2 [tok][i]
__device__ float g_X [(size_t)NTOKEN * CBD];     // encoded tokens; reused as D2
__device__ float g_R2[(size_t)NTOKEN * CBD];     // quantized tokens (Qt)
__device__ unsigned long long g_best0[NTOKEN];
__device__ unsigned long long g_best1[NTOKEN];
__device__ float  g_gamma[2 * NTOK];             // ||c||^2 - 2 b_e3.c
__device__ float  g_WT3 [64 * 512];              // W_e3 transposed [i][d]
__device__ float  g_Chat[2 * NTOK * 64];         // C . W_e3  [2048][64]
__device__ float  g_G   [(size_t)NTOK * NTOK];   // C0 . C1^T [1024][1024]
__device__ float  g_zero[1024];                  // stays zero
__device__ float  g_W2m [64 * 128];
__device__ float  g_Wd1m[128 * 512];
__device__ float  g_Wd2m[128 * 64];
__device__ float  g_bd1x[128];
__device__ float  g_bd2x[128];
__device__ double g_acc[3];   // loss0, loss1, recon

// ---------------- f32x2 packed helpers ------------------------------------------
__device__ __forceinline__ unsigned long long pk2(float lo, float hi) {
    unsigned long long r;
    asm("mov.b64 %0, {%1,%2};" : "=l"(r) : "f"(lo), "f"(hi));
    return r;
}
__device__ __forceinline__ float2 upk2(unsigned long long v) {
    float2 r;
    asm("mov.b64 {%0,%1}, %2;" : "=f"(r.x), "=f"(r.y) : "l"(v));
    return r;
}
__device__ __forceinline__ void fma2(unsigned long long& d,
                                     unsigned long long a, unsigned long long b) {
    asm("fma.rn.f32x2 %0, %1, %2, %0;" : "+l"(d) : "l"(a), "l"(b));
}

// ---------------- init ---------------------------------------------------------
__global__ void k_init() {
    int i = blockIdx.x * 256 + threadIdx.x;
    if (i < NTOKEN) { g_best0[i] = ~0ULL; g_best1[i] = ~0ULL; }
    if (i < 3) g_acc[i] = 0.0;
}

// ---------------- weight repack -------------------------------------------------
__global__ void k_repack(const float* __restrict__ W_e2,
                         const float* __restrict__ W_e3,
                         const float* __restrict__ Wt_d1,
                         const float* __restrict__ Wt_d2,
                         const float* __restrict__ b_d1,
                         const float* __restrict__ b_d2) {
    int i = blockIdx.x * 256 + threadIdx.x;      // 0..65535
    if (i < 64 * 128) {                          // W2m[o][k*64+ii] = W_e2[o][ii][k]
        int o = i >> 7, c = i & 127, k = c >> 6, ii = c & 63;
        g_W2m[i] = W_e2[(o * 64 + ii) * 2 + k];
    }
    if (i < 64 * 512) {                          // WT3[ii][d] = W_e3[d][ii]
        int r = i >> 9, d = i & 511;
        g_WT3[i] = W_e3[d * 64 + r];
    }
    if (i < 128 * 512) {                         // Wd1m[k*64+o][d] = Wt_d1[d][o][k]
        int n = i >> 9, d = i & 511;
        int k = n >> 6, o = n & 63;
        g_Wd1m[i] = Wt_d1[(d * 64 + o) * 2 + k];
    }
    if (i < 128 * 64) {                          // Wd2m[k*64+o][d] = Wt_d2[d][o][k]
        int n = i >> 6, d = i & 63;
        int k = n >> 6, o = n & 63;
        g_Wd2m[i] = Wt_d2[(d * 64 + o) * 2 + k];
    }
    if (i < 128) { g_bd1x[i] = b_d1[i & 63]; g_bd2x[i] = b_d2[i & 63]; }
}

// ---------------- gamma = ||c||^2 - 2 b_e3.c ------------------------------------
__global__ void k_gamma(const float* __restrict__ cb, const float* __restrict__ be3) {
    int row = blockIdx.x * 8 + (threadIdx.x >> 5);
    int lane = threadIdx.x & 31;
    if (row >= 2 * NTOK) return;
    const float* r = cb + (size_t)row * CBD;
    float s = 0.f, t = 0.f;
    for (int d = lane; d < CBD; d += 32) {
        float v = r[d];
        s = fmaf(v, v, s);
        t = fmaf(v, be3[d], t);
    }
    #pragma unroll
    for (int o = 16; o; o >>= 1) {
        s += __shfl_xor_sync(0xffffffffu, s, o);
        t += __shfl_xor_sync(0xffffffffu, t, o);
    }
    if (!lane) g_gamma[row] = s - 2.f * t;
}

// ---------------- encoder conv1 (k=2,s=2), channel-contiguous output ------------
__global__ void k_enc1(const float* __restrict__ img,
                       const float* __restrict__ W,
                       const float* __restrict__ bias) {
    int idx = blockIdx.x * 256 + threadIdx.x;    // over M1*64, exact
    int tok = idx >> 6, i = idx & 63;
    int b = tok / T1, t = tok % T1;
    float x0 = img[(size_t)b * TT + 2 * t];
    float x1 = img[(size_t)b * TT + 2 * t + 1];
    float v = fmaf(W[i * 2], x0, fmaf(W[i * 2 + 1], x1, bias[i]));
    g_H1[idx] = fmaxf(v, 0.f);
}

// ---------------- generic 128x128x(K) SGEMM (f32x2 packed FMA)
// MODE: 0 = store(+bias), 1 = store(+bias,+relu), 2 = argmin, 3 = argmin + 2*G[i0][n]
// A [M x K] row-major, Bm [N x K] row-major (dot of rows). grid=(nTilesN, nTilesM).
template<int MODE>
__global__ void __launch_bounds__(256) k_gemm(
    const float* __restrict__ A, const float* __restrict__ Bm,
    float* __restrict__ C, unsigned long long* __restrict__ best,
    const float* __restrict__ aux,   // bias[N] (store) or gamma[N] (argmin)
    const float* __restrict__ G,     // [1024][1024] for MODE 3
    const unsigned long long* __restrict__ best0prev,
    int N, int K)
{
    __shared__ float As[8][132];
    __shared__ float Bs[8][132];
    __shared__ unsigned long long sb[128];
    __shared__ int sI0[128];
    const int tid = threadIdx.x;
    const int tx = tid & 15, ty = tid >> 4;
    const int bn = blockIdx.x, bm = blockIdx.y;

    if (MODE >= 2) {
        if (tid < 128) {
            sb[tid] = ~0ULL;
            if (MODE == 3) sI0[tid] = (int)(best0prev[bm * 128 + tid] & 0xFFFFFFFFULL);
        }
    }

    unsigned long long acc2[8][4];
    #pragma unroll
    for (int i = 0; i < 8; i++)
        #pragma unroll
        for (int j = 0; j < 4; j++) acc2[i][j] = 0ULL;

    const int lr = tid >> 1;
    const int lc = (tid & 1) * 4;
    const float* Ap = A + (size_t)(bm * 128 + lr) * K + lc;
    const float* Bp = Bm + (size_t)(bn * 128 + lr) * K + lc;
    const bool bvalid = (bn * 128 + lr) < N;

    for (int k0 = 0; k0 < K; k0 += 8) {
        float4 av = *(const float4*)(Ap + k0);
        float4 bv = bvalid ? *(const float4*)(Bp + k0) : make_float4(0.f, 0.f, 0.f, 0.f);
        As[lc + 0][lr] = av.x; As[lc + 1][lr] = av.y; As[lc + 2][lr] = av.z; As[lc + 3][lr] = av.w;
        Bs[lc + 0][lr] = bv.x; Bs[lc + 1][lr] = bv.y; Bs[lc + 2][lr] = bv.z; Bs[lc + 3][lr] = bv.w;
        __syncthreads();
        #pragma unroll
        for (int kk = 0; kk < 8; kk++) {
            float4 a0 = *(const float4*)&As[kk][ty * 4];
            float4 a1 = *(const float4*)&As[kk][64 + ty * 4];
            float4 b0 = *(const float4*)&Bs[kk][tx * 4];
            float4 b1 = *(const float4*)&Bs[kk][64 + tx * 4];
            float a[8] = {a0.x, a0.y, a0.z, a0.w, a1.x, a1.y, a1.z, a1.w};
            unsigned long long bp[4] = {pk2(b0.x, b0.y), pk2(b0.z, b0.w),
                                        pk2(b1.x, b1.y), pk2(b1.z, b1.w)};
            #pragma unroll
            for (int i = 0; i < 8; i++) {
                unsigned long long ap = pk2(a[i], a[i]);
                #pragma unroll
                for (int j = 0; j < 4; j++) fma2(acc2[i][j], ap, bp[j]);
            }
        }
        __syncthreads();
    }

    if (MODE >= 2) {
        #pragma unroll
        for (int i = 0; i < 8; i++) {
            int rloc = (i < 4) ? (ty * 4 + i) : (64 + ty * 4 + i - 4);
            const float* Grow = (MODE == 3) ? (G + (size_t)sI0[rloc] * NTOK) : nullptr;
            unsigned long long bk = ~0ULL;
            #pragma unroll
            for (int q = 0; q < 4; q++) {
                float2 p = upk2(acc2[i][q]);
                int cbase = bn * 128 + ((q < 2) ? (tx * 4 + q * 2) : (64 + tx * 4 + (q - 2) * 2));
                #pragma unroll
                for (int h = 0; h < 2; h++) {
                    int c = cbase + h;
                    float d = (h == 0) ? p.x : p.y;
                    float s = fmaf(-2.f, d, aux[c]);
                    if (MODE == 3) s = fmaf(2.f, Grow[c], s);
                    unsigned u = __float_as_uint(s);
                    u = (u & 0x80000000u) ? ~u : (u | 0x80000000u);
                    unsigned long long key = ((unsigned long long)u << 32) | (unsigned)c;
                    bk = key < bk ? key : bk;
                }
            }
            atomicMin(&sb[rloc], bk);
        }
        __syncthreads();
        if (tid < 128) atomicMin(&best[bm * 128 + tid], sb[tid]);
    } else {
        #pragma unroll
        for (int i = 0; i < 8; i++) {
            int r = bm * 128 + ((i < 4) ? (ty * 4 + i) : (64 + ty * 4 + i - 4));
            #pragma unroll
            for (int jj = 0; jj < 2; jj++) {
                int c0 = (jj == 0) ? (tx * 4) : (64 + tx * 4);
                if (bn * 128 + c0 < N) {
                    int cg = bn * 128 + c0;
                    float2 p0 = upk2(acc2[i][jj * 2 + 0]);
                    float2 p1 = upk2(acc2[i][jj * 2 + 1]);
                    float4 v;
                    v.x = p0.x + aux[cg + 0];
                    v.y = p0.y + aux[cg + 1];
                    v.z = p1.x + aux[cg + 2];
                    v.w = p1.y + aux[cg + 3];
                    if (MODE == 1) {
                        v.x = fmaxf(v.x, 0.f); v.y = fmaxf(v.y, 0.f);
                        v.z = fmaxf(v.z, 0.f); v.w = fmaxf(v.w, 0.f);
                    }
                    *(float4*)(C + (size_t)r * N + cg) = v;
                }
            }
        }
    }
}

// ---------------- quantized (straight-through), commit losses, indices ----------
__global__ void __launch_bounds__(256) k_finalize(const float* __restrict__ cb,
                                                  float* __restrict__ dout) {
    int tid = threadIdx.x;
    double l0 = 0.0, l1 = 0.0;
    float* didx = dout + IDX_OFF;
    int t0 = blockIdx.x * 128;
    for (int tt = 0; tt < 128; tt++) {
        int t = t0 + tt;
        int i0 = (int)(g_best0[t] & 0xFFFFFFFFULL);
        int i1 = (int)(g_best1[t] & 0xFFFFFFFFULL);
        if (tid == 0) { didx[2 * t] = (float)i0; didx[2 * t + 1] = (float)i1; }
        float2 x  = ((const float2*)(g_X + (size_t)t * CBD))[tid];
        float2 q0 = ((const float2*)(cb + (size_t)i0 * CBD))[tid];
        float2 q1 = ((const float2*)(cb + ((size_t)NTOK + i1) * CBD))[tid];
        float r2x = x.x - q0.x, r2y = x.y - q0.y;
        float qsx = (x.x + (q0.x - x.x)) + (r2x + (q1.x - r2x));
        float qsy = (x.y + (q0.y - x.y)) + (r2y + (q1.y - r2y));
        ((float2*)(g_R2 + (size_t)t * CBD))[tid] = make_float2(qsx, qsy);
        float e0x = q0.x - x.x, e0y = q0.y - x.y;
        float e1x = q1.x - r2x, e1y = q1.y - r2y;
        l0 += (double)e0x * e0x + (double)e0y * e0y;
        l1 += (double)e1x * e1x + (double)e1y * e1y;
    }
    __shared__ double s0[256], s1[256];
    s0[tid] = l0; s1[tid] = l1; __syncthreads();
    for (int o = 128; o; o >>= 1) {
        if (tid < o) { s0[tid] += s0[tid + o]; s1[tid] += s1[tid + o]; }
        __syncthreads();
    }
    if (!tid) { atomicAdd(&g_acc[0], s0[0]); atomicAdd(&g_acc[1], s1[0]); }
}

// ---------------- quantized output transpose [tok][d] -> [b][d][t] --------------
__global__ void k_transpose(float* __restrict__ outq) {
    __shared__ float tile[32][33];
    int b = blockIdx.z;
    int t0 = blockIdx.x * 32, d0 = blockIdx.y * 32;
    int tx = threadIdx.x, ty = threadIdx.y;        // 32 x 8
    #pragma unroll
    for (int i = 0; i < 4; i++) {
        int t = t0 + ty + i * 8;
        if (t < T2) tile[ty + i * 8][tx] = g_R2[((size_t)b * T2 + t) * CBD + d0 + tx];
    }
    __syncthreads();
    #pragma unroll
    for (int i = 0; i < 4; i++) {
        int d = d0 + ty + i * 8;
        int t = t0 + tx;
        if (t < T2) outq[((size_t)b * CBD + d) * T2 + t] = tile[tx][ty + i * 8];
    }
}

// ---------------- final 1x1 conv + recon loss ------------------------------------
__global__ void __launch_bounds__(256) k_final(const float* __restrict__ img,
                                               const float* __restrict__ W3,
                                               const float* __restrict__ b3,
                                               float* __restrict__ dout) {
    __shared__ float w[64];
    int tid = threadIdx.x;
    if (tid < 64) w[tid] = W3[tid];
    __syncthreads();
    size_t idx = (size_t)blockIdx.x * 256 + tid;   // over B*TT, exact
    const float* row = g_X + idx * 64;             // D2 lives in g_X
    float s = b3[0];
    #pragma unroll
    for (int i = 0; i < 64; i += 4) {
        float4 v = *(const float4*)(row + i);
        s = fmaf(v.x, w[i], s);     s = fmaf(v.y, w[i + 1], s);
        s = fmaf(v.z, w[i + 2], s); s = fmaf(v.w, w[i + 3], s);
    }
    dout[idx] = s;
    float e = img[idx] - s;
    __shared__ double sd[256];
    sd[tid] = (double)e * e; __syncthreads();
    for (int o = 128; o; o >>= 1) { if (tid < o) sd[tid] += sd[tid + o]; __syncthreads(); }
    if (!tid) atomicAdd(&g_acc[2], sd[0]);
}

__global__ void k_scalars(float* __restrict__ dout) {
    dout[OUT_N + 0] = (float)(g_acc[2] / (double)OUT_N);
    dout[OUT_N + 1] = (float)(g_acc[0] / ((double)NTOKEN * CBD));
    dout[OUT_N + 2] = (float)(g_acc[1] / ((double)NTOKEN * CBD));
}

// ---------------- launch ----------------------------------------------------------
extern "C" void kernel_launch(void* const* d_in, const int* in_sizes, int n_in,
                              void* d_out, int out_size) {
    const float* img   = (const float*)d_in[0];
    const float* W_e1  = (const float*)d_in[1];
    const float* b_e1  = (const float*)d_in[2];
    const float* W_e2  = (const float*)d_in[3];
    const float* b_e2  = (const float*)d_in[4];
    const float* W_e3  = (const float*)d_in[5];
    const float* b_e3  = (const float*)d_in[6];
    const float* cb    = (const float*)d_in[7];
    const float* Wt_d1 = (const float*)d_in[8];
    const float* b_d1  = (const float*)d_in[9];
    const float* Wt_d2 = (const float*)d_in[10];
    const float* b_d2  = (const float*)d_in[11];
    const float* W_d3  = (const float*)d_in[12];
    const float* b_d3  = (const float*)d_in[13];
    float* out = (float*)d_out;

    float *pH1, *pH2, *pX, *pR2, *pW2m, *pWd1m, *pWd2m, *pbd1, *pbd2;
    float *pWT3, *pChat, *pG, *pGam, *pZero;
    unsigned long long *pb0, *pb1;
    cudaGetSymbolAddress((void**)&pH1,   g_H1);
    cudaGetSymbolAddress((void**)&pH2,   g_H2);
    cudaGetSymbolAddress((void**)&pX,    g_X);
    cudaGetSymbolAddress((void**)&pR2,   g_R2);
    cudaGetSymbolAddress((void**)&pW2m,  g_W2m);
    cudaGetSymbolAddress((void**)&pWd1m, g_Wd1m);
    cudaGetSymbolAddress((void**)&pWd2m, g_Wd2m);
    cudaGetSymbolAddress((void**)&pbd1,  g_bd1x);
    cudaGetSymbolAddress((void**)&pbd2,  g_bd2x);
    cudaGetSymbolAddress((void**)&pWT3,  g_WT3);
    cudaGetSymbolAddress((void**)&pChat, g_Chat);
    cudaGetSymbolAddress((void**)&pG,    g_G);
    cudaGetSymbolAddress((void**)&pGam,  g_gamma);
    cudaGetSymbolAddress((void**)&pZero, g_zero);
    cudaGetSymbolAddress((void**)&pb0,   g_best0);
    cudaGetSymbolAddress((void**)&pb1,   g_best1);

    k_init  <<<(NTOKEN + 255) / 256, 256>>>();
    k_repack<<<256, 256>>>(W_e2, W_e3, Wt_d1, Wt_d2, b_d1, b_d2);
    k_gamma <<<256, 256>>>(cb, b_e3);
    k_enc1  <<<M1 * HIDD / 256, 256>>>(img, W_e1, b_e1);

    // encoder conv2 as GEMM: [104448 x 128] x [128 x 64], relu
    k_gemm<1><<<dim3(1, 816), 256>>>(pH1, pW2m, pH2, nullptr, b_e2, nullptr, nullptr, 64, 128);
    // encoder 1x1: [104448 x 64] x [64 x 512] -> X (needed for losses/quantized)
    k_gemm<0><<<dim3(4, 816), 256>>>(pH2, W_e3, pX, nullptr, b_e3, nullptr, nullptr, 512, 64);
    // Chat = C . W_e3 : [2048 x 512] x [512 x 64]
    k_gemm<0><<<dim3(1, 16), 256>>>(cb, pWT3, pChat, nullptr, pZero, nullptr, nullptr, 64, 512);
    // G = C0 . C1^T : [1024 x 512] x [512 x 1024]
    k_gemm<0><<<dim3(8, 8), 256>>>(cb, cb + (size_t)NTOK * CBD, pG, nullptr, pZero,
                                   nullptr, nullptr, 1024, 512);
    // VQ stage 0: argmin of gamma0[n] - 2 h2.Chat0_n   (K=64!)
    k_gemm<2><<<dim3(8, 816), 256>>>(pH2, pChat, nullptr, pb0, pGam, nullptr, nullptr, 1024, 64);
    // VQ stage 1: argmin of gamma1[n] - 2 h2.Chat1_n + 2 G[i0][n]
    k_gemm<3><<<dim3(8, 816), 256>>>(pH2, pChat + (size_t)NTOK * 64, nullptr, pb1,
                                     pGam + NTOK, pG, pb0, 1024, 64);
    // quantized tokens (into g_R2), indices, commit losses
    k_finalize<<<816, 256>>>(cb, out);
    // quantized output, transposed to [b][c][t]
    k_transpose<<<dim3(13, 16, 256), dim3(32, 8)>>>(out + QOFF);
    // decoder convT1: [104448 x 512] x [512 x 128], relu -> D1 (in g_H1)
    k_gemm<1><<<dim3(1, 816), 256>>>(pR2, pWd1m, pH1, nullptr, pbd1, nullptr, nullptr, 128, 512);
    // decoder convT2: [208896 x 64] x [64 x 128], relu -> D2 (in g_X)
    k_gemm<1><<<dim3(1, 1632), 256>>>(pH1, pWd2m, pX, nullptr, pbd2, nullptr, nullptr, 128, 64);
    // final 1x1 conv + recon loss
    k_final<<<OUT_N / 256, 256>>>(img, W_d3, b_d3, out);
    k_scalars<<<1, 1>>>(out);
}

// round 9
// speedup vs baseline: 5.6913x; 2.0515x over previous
#include <cuda_runtime.h>

#define BI   256
#define TT   1632
#define T1   816
#define T2   408
#define HIDD 64
#define CBD  512
#define NTOK 1024
#define NTOKEN (BI*T2)   /* 104448 */
#define M1     (BI*T1)   /* 208896 */

#define OUT_N   (BI*TT)                 /* 417792 */
#define IDX_OFF (OUT_N + 3)             /* 417795 */
#define QOFF    (IDX_OFF + NTOKEN*2)    /* 626691 */

// ---------------- scratch (__device__ globals; no runtime allocation) ----------
__device__ float g_H1[(size_t)M1 * HIDD];        // conv1 out [M1*64]; reused as D1 [NTOKEN*128]
__device__ float g_H2[(size_t)NTOKEN * HIDD];    // h2 [tok][64]
__device__ float g_D2[(size_t)M1 * 128];         // decoder conv2 out
__device__ float g_WT3 [64 * 512];               // W_e3^T [i][d]
__device__ float g_Chat[2 * NTOK * 64];          // C . W_e3  [2048][64]
__device__ float g_chn [2 * NTOK];               // ||Chat row|| (inflated)
__device__ float g_gam [2 * NTOK];               // ||c||^2 - 2 b.c
__device__ float g_cn2 [2 * NTOK];               // ||c||^2
__device__ float g_bcv [2 * NTOK];               // b.c
__device__ int   g_cand0[NTOK];
__device__ int   g_n0;
__device__ int   g_slotOf[NTOK];
__device__ int   g_c1idx [(size_t)NTOK * NTOK];  // per-slot stage1 candidates
__device__ float g_c1base[(size_t)NTOK * NTOK];  // gamma1 + 2G[v][n]
__device__ int   g_n1[NTOK];
__device__ int   g_i0[NTOKEN], g_i1[NTOKEN];
__device__ unsigned g_h2maxsq;
__device__ float g_P0[NTOK * 128], g_P1[NTOK * 128];  // C . Wd1m
__device__ float g_Sp[64 * 4096];                // partial H2^T H2
__device__ float g_hp[64 * 64];                  // partial sum h2
__device__ float g_M3[64 * 64], g_w3b[64], g_bb;
__device__ float g_W2m [64 * 128];
__device__ float g_Wd1m[128 * 512];
__device__ float g_Wd2m[128 * 64];
__device__ float g_bd1x[128];
__device__ float g_bd2x[128];
__device__ float g_zero[128];
__device__ double g_acc[8];  // 0:Sum q0x 1:Sum q1x 2:recon_sse 3:Sum cn2_0 4:Sum cn2_1 5:Sum G 6:Sum xsq

// ---------------- f32x2 packed helpers ------------------------------------------
__device__ __forceinline__ unsigned long long pk2(float lo, float hi) {
    unsigned long long r;
    asm("mov.b64 %0, {%1,%2};" : "=l"(r) : "f"(lo), "f"(hi));
    return r;
}
__device__ __forceinline__ float2 upk2(unsigned long long v) {
    float2 r;
    asm("mov.b64 {%0,%1}, %2;" : "=f"(r.x), "=f"(r.y) : "l"(v));
    return r;
}
__device__ __forceinline__ void fma2(unsigned long long& d,
                                     unsigned long long a, unsigned long long b) {
    asm("fma.rn.f32x2 %0, %1, %2, %0;" : "+l"(d) : "l"(a), "l"(b));
}

// ---------------- init ---------------------------------------------------------
__global__ void k_init() {
    int i = threadIdx.x;
    if (i < 8) g_acc[i] = 0.0;
    if (i == 8) g_h2maxsq = 0u;
}

// ---------------- weight repack -------------------------------------------------
__global__ void k_repack(const float* __restrict__ W_e2,
                         const float* __restrict__ W_e3,
                         const float* __restrict__ Wt_d1,
                         const float* __restrict__ Wt_d2,
                         const float* __restrict__ b_d1,
                         const float* __restrict__ b_d2) {
    int i = blockIdx.x * 256 + threadIdx.x;      // 0..65535
    if (i < 64 * 128) {                          // W2m[o][k*64+ii] = W_e2[o][ii][k]
        int o = i >> 7, c = i & 127, k = c >> 6, ii = c & 63;
        g_W2m[i] = W_e2[(o * 64 + ii) * 2 + k];
    }
    if (i < 64 * 512) {                          // WT3[ii][d] = W_e3[d][ii]
        int r = i >> 9, d = i & 511;
        g_WT3[i] = W_e3[d * 64 + r];
    }
    if (i < 128 * 512) {                         // Wd1m[k*64+o][d] = Wt_d1[d][o][k]
        int n = i >> 9, d = i & 511;
        int k = n >> 6, o = n & 63;
        g_Wd1m[i] = Wt_d1[(d * 64 + o) * 2 + k];
    }
    if (i < 128 * 64) {                          // Wd2m[k*64+o][d] = Wt_d2[d][o][k]
        int n = i >> 6, d = i & 63;
        int k = n >> 6, o = n & 63;
        g_Wd2m[i] = Wt_d2[(d * 64 + o) * 2 + k];
    }
    if (i < 128) { g_bd1x[i] = b_d1[i & 63]; g_bd2x[i] = b_d2[i & 63]; g_zero[i] = 0.f; }
}

// ---------------- per-code stats: ||c||^2, b.c, gamma ---------------------------
__global__ void k_stats(const float* __restrict__ cb, const float* __restrict__ be3) {
    int row = blockIdx.x * 8 + (threadIdx.x >> 5);
    int lane = threadIdx.x & 31;
    const float* r = cb + (size_t)row * CBD;
    float s = 0.f, t = 0.f;
    for (int d = lane; d < CBD; d += 32) {
        float v = r[d];
        s = fmaf(v, v, s);
        t = fmaf(v, be3[d], t);
    }
    #pragma unroll
    for (int o = 16; o; o >>= 1) {
        s += __shfl_xor_sync(0xffffffffu, s, o);
        t += __shfl_xor_sync(0xffffffffu, t, o);
    }
    if (!lane) { g_cn2[row] = s; g_bcv[row] = t; g_gam[row] = s - 2.f * t; }
}

// ---------------- encoder conv1 (k=2,s=2) ---------------------------------------
__global__ void k_enc1(const float* __restrict__ img,
                       const float* __restrict__ W,
                       const float* __restrict__ bias) {
    int idx = blockIdx.x * 256 + threadIdx.x;    // over M1*64, exact
    int tok = idx >> 6, i = idx & 63;
    int b = tok / T1, t = tok % T1;
    float x0 = img[(size_t)b * TT + 2 * t];
    float x1 = img[(size_t)b * TT + 2 * t + 1];
    float v = fmaf(W[i * 2], x0, fmaf(W[i * 2 + 1], x1, bias[i]));
    g_H1[idx] = fmaxf(v, 0.f);
}

// ---------------- 128x128x(K) SGEMM (f32x2); MODE 0 = +bias, 1 = +bias+relu ----
template<int MODE>
__global__ void __launch_bounds__(256) k_gemm(
    const float* __restrict__ A, const float* __restrict__ Bm,
    float* __restrict__ C, const float* __restrict__ aux, int N, int K)
{
    __shared__ float As[8][132];
    __shared__ float Bs[8][132];
    const int tid = threadIdx.x;
    const int tx = tid & 15, ty = tid >> 4;
    const int bn = blockIdx.x, bm = blockIdx.y;

    unsigned long long acc2[8][4];
    #pragma unroll
    for (int i = 0; i < 8; i++)
        #pragma unroll
        for (int j = 0; j < 4; j++) acc2[i][j] = 0ULL;

    const int lr = tid >> 1;
    const int lc = (tid & 1) * 4;
    const float* Ap = A + (size_t)(bm * 128 + lr) * K + lc;
    const float* Bp = Bm + (size_t)(bn * 128 + lr) * K + lc;
    const bool bvalid = (bn * 128 + lr) < N;

    for (int k0 = 0; k0 < K; k0 += 8) {
        float4 av = *(const float4*)(Ap + k0);
        float4 bv = bvalid ? *(const float4*)(Bp + k0) : make_float4(0.f, 0.f, 0.f, 0.f);
        As[lc + 0][lr] = av.x; As[lc + 1][lr] = av.y; As[lc + 2][lr] = av.z; As[lc + 3][lr] = av.w;
        Bs[lc + 0][lr] = bv.x; Bs[lc + 1][lr] = bv.y; Bs[lc + 2][lr] = bv.z; Bs[lc + 3][lr] = bv.w;
        __syncthreads();
        #pragma unroll
        for (int kk = 0; kk < 8; kk++) {
            float4 a0 = *(const float4*)&As[kk][ty * 4];
            float4 a1 = *(const float4*)&As[kk][64 + ty * 4];
            float4 b0 = *(const float4*)&Bs[kk][tx * 4];
            float4 b1 = *(const float4*)&Bs[kk][64 + tx * 4];
            float a[8] = {a0.x, a0.y, a0.z, a0.w, a1.x, a1.y, a1.z, a1.w};
            unsigned long long bp[4] = {pk2(b0.x, b0.y), pk2(b0.z, b0.w),
                                        pk2(b1.x, b1.y), pk2(b1.z, b1.w)};
            #pragma unroll
            for (int i = 0; i < 8; i++) {
                unsigned long long ap = pk2(a[i], a[i]);
                #pragma unroll
                for (int j = 0; j < 4; j++) fma2(acc2[i][j], ap, bp[j]);
            }
        }
        __syncthreads();
    }

    #pragma unroll
    for (int i = 0; i < 8; i++) {
        int r = bm * 128 + ((i < 4) ? (ty * 4 + i) : (64 + ty * 4 + i - 4));
        #pragma unroll
        for (int jj = 0; jj < 2; jj++) {
            int c0 = (jj == 0) ? (tx * 4) : (64 + tx * 4);
            if (bn * 128 + c0 < N) {
                int cg = bn * 128 + c0;
                float2 p0 = upk2(acc2[i][jj * 2 + 0]);
                float2 p1 = upk2(acc2[i][jj * 2 + 1]);
                float4 v;
                v.x = p0.x + aux[cg + 0];
                v.y = p0.y + aux[cg + 1];
                v.z = p1.x + aux[cg + 2];
                v.w = p1.y + aux[cg + 3];
                if (MODE == 1) {
                    v.x = fmaxf(v.x, 0.f); v.y = fmaxf(v.y, 0.f);
                    v.z = fmaxf(v.z, 0.f); v.w = fmaxf(v.w, 0.f);
                }
                *(float4*)(C + (size_t)r * N + cg) = v;
            }
        }
    }
}

// ---------------- ||Chat row|| (inflated upper bound) ----------------------------
__global__ void k_chnorm() {
    int row = blockIdx.x * 8 + (threadIdx.x >> 5);
    int lane = threadIdx.x & 31;
    float2 v = ((const float2*)(g_Chat + (size_t)row * 64))[lane];
    float s = fmaf(v.x, v.x, v.y * v.y);
    #pragma unroll
    for (int o = 16; o; o >>= 1) s += __shfl_xor_sync(0xffffffffu, s, o);
    if (!lane) g_chn[row] = sqrtf(s) * 1.0001f + 1e-20f;
}

// ---------------- max_t ||h2_t||^2 ------------------------------------------------
__global__ void k_h2max() {
    __shared__ float sm[8];
    int w = threadIdx.x >> 5, lane = threadIdx.x & 31;
    int base = (blockIdx.x * 8 + w) * 32;
    float m = 0.f;
    for (int r = 0; r < 32; r++) {
        float2 h = ((const float2*)(g_H2 + (size_t)(base + r) * 64))[lane];
        float s = fmaf(h.x, h.x, h.y * h.y);
        #pragma unroll
        for (int o = 16; o; o >>= 1) s += __shfl_xor_sync(0xffffffffu, s, o);
        m = fmaxf(m, s);
    }
    if (!lane) sm[w] = m;
    __syncthreads();
    if (threadIdx.x == 0) {
        float mm = sm[0];
        #pragma unroll
        for (int i = 1; i < 8; i++) mm = fmaxf(mm, sm[i]);
        atomicMax(&g_h2maxsq, __float_as_uint(mm));
    }
}

// ---------------- stage-0 candidate set (provably sufficient) --------------------
__global__ void k_cand0() {
    __shared__ float red[256];
    int tid = threadIdx.x;
    float H = sqrtf(__uint_as_float(g_h2maxsq)) * 1.0001f;
    float mn = 3.4e38f;
    for (int n = tid; n < NTOK; n += 256)
        mn = fminf(mn, g_gam[n] + 2.f * H * g_chn[n]);
    red[tid] = mn; __syncthreads();
    for (int o = 128; o; o >>= 1) {
        if (tid < o) red[tid] = fminf(red[tid], red[tid + o]);
        __syncthreads();
    }
    if (tid == 0) {
        float thresh = red[0] + 0.05f;
        int cnt = 0;
        for (int n = 0; n < NTOK; n++) {
            if (g_gam[n] - 2.f * H * g_chn[n] <= thresh) {
                g_cand0[cnt] = n; g_slotOf[n] = cnt; cnt++;
            }
        }
        g_n0 = cnt;
    }
}

// ---------------- stage-1 per-slot bases + candidates -----------------------------
__global__ void __launch_bounds__(256) k_s1prep(const float* __restrict__ cb) {
    __shared__ float c0row[512];
    __shared__ float sbase[NTOK];
    __shared__ float red[256];
    int s = blockIdx.x, tid = threadIdx.x;
    if (s >= g_n0) return;
    int v = g_cand0[s];
    if (tid < 128) ((float4*)c0row)[tid] = ((const float4*)(cb + (size_t)v * CBD))[tid];
    __syncthreads();
    float H = sqrtf(__uint_as_float(g_h2maxsq)) * 1.0001f;
    float mn = 3.4e38f;
    for (int n = tid; n < NTOK; n += 256) {
        const float4* r1 = (const float4*)(cb + ((size_t)NTOK + n) * CBD);
        float d = 0.f;
        #pragma unroll 8
        for (int k = 0; k < 128; k++) {
            float4 a = ((const float4*)c0row)[k], b = r1[k];
            d = fmaf(a.x, b.x, d); d = fmaf(a.y, b.y, d);
            d = fmaf(a.z, b.z, d); d = fmaf(a.w, b.w, d);
        }
        float base = fmaf(2.f, d, g_gam[NTOK + n]);
        sbase[n] = base;
        mn = fminf(mn, base + 2.f * H * g_chn[NTOK + n]);
    }
    red[tid] = mn; __syncthreads();
    for (int o = 128; o; o >>= 1) {
        if (tid < o) red[tid] = fminf(red[tid], red[tid + o]);
        __syncthreads();
    }
    if (tid == 0) {
        float thresh = red[0] + 0.05f;
        int cnt = 0;
        for (int n = 0; n < NTOK; n++) {
            if (sbase[n] - 2.f * H * g_chn[NTOK + n] <= thresh) {
                g_c1idx [(size_t)s * NTOK + cnt] = n;
                g_c1base[(size_t)s * NTOK + cnt] = sbase[n];
                cnt++;
            }
        }
        g_n1[s] = cnt;
    }
}

// ---------------- M3 = W^T W, w3b = W^T b, bb = ||b||^2 --------------------------
__global__ void k_m3(const float* __restrict__ be3) {
    int blk = blockIdx.x, tid = threadIdx.x;
    if (blk < 16) {
        int idx = blk * 256 + tid;
        int i = idx >> 6, j = idx & 63;
        const float4* ri = (const float4*)(g_WT3 + (size_t)i * 512);
        const float4* rj = (const float4*)(g_WT3 + (size_t)j * 512);
        float sacc = 0.f;
        for (int k = 0; k < 128; k++) {
            float4 a = ri[k], b = rj[k];
            sacc = fmaf(a.x, b.x, sacc); sacc = fmaf(a.y, b.y, sacc);
            sacc = fmaf(a.z, b.z, sacc); sacc = fmaf(a.w, b.w, sacc);
        }
        g_M3[idx] = sacc;
    } else {
        if (tid < 64) {
            const float4* ri = (const float4*)(g_WT3 + (size_t)tid * 512);
            const float4* rb = (const float4*)be3;
            float sacc = 0.f;
            for (int k = 0; k < 128; k++) {
                float4 a = ri[k], b = rb[k];
                sacc = fmaf(a.x, b.x, sacc); sacc = fmaf(a.y, b.y, sacc);
                sacc = fmaf(a.z, b.z, sacc); sacc = fmaf(a.w, b.w, sacc);
            }
            g_w3b[tid] = sacc;
        } else if (tid == 64) {
            float sacc = 0.f;
            for (int d = 0; d < 512; d++) { float v = be3[d]; sacc = fmaf(v, v, sacc); }
            g_bb = sacc;
        }
    }
}

// ---------------- per-token argmin over candidate sets + loss terms --------------
__global__ void __launch_bounds__(256) k_vq(float* __restrict__ dout) {
    int tid = threadIdx.x;
    int w = tid >> 5, lane = tid & 31;
    int n0 = g_n0;
    double a_q0x = 0, a_q1x = 0, a_c0 = 0, a_c1 = 0, a_G = 0;
    int wbase = (blockIdx.x * 8 + w) * 8;
    float* didx = dout + IDX_OFF;
    for (int r = 0; r < 8; r++) {
        int t = wbase + r;
        float2 h = ((const float2*)(g_H2 + (size_t)t * 64))[lane];
        // stage 0
        float bs = 3.4e38f, bd0 = 0.f; int bi = 0;
        for (int j = 0; j < n0; j++) {
            int c = g_cand0[j];
            float2 cv = ((const float2*)(g_Chat + (size_t)c * 64))[lane];
            float p = fmaf(h.x, cv.x, h.y * cv.y);
            #pragma unroll
            for (int o = 16; o; o >>= 1) p += __shfl_xor_sync(0xffffffffu, p, o);
            float s = fmaf(-2.f, p, g_gam[c]);
            if (s < bs) { bs = s; bi = c; bd0 = p; }
        }
        int i0 = bi;
        int slot = g_slotOf[i0];
        int n1 = g_n1[slot];
        const int*   c1i = g_c1idx  + (size_t)slot * NTOK;
        const float* c1b = g_c1base + (size_t)slot * NTOK;
        bs = 3.4e38f; bi = 0; float bd1 = 0.f, bb1 = 0.f;
        for (int j = 0; j < n1; j++) {
            int c = c1i[j]; float base = c1b[j];
            float2 cv = ((const float2*)(g_Chat + (size_t)(NTOK + c) * 64))[lane];
            float p = fmaf(h.x, cv.x, h.y * cv.y);
            #pragma unroll
            for (int o = 16; o; o >>= 1) p += __shfl_xor_sync(0xffffffffu, p, o);
            float s = fmaf(-2.f, p, base);
            if (s < bs) { bs = s; bi = c; bd1 = p; bb1 = base; }
        }
        int i1 = bi;
        if (lane == 0) {
            g_i0[t] = i0; g_i1[t] = i1;
            didx[2 * t] = (float)i0; didx[2 * t + 1] = (float)i1;
            a_q0x += (double)bd0 + (double)g_bcv[i0];
            a_q1x += (double)bd1 + (double)g_bcv[NTOK + i1];
            a_c0  += (double)g_cn2[i0];
            a_c1  += (double)g_cn2[NTOK + i1];
            a_G   += 0.5 * ((double)bb1 - (double)g_gam[NTOK + i1]);
        }
    }
    __shared__ double sm[8][5];
    if (lane == 0) {
        sm[w][0] = a_q0x; sm[w][1] = a_q1x; sm[w][2] = a_c0; sm[w][3] = a_c1; sm[w][4] = a_G;
    }
    __syncthreads();
    if (tid == 0) {
        double v0 = 0, v1 = 0, v2 = 0, v3 = 0, v4 = 0;
        #pragma unroll
        for (int i = 0; i < 8; i++) {
            v0 += sm[i][0]; v1 += sm[i][1]; v2 += sm[i][2]; v3 += sm[i][3]; v4 += sm[i][4];
        }
        atomicAdd(&g_acc[0], v0); atomicAdd(&g_acc[1], v1);
        atomicAdd(&g_acc[3], v2); atomicAdd(&g_acc[4], v3);
        atomicAdd(&g_acc[5], v4);
    }
}

// ---------------- partial S = H2^T H2 and sum(h2) --------------------------------
__global__ void __launch_bounds__(256) k_Spart() {
    __shared__ float sh2[8 * 64];
    int tid = threadIdx.x, blk = blockIdx.x;
    int t0 = blk * 1632;
    float acc[16];
    #pragma unroll
    for (int i = 0; i < 16; i++) acc[i] = 0.f;
    float hsum = 0.f;
    int ti = tid >> 4, tj = tid & 15;
    for (int g = 0; g < 204; g++) {
        int base = t0 + g * 8;
        if (tid < 128)
            ((float4*)sh2)[tid] = ((const float4*)(g_H2 + (size_t)base * 64))[tid];
        __syncthreads();
        #pragma unroll
        for (int r = 0; r < 8; r++) {
            float4 a = *(const float4*)&sh2[r * 64 + ti * 4];
            float4 b = *(const float4*)&sh2[r * 64 + tj * 4];
            float av[4] = {a.x, a.y, a.z, a.w}, bv[4] = {b.x, b.y, b.z, b.w};
            #pragma unroll
            for (int p = 0; p < 4; p++)
                #pragma unroll
                for (int q = 0; q < 4; q++) acc[p * 4 + q] = fmaf(av[p], bv[q], acc[p * 4 + q]);
        }
        if (tid < 64) {
            #pragma unroll
            for (int r = 0; r < 8; r++) hsum += sh2[r * 64 + tid];
        }
        __syncthreads();
    }
    #pragma unroll
    for (int p = 0; p < 4; p++)
        #pragma unroll
        for (int q = 0; q < 4; q++)
            g_Sp[(size_t)blk * 4096 + (ti * 4 + p) * 64 + (tj * 4 + q)] = acc[p * 4 + q];
    if (tid < 64) g_hp[blk * 64 + tid] = hsum;
}

// ---------------- Sum ||x||^2 = <M3,S> + 2 w3b.sum(h2) + N*bb --------------------
__global__ void k_Sfinal() {
    __shared__ double red[256];
    int tid = threadIdx.x, blk = blockIdx.x;
    int c = blk * 256 + tid;
    float s = 0.f;
    for (int p = 0; p < 64; p++) s += g_Sp[(size_t)p * 4096 + c];
    double partial = (double)s * (double)g_M3[c];
    if (blk == 0) {
        if (tid < 64) {
            float sh = 0.f;
            for (int p = 0; p < 64; p++) sh += g_hp[p * 64 + tid];
            partial += 2.0 * (double)sh * (double)g_w3b[tid];
        } else if (tid == 64) {
            partial += (double)NTOKEN * (double)g_bb;
        }
    }
    red[tid] = partial; __syncthreads();
    for (int o = 128; o; o >>= 1) {
        if (tid < o) red[tid] += red[tid + o];
        __syncthreads();
    }
    if (tid == 0) atomicAdd(&g_acc[6], red[0]);
}

// ---------------- decoder stage 1 via code gather --------------------------------
__global__ void k_d1gather() {
    int idx = blockIdx.x * 256 + threadIdx.x;    // over NTOKEN*128, exact
    int t = idx >> 7, n = idx & 127;
    int i0 = g_i0[t], i1 = g_i1[t];
    float v = g_P0[i0 * 128 + n] + g_P1[i1 * 128 + n] + g_bd1x[n];
    g_H1[idx] = fmaxf(v, 0.f);
}

// ---------------- quantized output, directly transposed --------------------------
__global__ void k_qout(const float* __restrict__ cb, float* __restrict__ dout) {
    int idx = blockIdx.x * 256 + threadIdx.x;    // over B*CBD*T2, exact
    int t = idx % T2;
    int rd = idx / T2;
    int d = rd & 511;
    int b = rd >> 9;
    int tok = b * T2 + t;
    float v = cb[(size_t)g_i0[tok] * CBD + d] + cb[((size_t)NTOK + g_i1[tok]) * CBD + d];
    dout[QOFF + idx] = v;
}

// ---------------- final 1x1 conv + recon loss ------------------------------------
__global__ void __launch_bounds__(256) k_final(const float* __restrict__ img,
                                               const float* __restrict__ W3,
                                               const float* __restrict__ b3,
                                               float* __restrict__ dout) {
    __shared__ float w[64];
    int tid = threadIdx.x;
    if (tid < 64) w[tid] = W3[tid];
    __syncthreads();
    size_t idx = (size_t)blockIdx.x * 256 + tid;   // over B*TT, exact
    const float* row = g_D2 + idx * 64;
    float s = b3[0];
    #pragma unroll
    for (int i = 0; i < 64; i += 4) {
        float4 v = *(const float4*)(row + i);
        s = fmaf(v.x, w[i], s);     s = fmaf(v.y, w[i + 1], s);
        s = fmaf(v.z, w[i + 2], s); s = fmaf(v.w, w[i + 3], s);
    }
    dout[idx] = s;
    float e = img[idx] - s;
    __shared__ double sd[256];
    sd[tid] = (double)e * e; __syncthreads();
    for (int o = 128; o; o >>= 1) { if (tid < o) sd[tid] += sd[tid + o]; __syncthreads(); }
    if (!tid) atomicAdd(&g_acc[2], sd[0]);
}

__global__ void k_scalars(float* __restrict__ dout) {
    double denom = (double)NTOKEN * CBD;
    double q0x = g_acc[0], q1x = g_acc[1], c0 = g_acc[3], c1 = g_acc[4];
    double G = g_acc[5], xsq = g_acc[6];
    dout[OUT_N + 0] = (float)(g_acc[2] / (double)OUT_N);
    dout[OUT_N + 1] = (float)((c0 - 2.0 * q0x + xsq) / denom);
    dout[OUT_N + 2] = (float)((c0 + c1 + xsq + 2.0 * G - 2.0 * q0x - 2.0 * q1x) / denom);
}

// ---------------- launch ----------------------------------------------------------
extern "C" void kernel_launch(void* const* d_in, const int* in_sizes, int n_in,
                              void* d_out, int out_size) {
    const float* img   = (const float*)d_in[0];
    const float* W_e1  = (const float*)d_in[1];
    const float* b_e1  = (const float*)d_in[2];
    const float* W_e2  = (const float*)d_in[3];
    const float* b_e2  = (const float*)d_in[4];
    const float* W_e3  = (const float*)d_in[5];
    const float* b_e3  = (const float*)d_in[6];
    const float* cb    = (const float*)d_in[7];
    const float* Wt_d1 = (const float*)d_in[8];
    const float* b_d1  = (const float*)d_in[9];
    const float* Wt_d2 = (const float*)d_in[10];
    const float* b_d2  = (const float*)d_in[11];
    const float* W_d3  = (const float*)d_in[12];
    const float* b_d3  = (const float*)d_in[13];
    float* out = (float*)d_out;

    float *pH1, *pH2, *pD2, *pW2m, *pWd1m, *pWd2m, *pWT3, *pChat, *pP0, *pP1, *pZero, *pbd2;
    cudaGetSymbolAddress((void**)&pH1,   g_H1);
    cudaGetSymbolAddress((void**)&pH2,   g_H2);
    cudaGetSymbolAddress((void**)&pD2,   g_D2);
    cudaGetSymbolAddress((void**)&pW2m,  g_W2m);
    cudaGetSymbolAddress((void**)&pWd1m, g_Wd1m);
    cudaGetSymbolAddress((void**)&pWd2m, g_Wd2m);
    cudaGetSymbolAddress((void**)&pWT3,  g_WT3);
    cudaGetSymbolAddress((void**)&pChat, g_Chat);
    cudaGetSymbolAddress((void**)&pP0,   g_P0);
    cudaGetSymbolAddress((void**)&pP1,   g_P1);
    cudaGetSymbolAddress((void**)&pZero, g_zero);
    cudaGetSymbolAddress((void**)&pbd2,  g_bd2x);

    k_init  <<<1, 32>>>();
    k_repack<<<256, 256>>>(W_e2, W_e3, Wt_d1, Wt_d2, b_d1, b_d2);
    k_stats <<<256, 256>>>(cb, b_e3);
    k_enc1  <<<M1 * HIDD / 256, 256>>>(img, W_e1, b_e1);

    // encoder conv2 as GEMM: [104448 x 128] x [128 x 64], relu -> H2
    k_gemm<1><<<dim3(1, 816), 256>>>(pH1, pW2m, pH2, b_e2, 64, 128);
    // Chat = C . W_e3 : [2048 x 512] x [512 x 64]
    k_gemm<0><<<dim3(1, 16), 256>>>(cb, pWT3, pChat, pZero, 64, 512);
    k_chnorm<<<256, 256>>>();
    k_h2max <<<408, 256>>>();
    k_cand0 <<<1, 256>>>();
    k_s1prep<<<NTOK, 256>>>(cb);
    k_m3    <<<17, 256>>>(b_e3);
    // per-token argmins + index outputs + loss cross terms
    k_vq    <<<1632, 256>>>(out);
    // Sum ||x||^2 via S = H2^T H2
    k_Spart <<<64, 256>>>();
    k_Sfinal<<<16, 256>>>();
    // P = C . Wd1m (per codebook)
    k_gemm<0><<<dim3(1, 8), 256>>>(cb, pWd1m, pP0, pZero, 128, 512);
    k_gemm<0><<<dim3(1, 8), 256>>>(cb + (size_t)NTOK * CBD, pWd1m, pP1, pZero, 128, 512);
    // decoder stage 1 by gather: D1 = relu(P0[i0] + P1[i1] + b)
    k_d1gather<<<NTOKEN * 128 / 256, 256>>>();
    // decoder convT2: [208896 x 64] x [64 x 128], relu -> D2
    k_gemm<1><<<dim3(1, 1632), 256>>>(pH1, pWd2m, pD2, pbd2, 128, 64);
    // quantized output [b][d][t]
    k_qout <<<BI * CBD * T2 / 256, 256>>>(cb, out);
    // final 1x1 conv + recon loss
    k_final<<<OUT_N / 256, 256>>>(img, W_d3, b_d3, out);
    k_scalars<<<1, 1>>>(out);
}

// round 10
// speedup vs baseline: 6.8581x; 1.2050x over previous
#include <cuda_runtime.h>

#define BI   256
#define TT   1632
#define T1   816
#define T2   408
#define HIDD 64
#define CBD  512
#define NTOK 1024
#define NTOKEN (BI*T2)   /* 104448 */
#define M1     (BI*T1)   /* 208896 */

#define OUT_N   (BI*TT)                 /* 417792 */
#define IDX_OFF (OUT_N + 3)             /* 417795 */
#define QOFF    (IDX_OFF + NTOKEN*2)    /* 626691 */

// ---------------- scratch (__device__ globals; no runtime allocation) ----------
__device__ float g_H2[(size_t)NTOKEN * HIDD];    // h2 [tok][64]
__device__ float g_WT3 [64 * 512];               // W_e3^T [i][d]
__device__ float g_Chat[2 * NTOK * 64];          // C . W_e3  [2048][64]
__device__ float g_chn [2 * NTOK];               // ||Chat row|| (inflated)
__device__ float g_gam [2 * NTOK];               // ||c||^2 - 2 b.c
__device__ float g_cn2 [2 * NTOK];               // ||c||^2
__device__ float g_bcv [2 * NTOK];               // b.c
__device__ int   g_cand0[NTOK];
__device__ int   g_n0;
__device__ int   g_slotOf[NTOK];
__device__ int   g_c1idx [(size_t)NTOK * NTOK];  // per-slot stage1 candidates
__device__ float g_c1base[(size_t)NTOK * NTOK];  // gamma1 + 2G[v][n]
__device__ int   g_n1[NTOK];
__device__ int   g_i0[NTOKEN], g_i1[NTOKEN];
__device__ unsigned g_h2maxsq;
__device__ float g_P0[NTOK * 128], g_P1[NTOK * 128];  // C . Wd1m
__device__ float g_Sp[64 * 4096];                // partial H2^T H2
__device__ float g_hp[64 * 64];                  // partial sum h2
__device__ float g_M3[64 * 64], g_w3b[64], g_bb;
__device__ float g_W2m [64 * 128];
__device__ float g_Wd1m[128 * 512];
__device__ float g_Wd2m[128 * 64];
__device__ float g_bd1x[128];
__device__ float g_bd2x[128];
__device__ float g_zero[128];
__device__ double g_acc[8];  // 0:Sum q0x 1:Sum q1x 2:recon_sse 3:Sum cn2_0 4:Sum cn2_1 5:Sum G 6:Sum xsq

// ---------------- f32x2 packed helpers ------------------------------------------
__device__ __forceinline__ unsigned long long pk2(float lo, float hi) {
    unsigned long long r;
    asm("mov.b64 %0, {%1,%2};" : "=l"(r) : "f"(lo), "f"(hi));
    return r;
}
__device__ __forceinline__ float2 upk2(unsigned long long v) {
    float2 r;
    asm("mov.b64 {%0,%1}, %2;" : "=f"(r.x), "=f"(r.y) : "l"(v));
    return r;
}
__device__ __forceinline__ void fma2(unsigned long long& d,
                                     unsigned long long a, unsigned long long b) {
    asm("fma.rn.f32x2 %0, %1, %2, %0;" : "+l"(d) : "l"(a), "l"(b));
}

// ---------------- init ---------------------------------------------------------
__global__ void k_init() {
    int i = threadIdx.x;
    if (i < 8) g_acc[i] = 0.0;
    if (i == 8) g_h2maxsq = 0u;
}

// ---------------- weight repack -------------------------------------------------
__global__ void k_repack(const float* __restrict__ W_e2,
                         const float* __restrict__ W_e3,
                         const float* __restrict__ Wt_d1,
                         const float* __restrict__ Wt_d2,
                         const float* __restrict__ b_d1,
                         const float* __restrict__ b_d2) {
    int i = blockIdx.x * 256 + threadIdx.x;      // 0..65535
    if (i < 64 * 128) {                          // W2m[o][k*64+ii] = W_e2[o][ii][k]
        int o = i >> 7, c = i & 127, k = c >> 6, ii = c & 63;
        g_W2m[i] = W_e2[(o * 64 + ii) * 2 + k];
    }
    if (i < 64 * 512) {                          // WT3[ii][d] = W_e3[d][ii]
        int r = i >> 9, d = i & 511;
        g_WT3[i] = W_e3[d * 64 + r];
    }
    if (i < 128 * 512) {                         // Wd1m[k*64+o][d] = Wt_d1[d][o][k]
        int n = i >> 9, d = i & 511;
        int k = n >> 6, o = n & 63;
        g_Wd1m[i] = Wt_d1[(d * 64 + o) * 2 + k];
    }
    if (i < 128 * 64) {                          // Wd2m[k*64+o][d] = Wt_d2[d][o][k]
        int n = i >> 6, d = i & 63;
        int k = n >> 6, o = n & 63;
        g_Wd2m[i] = Wt_d2[(d * 64 + o) * 2 + k];
    }
    if (i < 128) { g_bd1x[i] = b_d1[i & 63]; g_bd2x[i] = b_d2[i & 63]; g_zero[i] = 0.f; }
}

// ---------------- per-code stats: ||c||^2, b.c, gamma ---------------------------
__global__ void k_stats(const float* __restrict__ cb, const float* __restrict__ be3) {
    int row = blockIdx.x * 8 + (threadIdx.x >> 5);
    int lane = threadIdx.x & 31;
    const float* r = cb + (size_t)row * CBD;
    float s = 0.f, t = 0.f;
    for (int d = lane; d < CBD; d += 32) {
        float v = r[d];
        s = fmaf(v, v, s);
        t = fmaf(v, be3[d], t);
    }
    #pragma unroll
    for (int o = 16; o; o >>= 1) {
        s += __shfl_xor_sync(0xffffffffu, s, o);
        t += __shfl_xor_sync(0xffffffffu, t, o);
    }
    if (!lane) { g_cn2[row] = s; g_bcv[row] = t; g_gam[row] = s - 2.f * t; }
}

// ---------------- FUSED encoder: img -> H2 (conv1 + conv2 + relu) + h2max --------
// Tile: 256 tokens x 64 cols, K=128 (h1 computed on the fly). grid = 408.
__global__ void __launch_bounds__(256) k_enc(const float* __restrict__ img,
                                             const float* __restrict__ W_e1,
                                             const float* __restrict__ b_e1,
                                             const float* __restrict__ b_e2) {
    __shared__ float W2ts[128][68];   // W2 transposed: [c][o]
    __shared__ float As[8][260];      // h1 chunk: [kk][row]
    __shared__ float imgs2[4][260];   // img comp j for token row
    __shared__ float We1s[128], b1s[64], b2s[64];
    __shared__ float smax[8];
    const int tid = threadIdx.x, blk = blockIdx.x;

    for (int e = tid; e < 8192; e += 256) {
        int o = e >> 7, c = e & 127;
        W2ts[c][o] = g_W2m[e];
    }
    if (tid < 128) We1s[tid] = W_e1[tid];
    if (tid < 64) { b1s[tid] = b_e1[tid]; b2s[tid] = b_e2[tid]; }
    {
        float4 iv = ((const float4*)img)[blk * 256 + tid];
        imgs2[0][tid] = iv.x; imgs2[1][tid] = iv.y;
        imgs2[2][tid] = iv.z; imgs2[3][tid] = iv.w;
    }
    __syncthreads();

    const int tx = tid & 7, ty = tid >> 3;
    unsigned long long acc2[8][4];
    #pragma unroll
    for (int i = 0; i < 8; i++)
        #pragma unroll
        for (int j = 0; j < 4; j++) acc2[i][j] = 0ULL;

    for (int k0 = 0; k0 < 128; k0 += 8) {
        #pragma unroll
        for (int u = 0; u < 8; u++) {      // kk = u, row = tid
            int c = k0 + u, kp = c >> 6, ii = c & 63;
            float v = fmaf(We1s[2 * ii], imgs2[2 * kp][tid],
                     fmaf(We1s[2 * ii + 1], imgs2[2 * kp + 1][tid], b1s[ii]));
            As[u][tid] = fmaxf(v, 0.f);
        }
        __syncthreads();
        #pragma unroll
        for (int kk = 0; kk < 8; kk++) {
            int kc = k0 + kk;
            float4 a0 = *(const float4*)&As[kk][ty * 4];
            float4 a1 = *(const float4*)&As[kk][128 + ty * 4];
            float4 b0 = *(const float4*)&W2ts[kc][tx * 4];
            float4 b1v = *(const float4*)&W2ts[kc][32 + tx * 4];
            float a[8] = {a0.x, a0.y, a0.z, a0.w, a1.x, a1.y, a1.z, a1.w};
            unsigned long long bp[4] = {pk2(b0.x, b0.y), pk2(b0.z, b0.w),
                                        pk2(b1v.x, b1v.y), pk2(b1v.z, b1v.w)};
            #pragma unroll
            for (int i = 0; i < 8; i++) {
                unsigned long long ap = pk2(a[i], a[i]);
                #pragma unroll
                for (int j = 0; j < 4; j++) fma2(acc2[i][j], ap, bp[j]);
            }
        }
        __syncthreads();
    }

    // epilogue: bias+relu, store H2, and max ||h2||^2
    float mrow = 0.f;
    #pragma unroll
    for (int i = 0; i < 8; i++) {
        int rloc = (i < 4) ? (ty * 4 + i) : (128 + ty * 4 + (i - 4));
        int tok = blk * 256 + rloc;
        float ssq = 0.f;
        #pragma unroll
        for (int jj = 0; jj < 2; jj++) {
            int c0 = (jj == 0) ? (tx * 4) : (32 + tx * 4);
            float2 p0 = upk2(acc2[i][jj * 2 + 0]);
            float2 p1 = upk2(acc2[i][jj * 2 + 1]);
            float4 v;
            v.x = fmaxf(p0.x + b2s[c0 + 0], 0.f);
            v.y = fmaxf(p0.y + b2s[c0 + 1], 0.f);
            v.z = fmaxf(p1.x + b2s[c0 + 2], 0.f);
            v.w = fmaxf(p1.y + b2s[c0 + 3], 0.f);
            ssq = fmaf(v.x, v.x, ssq); ssq = fmaf(v.y, v.y, ssq);
            ssq = fmaf(v.z, v.z, ssq); ssq = fmaf(v.w, v.w, ssq);
            *(float4*)(g_H2 + (size_t)tok * 64 + c0) = v;
        }
        ssq += __shfl_xor_sync(0xffffffffu, ssq, 1);
        ssq += __shfl_xor_sync(0xffffffffu, ssq, 2);
        ssq += __shfl_xor_sync(0xffffffffu, ssq, 4);
        mrow = fmaxf(mrow, ssq);
    }
    mrow = fmaxf(mrow, __shfl_xor_sync(0xffffffffu, mrow, 8));
    mrow = fmaxf(mrow, __shfl_xor_sync(0xffffffffu, mrow, 16));
    if ((tid & 31) == 0) smax[tid >> 5] = mrow;
    __syncthreads();
    if (tid == 0) {
        float mm = smax[0];
        #pragma unroll
        for (int i = 1; i < 8; i++) mm = fmaxf(mm, smax[i]);
        atomicMax(&g_h2maxsq, __float_as_uint(mm));
    }
}

// ---------------- 128x128x(K) SGEMM (f32x2); store +bias (Chat / P0 / P1) -------
__global__ void __launch_bounds__(256) k_gemm(
    const float* __restrict__ A, const float* __restrict__ Bm,
    float* __restrict__ C, const float* __restrict__ aux, int N, int K)
{
    __shared__ float As[8][132];
    __shared__ float Bs[8][132];
    const int tid = threadIdx.x;
    const int tx = tid & 15, ty = tid >> 4;
    const int bn = blockIdx.x, bm = blockIdx.y;

    unsigned long long acc2[8][4];
    #pragma unroll
    for (int i = 0; i < 8; i++)
        #pragma unroll
        for (int j = 0; j < 4; j++) acc2[i][j] = 0ULL;

    const int lr = tid >> 1;
    const int lc = (tid & 1) * 4;
    const float* Ap = A + (size_t)(bm * 128 + lr) * K + lc;
    const float* Bp = Bm + (size_t)(bn * 128 + lr) * K + lc;
    const bool bvalid = (bn * 128 + lr) < N;

    for (int k0 = 0; k0 < K; k0 += 8) {
        float4 av = *(const float4*)(Ap + k0);
        float4 bv = bvalid ? *(const float4*)(Bp + k0) : make_float4(0.f, 0.f, 0.f, 0.f);
        As[lc + 0][lr] = av.x; As[lc + 1][lr] = av.y; As[lc + 2][lr] = av.z; As[lc + 3][lr] = av.w;
        Bs[lc + 0][lr] = bv.x; Bs[lc + 1][lr] = bv.y; Bs[lc + 2][lr] = bv.z; Bs[lc + 3][lr] = bv.w;
        __syncthreads();
        #pragma unroll
        for (int kk = 0; kk < 8; kk++) {
            float4 a0 = *(const float4*)&As[kk][ty * 4];
            float4 a1 = *(const float4*)&As[kk][64 + ty * 4];
            float4 b0 = *(const float4*)&Bs[kk][tx * 4];
            float4 b1 = *(const float4*)&Bs[kk][64 + tx * 4];
            float a[8] = {a0.x, a0.y, a0.z, a0.w, a1.x, a1.y, a1.z, a1.w};
            unsigned long long bp[4] = {pk2(b0.x, b0.y), pk2(b0.z, b0.w),
                                        pk2(b1.x, b1.y), pk2(b1.z, b1.w)};
            #pragma unroll
            for (int i = 0; i < 8; i++) {
                unsigned long long ap = pk2(a[i], a[i]);
                #pragma unroll
                for (int j = 0; j < 4; j++) fma2(acc2[i][j], ap, bp[j]);
            }
        }
        __syncthreads();
    }

    #pragma unroll
    for (int i = 0; i < 8; i++) {
        int r = bm * 128 + ((i < 4) ? (ty * 4 + i) : (64 + ty * 4 + i - 4));
        #pragma unroll
        for (int jj = 0; jj < 2; jj++) {
            int c0 = (jj == 0) ? (tx * 4) : (64 + tx * 4);
            if (bn * 128 + c0 < N) {
                int cg = bn * 128 + c0;
                float2 p0 = upk2(acc2[i][jj * 2 + 0]);
                float2 p1 = upk2(acc2[i][jj * 2 + 1]);
                float4 v;
                v.x = p0.x + aux[cg + 0];
                v.y = p0.y + aux[cg + 1];
                v.z = p1.x + aux[cg + 2];
                v.w = p1.y + aux[cg + 3];
                *(float4*)(C + (size_t)r * N + cg) = v;
            }
        }
    }
}

// ---------------- ||Chat row|| (inflated upper bound) ----------------------------
__global__ void k_chnorm() {
    int row = blockIdx.x * 8 + (threadIdx.x >> 5);
    int lane = threadIdx.x & 31;
    float2 v = ((const float2*)(g_Chat + (size_t)row * 64))[lane];
    float s = fmaf(v.x, v.x, v.y * v.y);
    #pragma unroll
    for (int o = 16; o; o >>= 1) s += __shfl_xor_sync(0xffffffffu, s, o);
    if (!lane) g_chn[row] = sqrtf(s) * 1.0001f + 1e-20f;
}

// ---------------- stage-0 candidate set (provably sufficient) --------------------
__global__ void k_cand0() {
    __shared__ float red[256];
    int tid = threadIdx.x;
    float H = sqrtf(__uint_as_float(g_h2maxsq)) * 1.0001f;
    float mn = 3.4e38f;
    for (int n = tid; n < NTOK; n += 256)
        mn = fminf(mn, g_gam[n] + 2.f * H * g_chn[n]);
    red[tid] = mn; __syncthreads();
    for (int o = 128; o; o >>= 1) {
        if (tid < o) red[tid] = fminf(red[tid], red[tid + o]);
        __syncthreads();
    }
    if (tid == 0) {
        float thresh = red[0] + 0.05f;
        int cnt = 0;
        for (int n = 0; n < NTOK; n++) {
            if (g_gam[n] - 2.f * H * g_chn[n] <= thresh) {
                g_cand0[cnt] = n; g_slotOf[n] = cnt; cnt++;
            }
        }
        g_n0 = cnt;
    }
}

// ---------------- stage-1 per-slot bases + candidates -----------------------------
__global__ void __launch_bounds__(256) k_s1prep(const float* __restrict__ cb) {
    __shared__ float c0row[512];
    __shared__ float sbase[NTOK];
    __shared__ float red[256];
    int s = blockIdx.x, tid = threadIdx.x;
    if (s >= g_n0) return;
    int v = g_cand0[s];
    if (tid < 128) ((float4*)c0row)[tid] = ((const float4*)(cb + (size_t)v * CBD))[tid];
    __syncthreads();
    float H = sqrtf(__uint_as_float(g_h2maxsq)) * 1.0001f;
    float mn = 3.4e38f;
    for (int n = tid; n < NTOK; n += 256) {
        const float4* r1 = (const float4*)(cb + ((size_t)NTOK + n) * CBD);
        float d = 0.f;
        #pragma unroll 8
        for (int k = 0; k < 128; k++) {
            float4 a = ((const float4*)c0row)[k], b = r1[k];
            d = fmaf(a.x, b.x, d); d = fmaf(a.y, b.y, d);
            d = fmaf(a.z, b.z, d); d = fmaf(a.w, b.w, d);
        }
        float base = fmaf(2.f, d, g_gam[NTOK + n]);
        sbase[n] = base;
        mn = fminf(mn, base + 2.f * H * g_chn[NTOK + n]);
    }
    red[tid] = mn; __syncthreads();
    for (int o = 128; o; o >>= 1) {
        if (tid < o) red[tid] = fminf(red[tid], red[tid + o]);
        __syncthreads();
    }
    if (tid == 0) {
        float thresh = red[0] + 0.05f;
        int cnt = 0;
        for (int n = 0; n < NTOK; n++) {
            if (sbase[n] - 2.f * H * g_chn[NTOK + n] <= thresh) {
                g_c1idx [(size_t)s * NTOK + cnt] = n;
                g_c1base[(size_t)s * NTOK + cnt] = sbase[n];
                cnt++;
            }
        }
        g_n1[s] = cnt;
    }
}

// ---------------- M3 = W^T W, w3b = W^T b, bb = ||b||^2 --------------------------
__global__ void k_m3(const float* __restrict__ be3) {
    int blk = blockIdx.x, tid = threadIdx.x;
    if (blk < 16) {
        int idx = blk * 256 + tid;
        int i = idx >> 6, j = idx & 63;
        const float4* ri = (const float4*)(g_WT3 + (size_t)i * 512);
        const float4* rj = (const float4*)(g_WT3 + (size_t)j * 512);
        float sacc = 0.f;
        for (int k = 0; k < 128; k++) {
            float4 a = ri[k], b = rj[k];
            sacc = fmaf(a.x, b.x, sacc); sacc = fmaf(a.y, b.y, sacc);
            sacc = fmaf(a.z, b.z, sacc); sacc = fmaf(a.w, b.w, sacc);
        }
        g_M3[idx] = sacc;
    } else {
        if (tid < 64) {
            const float4* ri = (const float4*)(g_WT3 + (size_t)tid * 512);
            const float4* rb = (const float4*)be3;
            float sacc = 0.f;
            for (int k = 0; k < 128; k++) {
                float4 a = ri[k], b = rb[k];
                sacc = fmaf(a.x, b.x, sacc); sacc = fmaf(a.y, b.y, sacc);
                sacc = fmaf(a.z, b.z, sacc); sacc = fmaf(a.w, b.w, sacc);
            }
            g_w3b[tid] = sacc;
        } else if (tid == 64) {
            float sacc = 0.f;
            for (int d = 0; d < 512; d++) { float v = be3[d]; sacc = fmaf(v, v, sacc); }
            g_bb = sacc;
        }
    }
}

// ---------------- per-token argmin over candidate sets + loss terms --------------
__global__ void __launch_bounds__(256) k_vq(float* __restrict__ dout) {
    int tid = threadIdx.x;
    int w = tid >> 5, lane = tid & 31;
    int n0 = g_n0;
    double a_q0x = 0, a_q1x = 0, a_c0 = 0, a_c1 = 0, a_G = 0;
    int wbase = (blockIdx.x * 8 + w) * 8;
    float* didx = dout + IDX_OFF;
    for (int r = 0; r < 8; r++) {
        int t = wbase + r;
        float2 h = ((const float2*)(g_H2 + (size_t)t * 64))[lane];
        // stage 0
        float bs = 3.4e38f, bd0 = 0.f; int bi = 0;
        for (int j = 0; j < n0; j++) {
            int c = g_cand0[j];
            float2 cv = ((const float2*)(g_Chat + (size_t)c * 64))[lane];
            float p = fmaf(h.x, cv.x, h.y * cv.y);
            #pragma unroll
            for (int o = 16; o; o >>= 1) p += __shfl_xor_sync(0xffffffffu, p, o);
            float s = fmaf(-2.f, p, g_gam[c]);
            if (s < bs) { bs = s; bi = c; bd0 = p; }
        }
        int i0 = bi;
        int slot = g_slotOf[i0];
        int n1 = g_n1[slot];
        const int*   c1i = g_c1idx  + (size_t)slot * NTOK;
        const float* c1b = g_c1base + (size_t)slot * NTOK;
        bs = 3.4e38f; bi = 0; float bd1 = 0.f, bb1 = 0.f;
        for (int j = 0; j < n1; j++) {
            int c = c1i[j]; float base = c1b[j];
            float2 cv = ((const float2*)(g_Chat + (size_t)(NTOK + c) * 64))[lane];
            float p = fmaf(h.x, cv.x, h.y * cv.y);
            #pragma unroll
            for (int o = 16; o; o >>= 1) p += __shfl_xor_sync(0xffffffffu, p, o);
            float s = fmaf(-2.f, p, base);
            if (s < bs) { bs = s; bi = c; bd1 = p; bb1 = base; }
        }
        int i1 = bi;
        if (lane == 0) {
            g_i0[t] = i0; g_i1[t] = i1;
            didx[2 * t] = (float)i0; didx[2 * t + 1] = (float)i1;
            a_q0x += (double)bd0 + (double)g_bcv[i0];
            a_q1x += (double)bd1 + (double)g_bcv[NTOK + i1];
            a_c0  += (double)g_cn2[i0];
            a_c1  += (double)g_cn2[NTOK + i1];
            a_G   += 0.5 * ((double)bb1 - (double)g_gam[NTOK + i1]);
        }
    }
    __shared__ double sm[8][5];
    if (lane == 0) {
        sm[w][0] = a_q0x; sm[w][1] = a_q1x; sm[w][2] = a_c0; sm[w][3] = a_c1; sm[w][4] = a_G;
    }
    __syncthreads();
    if (tid == 0) {
        double v0 = 0, v1 = 0, v2 = 0, v3 = 0, v4 = 0;
        #pragma unroll
        for (int i = 0; i < 8; i++) {
            v0 += sm[i][0]; v1 += sm[i][1]; v2 += sm[i][2]; v3 += sm[i][3]; v4 += sm[i][4];
        }
        atomicAdd(&g_acc[0], v0); atomicAdd(&g_acc[1], v1);
        atomicAdd(&g_acc[3], v2); atomicAdd(&g_acc[4], v3);
        atomicAdd(&g_acc[5], v4);
    }
}

// ---------------- partial S = H2^T H2 and sum(h2) --------------------------------
__global__ void __launch_bounds__(256) k_Spart() {
    __shared__ float sh2[8 * 64];
    int tid = threadIdx.x, blk = blockIdx.x;
    int t0 = blk * 1632;
    float acc[16];
    #pragma unroll
    for (int i = 0; i < 16; i++) acc[i] = 0.f;
    float hsum = 0.f;
    int ti = tid >> 4, tj = tid & 15;
    for (int g = 0; g < 204; g++) {
        int base = t0 + g * 8;
        if (tid < 128)
            ((float4*)sh2)[tid] = ((const float4*)(g_H2 + (size_t)base * 64))[tid];
        __syncthreads();
        #pragma unroll
        for (int r = 0; r < 8; r++) {
            float4 a = *(const float4*)&sh2[r * 64 + ti * 4];
            float4 b = *(const float4*)&sh2[r * 64 + tj * 4];
            float av[4] = {a.x, a.y, a.z, a.w}, bv[4] = {b.x, b.y, b.z, b.w};
            #pragma unroll
            for (int p = 0; p < 4; p++)
                #pragma unroll
                for (int q = 0; q < 4; q++) acc[p * 4 + q] = fmaf(av[p], bv[q], acc[p * 4 + q]);
        }
        if (tid < 64) {
            #pragma unroll
            for (int r = 0; r < 8; r++) hsum += sh2[r * 64 + tid];
        }
        __syncthreads();
    }
    #pragma unroll
    for (int p = 0; p < 4; p++)
        #pragma unroll
        for (int q = 0; q < 4; q++)
            g_Sp[(size_t)blk * 4096 + (ti * 4 + p) * 64 + (tj * 4 + q)] = acc[p * 4 + q];
    if (tid < 64) g_hp[blk * 64 + tid] = hsum;
}

// ---------------- Sum ||x||^2 = <M3,S> + 2 w3b.sum(h2) + N*bb --------------------
__global__ void k_Sfinal() {
    __shared__ double red[256];
    int tid = threadIdx.x, blk = blockIdx.x;
    int c = blk * 256 + tid;
    float s = 0.f;
    for (int p = 0; p < 64; p++) s += g_Sp[(size_t)p * 4096 + c];
    double partial = (double)s * (double)g_M3[c];
    if (blk == 0) {
        if (tid < 64) {
            float sh = 0.f;
            for (int p = 0; p < 64; p++) sh += g_hp[p * 64 + tid];
            partial += 2.0 * (double)sh * (double)g_w3b[tid];
        } else if (tid == 64) {
            partial += (double)NTOKEN * (double)g_bb;
        }
    }
    red[tid] = partial; __syncthreads();
    for (int o = 128; o; o >>= 1) {
        if (tid < o) red[tid] += red[tid + o];
        __syncthreads();
    }
    if (tid == 0) atomicAdd(&g_acc[6], red[0]);
}

// ---------------- FUSED decoder: indices -> out + recon loss ---------------------
// d1gather + convT2(relu) + final 1x1 conv, 128 t1-rows x 128 cols, K=64. grid=1632.
__global__ void __launch_bounds__(256) k_dec(const float* __restrict__ img,
                                             const float* __restrict__ W3,
                                             const float* __restrict__ b3,
                                             float* __restrict__ dout) {
    __shared__ float Wts[64][132];    // Wd2 transposed: [c][n]
    __shared__ float As[8][132];
    __shared__ int i0s[64], i1s[64];
    __shared__ float bd1s[128], bd2s[128], w3s[64];
    __shared__ double sd[256];
    const int tid = threadIdx.x, bm = blockIdx.x;

    for (int e = tid; e < 8192; e += 256) {
        int n = e >> 6, c = e & 63;
        Wts[c][n] = g_Wd2m[e];
    }
    if (tid < 64) {
        i0s[tid] = g_i0[bm * 64 + tid];
        i1s[tid] = g_i1[bm * 64 + tid];
        w3s[tid] = W3[tid];
    }
    if (tid < 128) { bd1s[tid] = g_bd1x[tid]; bd2s[tid] = g_bd2x[tid]; }
    __syncthreads();

    const int tx = tid & 15, ty = tid >> 4;
    unsigned long long acc2[8][4];
    #pragma unroll
    for (int i = 0; i < 8; i++)
        #pragma unroll
        for (int j = 0; j < 4; j++) acc2[i][j] = 0ULL;

    const int grow = tid & 127, gkh = tid >> 7;
    const int gbase0 = (grow & 1) * 64;
    const float* P0r = g_P0 + (size_t)i0s[grow >> 1] * 128;
    const float* P1r = g_P1 + (size_t)i1s[grow >> 1] * 128;

    for (int k0 = 0; k0 < 64; k0 += 8) {
        {
            int base = gbase0 + k0 + gkh * 4;
            float4 p0 = *(const float4*)(P0r + base);
            float4 p1 = *(const float4*)(P1r + base);
            As[gkh * 4 + 0][grow] = fmaxf(p0.x + p1.x + bd1s[base + 0], 0.f);
            As[gkh * 4 + 1][grow] = fmaxf(p0.y + p1.y + bd1s[base + 1], 0.f);
            As[gkh * 4 + 2][grow] = fmaxf(p0.z + p1.z + bd1s[base + 2], 0.f);
            As[gkh * 4 + 3][grow] = fmaxf(p0.w + p1.w + bd1s[base + 3], 0.f);
        }
        __syncthreads();
        #pragma unroll
        for (int kk = 0; kk < 8; kk++) {
            int kc = k0 + kk;
            float4 a0 = *(const float4*)&As[kk][ty * 4];
            float4 a1 = *(const float4*)&As[kk][64 + ty * 4];
            float4 b0 = *(const float4*)&Wts[kc][tx * 4];
            float4 b1 = *(const float4*)&Wts[kc][64 + tx * 4];
            float a[8] = {a0.x, a0.y, a0.z, a0.w, a1.x, a1.y, a1.z, a1.w};
            unsigned long long bp[4] = {pk2(b0.x, b0.y), pk2(b0.z, b0.w),
                                        pk2(b1.x, b1.y), pk2(b1.z, b1.w)};
            #pragma unroll
            for (int i = 0; i < 8; i++) {
                unsigned long long ap = pk2(a[i], a[i]);
                #pragma unroll
                for (int j = 0; j < 4; j++) fma2(acc2[i][j], ap, bp[j]);
            }
        }
        __syncthreads();
    }

    // epilogue: relu(+bd2), dot with w3, write 2 output samples per row, SSE
    const float b3v = b3[0];
    const int lane = tid & 31;
    const int c0 = tx * 4;
    double lacc = 0.0;
    #pragma unroll
    for (int i = 0; i < 8; i++) {
        int rloc = (i < 4) ? (ty * 4 + i) : (64 + ty * 4 + (i - 4));
        float2 p0 = upk2(acc2[i][0]), p1 = upk2(acc2[i][1]);
        float2 p2 = upk2(acc2[i][2]), p3 = upk2(acc2[i][3]);
        float s0 = fmaxf(p0.x + bd2s[c0 + 0], 0.f) * w3s[c0 + 0]
                 + fmaxf(p0.y + bd2s[c0 + 1], 0.f) * w3s[c0 + 1]
                 + fmaxf(p1.x + bd2s[c0 + 2], 0.f) * w3s[c0 + 2]
                 + fmaxf(p1.y + bd2s[c0 + 3], 0.f) * w3s[c0 + 3];
        float s1 = fmaxf(p2.x + bd2s[64 + c0 + 0], 0.f) * w3s[c0 + 0]
                 + fmaxf(p2.y + bd2s[64 + c0 + 1], 0.f) * w3s[c0 + 1]
                 + fmaxf(p3.x + bd2s[64 + c0 + 2], 0.f) * w3s[c0 + 2]
                 + fmaxf(p3.y + bd2s[64 + c0 + 3], 0.f) * w3s[c0 + 3];
        #pragma unroll
        for (int o = 1; o <= 8; o <<= 1) {
            s0 += __shfl_xor_sync(0xffffffffu, s0, o);
            s1 += __shfl_xor_sync(0xffffffffu, s1, o);
        }
        if ((lane & 15) == 0) {
            int m = bm * 128 + rloc;
            int b = m / T1, t1 = m - b * T1;
            size_t o = (size_t)b * TT + 2 * t1;
            float v0 = s0 + b3v, v1 = s1 + b3v;
            dout[o] = v0; dout[o + 1] = v1;
            float e0 = img[o] - v0, e1 = img[o + 1] - v1;
            lacc += (double)e0 * e0 + (double)e1 * e1;
        }
    }
    sd[tid] = lacc; __syncthreads();
    for (int o = 128; o; o >>= 1) {
        if (tid < o) sd[tid] += sd[tid + o];
        __syncthreads();
    }
    if (!tid) atomicAdd(&g_acc[2], sd[0]);
}

// ---------------- quantized output, directly transposed (4 t per thread) --------
__global__ void k_qout(const float* __restrict__ cb, float* __restrict__ dout) {
    int idx = blockIdx.x * 256 + threadIdx.x;    // over B*CBD*T2/4, exact
    int t4 = idx % (T2 / 4);
    int rd = idx / (T2 / 4);
    int d = rd & 511;
    int b = rd >> 9;
    int tokb = b * T2 + t4 * 4;
    size_t obase = QOFF + (size_t)idx * 4;
    #pragma unroll
    for (int q = 0; q < 4; q++) {
        int tok = tokb + q;
        dout[obase + q] = cb[(size_t)g_i0[tok] * CBD + d]
                        + cb[((size_t)NTOK + g_i1[tok]) * CBD + d];
    }
}

__global__ void k_scalars(float* __restrict__ dout) {
    double denom = (double)NTOKEN * CBD;
    double q0x = g_acc[0], q1x = g_acc[1], c0 = g_acc[3], c1 = g_acc[4];
    double G = g_acc[5], xsq = g_acc[6];
    dout[OUT_N + 0] = (float)(g_acc[2] / (double)OUT_N);
    dout[OUT_N + 1] = (float)((c0 - 2.0 * q0x + xsq) / denom);
    dout[OUT_N + 2] = (float)((c0 + c1 + xsq + 2.0 * G - 2.0 * q0x - 2.0 * q1x) / denom);
}

// ---------------- launch ----------------------------------------------------------
extern "C" void kernel_launch(void* const* d_in, const int* in_sizes, int n_in,
                              void* d_out, int out_size) {
    const float* img   = (const float*)d_in[0];
    const float* W_e1  = (const float*)d_in[1];
    const float* b_e1  = (const float*)d_in[2];
    const float* W_e2  = (const float*)d_in[3];
    const float* b_e2  = (const float*)d_in[4];
    const float* W_e3  = (const float*)d_in[5];
    const float* b_e3  = (const float*)d_in[6];
    const float* cb    = (const float*)d_in[7];
    const float* Wt_d1 = (const float*)d_in[8];
    const float* b_d1  = (const float*)d_in[9];
    const float* Wt_d2 = (const float*)d_in[10];
    const float* b_d2  = (const float*)d_in[11];
    const float* W_d3  = (const float*)d_in[12];
    const float* b_d3  = (const float*)d_in[13];
    float* out = (float*)d_out;

    float *pWT3, *pChat, *pP0, *pP1, *pZero, *pWd1m;
    cudaGetSymbolAddress((void**)&pWT3,  g_WT3);
    cudaGetSymbolAddress((void**)&pChat, g_Chat);
    cudaGetSymbolAddress((void**)&pP0,   g_P0);
    cudaGetSymbolAddress((void**)&pP1,   g_P1);
    cudaGetSymbolAddress((void**)&pZero, g_zero);
    cudaGetSymbolAddress((void**)&pWd1m, g_Wd1m);

    k_init  <<<1, 32>>>();
    k_repack<<<256, 256>>>(W_e2, W_e3, Wt_d1, Wt_d2, b_d1, b_d2);
    k_stats <<<256, 256>>>(cb, b_e3);
    // fused encoder: img -> H2 (+ h2max)
    k_enc   <<<408, 256>>>(img, W_e1, b_e1, b_e2);
    // Chat = C . W_e3 : [2048 x 512] x [512 x 64]
    k_gemm  <<<dim3(1, 16), 256>>>(cb, pWT3, pChat, pZero, 64, 512);
    k_chnorm<<<256, 256>>>();
    k_cand0 <<<1, 256>>>();
    k_s1prep<<<NTOK, 256>>>(cb);
    k_m3    <<<17, 256>>>(b_e3);
    // per-token argmins + index outputs + loss cross terms
    k_vq    <<<1632, 256>>>(out);
    // Sum ||x||^2 via S = H2^T H2
    k_Spart <<<64, 256>>>();
    k_Sfinal<<<16, 256>>>();
    // P = C . Wd1m (per codebook)
    k_gemm  <<<dim3(1, 8), 256>>>(cb, pWd1m, pP0, pZero, 128, 512);
    k_gemm  <<<dim3(1, 8), 256>>>(cb + (size_t)NTOK * CBD, pWd1m, pP1, pZero, 128, 512);
    // fused decoder: indices -> out + recon loss
    k_dec   <<<1632, 256>>>(img, W_d3, b_d3, out);
    // quantized output [b][d][t]
    k_qout  <<<BI * CBD * T2 / 1024, 256>>>(cb, out);
    k_scalars<<<1, 1>>>(out);
}

// round 11
// speedup vs baseline: 10.4840x; 1.5287x over previous
#include <cuda_runtime.h>

#define BI   256
#define TT   1632
#define T1   816
#define T2   408
#define HIDD 64
#define CBD  512
#define NTOK 1024
#define NTOKEN (BI*T2)   /* 104448 */
#define M1     (BI*T1)   /* 208896 */

#define OUT_N   (BI*TT)                 /* 417792 */
#define IDX_OFF (OUT_N + 3)             /* 417795 */
#define QOFF    (IDX_OFF + NTOKEN*2)    /* 626691 */

// ---------------- scratch (__device__ globals; no runtime allocation) ----------
__device__ float g_H2[(size_t)NTOKEN * HIDD];    // h2 [tok][64]
__device__ float g_WT3 [64 * 512];               // W_e3^T [i][d]
__device__ float g_Wcat[192 * 512];              // rows 0..63 = WT3, 64..191 = Wd1m
__device__ float g_Chat[2 * NTOK * 64];          // C . W_e3  [2048][64]
__device__ float g_chn [2 * NTOK];               // ||Chat row|| (inflated)
__device__ float g_gam [2 * NTOK];               // ||c||^2 - 2 b.c
__device__ float g_cn2 [2 * NTOK];               // ||c||^2
__device__ float g_bcv [2 * NTOK];               // b.c
__device__ int   g_cand0[NTOK];
__device__ int   g_n0;
__device__ int   g_slotOf[NTOK];
__device__ int   g_c1idx [(size_t)NTOK * NTOK];  // per-slot stage1 candidates
__device__ float g_c1base[(size_t)NTOK * NTOK];  // gamma1 + 2G[v][n]
__device__ int   g_n1[NTOK];
__device__ int   g_i0[NTOKEN], g_i1[NTOKEN], g_pid[NTOKEN];
__device__ unsigned g_h2maxsq;
__device__ float g_P0[NTOK * 128], g_P1[NTOK * 128];  // C . Wd1m
__device__ float g_ptab[(size_t)NTOK * NTOK * 4];     // 4 out samples per (slot,j) pair
__device__ float g_Sp[128 * 4096];               // partial H2^T H2
__device__ float g_hp[128 * 64];                 // partial sum h2
__device__ float g_M3[64 * 64], g_w3b[64], g_bb;
__device__ float g_W2m [64 * 128];
__device__ float g_Wd2m[128 * 64];
__device__ float g_bd1x[128];
__device__ float g_bd2x[128];
__device__ double g_acc[8];  // 0:Sum q0x 1:Sum q1x 2:recon_sse 3:Sum cn2_0 4:Sum cn2_1 5:Sum G 6:Sum xsq

// ---------------- f32x2 packed helpers ------------------------------------------
__device__ __forceinline__ unsigned long long pk2(float lo, float hi) {
    unsigned long long r;
    asm("mov.b64 %0, {%1,%2};" : "=l"(r) : "f"(lo), "f"(hi));
    return r;
}
__device__ __forceinline__ float2 upk2(unsigned long long v) {
    float2 r;
    asm("mov.b64 {%0,%1}, %2;" : "=f"(r.x), "=f"(r.y) : "l"(v));
    return r;
}
__device__ __forceinline__ void fma2(unsigned long long& d,
                                     unsigned long long a, unsigned long long b) {
    asm("fma.rn.f32x2 %0, %1, %2, %0;" : "+l"(d) : "l"(a), "l"(b));
}

// ---------------- init ---------------------------------------------------------
__global__ void k_init() {
    int i = threadIdx.x;
    if (i < 8) g_acc[i] = 0.0;
    if (i == 8) g_h2maxsq = 0u;
}

// ---------------- weight repack -------------------------------------------------
__global__ void k_repack(const float* __restrict__ W_e2,
                         const float* __restrict__ W_e3,
                         const float* __restrict__ Wt_d1,
                         const float* __restrict__ Wt_d2,
                         const float* __restrict__ b_d1,
                         const float* __restrict__ b_d2) {
    int i = blockIdx.x * 256 + threadIdx.x;      // 0..65535
    if (i < 64 * 128) {                          // W2m[o][k*64+ii] = W_e2[o][ii][k]
        int o = i >> 7, c = i & 127, k = c >> 6, ii = c & 63;
        g_W2m[i] = W_e2[(o * 64 + ii) * 2 + k];
    }
    if (i < 64 * 512) {                          // WT3[ii][d] = W_e3[d][ii]
        int r = i >> 9, d = i & 511;
        float v = W_e3[d * 64 + r];
        g_WT3[i] = v;
        g_Wcat[i] = v;
    }
    if (i < 128 * 512) {                         // Wcat row 64+n: Wd1m[k*64+o][d]
        int n = i >> 9, d = i & 511;
        int k = n >> 6, o = n & 63;
        g_Wcat[64 * 512 + i] = Wt_d1[(d * 64 + o) * 2 + k];
    }
    if (i < 128 * 64) {                          // Wd2m[k*64+o][d] = Wt_d2[d][o][k]
        int n = i >> 6, d = i & 63;
        int k = n >> 6, o = n & 63;
        g_Wd2m[i] = Wt_d2[(d * 64 + o) * 2 + k];
    }
    if (i < 128) { g_bd1x[i] = b_d1[i & 63]; g_bd2x[i] = b_d2[i & 63]; }
}

// ---------------- per-code stats: ||c||^2, b.c, gamma ---------------------------
__global__ void k_stats(const float* __restrict__ cb, const float* __restrict__ be3) {
    int row = blockIdx.x * 8 + (threadIdx.x >> 5);
    int lane = threadIdx.x & 31;
    const float* r = cb + (size_t)row * CBD;
    float s = 0.f, t = 0.f;
    for (int d = lane; d < CBD; d += 32) {
        float v = r[d];
        s = fmaf(v, v, s);
        t = fmaf(v, be3[d], t);
    }
    #pragma unroll
    for (int o = 16; o; o >>= 1) {
        s += __shfl_xor_sync(0xffffffffu, s, o);
        t += __shfl_xor_sync(0xffffffffu, t, o);
    }
    if (!lane) { g_cn2[row] = s; g_bcv[row] = t; g_gam[row] = s - 2.f * t; }
}

// ---------------- FUSED encoder: img -> H2 (conv1 + conv2 + relu) + h2max --------
__global__ void __launch_bounds__(256) k_enc(const float* __restrict__ img,
                                             const float* __restrict__ W_e1,
                                             const float* __restrict__ b_e1,
                                             const float* __restrict__ b_e2) {
    __shared__ float W2ts[128][68];   // W2 transposed: [c][o]
    __shared__ float As[8][260];      // h1 chunk: [kk][row]
    __shared__ float imgs2[4][260];
    __shared__ float We1s[128], b1s[64], b2s[64];
    __shared__ float smax[8];
    const int tid = threadIdx.x, blk = blockIdx.x;

    for (int e = tid; e < 8192; e += 256) {
        int o = e >> 7, c = e & 127;
        W2ts[c][o] = g_W2m[e];
    }
    if (tid < 128) We1s[tid] = W_e1[tid];
    if (tid < 64) { b1s[tid] = b_e1[tid]; b2s[tid] = b_e2[tid]; }
    {
        float4 iv = ((const float4*)img)[blk * 256 + tid];
        imgs2[0][tid] = iv.x; imgs2[1][tid] = iv.y;
        imgs2[2][tid] = iv.z; imgs2[3][tid] = iv.w;
    }
    __syncthreads();

    const int tx = tid & 7, ty = tid >> 3;
    unsigned long long acc2[8][4];
    #pragma unroll
    for (int i = 0; i < 8; i++)
        #pragma unroll
        for (int j = 0; j < 4; j++) acc2[i][j] = 0ULL;

    for (int k0 = 0; k0 < 128; k0 += 8) {
        #pragma unroll
        for (int u = 0; u < 8; u++) {
            int c = k0 + u, kp = c >> 6, ii = c & 63;
            float v = fmaf(We1s[2 * ii], imgs2[2 * kp][tid],
                     fmaf(We1s[2 * ii + 1], imgs2[2 * kp + 1][tid], b1s[ii]));
            As[u][tid] = fmaxf(v, 0.f);
        }
        __syncthreads();
        #pragma unroll
        for (int kk = 0; kk < 8; kk++) {
            int kc = k0 + kk;
            float4 a0 = *(const float4*)&As[kk][ty * 4];
            float4 a1 = *(const float4*)&As[kk][128 + ty * 4];
            float4 b0 = *(const float4*)&W2ts[kc][tx * 4];
            float4 b1v = *(const float4*)&W2ts[kc][32 + tx * 4];
            float a[8] = {a0.x, a0.y, a0.z, a0.w, a1.x, a1.y, a1.z, a1.w};
            unsigned long long bp[4] = {pk2(b0.x, b0.y), pk2(b0.z, b0.w),
                                        pk2(b1v.x, b1v.y), pk2(b1v.z, b1v.w)};
            #pragma unroll
            for (int i = 0; i < 8; i++) {
                unsigned long long ap = pk2(a[i], a[i]);
                #pragma unroll
                for (int j = 0; j < 4; j++) fma2(acc2[i][j], ap, bp[j]);
            }
        }
        __syncthreads();
    }

    float mrow = 0.f;
    #pragma unroll
    for (int i = 0; i < 8; i++) {
        int rloc = (i < 4) ? (ty * 4 + i) : (128 + ty * 4 + (i - 4));
        int tok = blk * 256 + rloc;
        float ssq = 0.f;
        #pragma unroll
        for (int jj = 0; jj < 2; jj++) {
            int c0 = (jj == 0) ? (tx * 4) : (32 + tx * 4);
            float2 p0 = upk2(acc2[i][jj * 2 + 0]);
            float2 p1 = upk2(acc2[i][jj * 2 + 1]);
            float4 v;
            v.x = fmaxf(p0.x + b2s[c0 + 0], 0.f);
            v.y = fmaxf(p0.y + b2s[c0 + 1], 0.f);
            v.z = fmaxf(p1.x + b2s[c0 + 2], 0.f);
            v.w = fmaxf(p1.y + b2s[c0 + 3], 0.f);
            ssq = fmaf(v.x, v.x, ssq); ssq = fmaf(v.y, v.y, ssq);
            ssq = fmaf(v.z, v.z, ssq); ssq = fmaf(v.w, v.w, ssq);
            *(float4*)(g_H2 + (size_t)tok * 64 + c0) = v;
        }
        ssq += __shfl_xor_sync(0xffffffffu, ssq, 1);
        ssq += __shfl_xor_sync(0xffffffffu, ssq, 2);
        ssq += __shfl_xor_sync(0xffffffffu, ssq, 4);
        mrow = fmaxf(mrow, ssq);
    }
    mrow = fmaxf(mrow, __shfl_xor_sync(0xffffffffu, mrow, 8));
    mrow = fmaxf(mrow, __shfl_xor_sync(0xffffffffu, mrow, 16));
    if ((tid & 31) == 0) smax[tid >> 5] = mrow;
    __syncthreads();
    if (tid == 0) {
        float mm = smax[0];
        #pragma unroll
        for (int i = 1; i < 8; i++) mm = fmaxf(mm, smax[i]);
        atomicMax(&g_h2maxsq, __float_as_uint(mm));
    }
}

// ---------------- combined weight GEMM: cb[2048x512] . Wcat^T -> Chat|P0|P1 ------
__global__ void __launch_bounds__(256) k_wgemm(const float* __restrict__ cb) {
    __shared__ float As[8][132];
    __shared__ float Bs[8][132];
    const int tid = threadIdx.x;
    const int tx = tid & 15, ty = tid >> 4;
    const int bn = blockIdx.x, bm = blockIdx.y;
    const int N = 192, K = 512;

    unsigned long long acc2[8][4];
    #pragma unroll
    for (int i = 0; i < 8; i++)
        #pragma unroll
        for (int j = 0; j < 4; j++) acc2[i][j] = 0ULL;

    const int lr = tid >> 1;
    const int lc = (tid & 1) * 4;
    const float* Ap = cb + (size_t)(bm * 128 + lr) * K + lc;
    const float* Bp = g_Wcat + (size_t)(bn * 128 + lr) * K + lc;
    const bool bvalid = (bn * 128 + lr) < N;

    for (int k0 = 0; k0 < K; k0 += 8) {
        float4 av = *(const float4*)(Ap + k0);
        float4 bv = bvalid ? *(const float4*)(Bp + k0) : make_float4(0.f, 0.f, 0.f, 0.f);
        As[lc + 0][lr] = av.x; As[lc + 1][lr] = av.y; As[lc + 2][lr] = av.z; As[lc + 3][lr] = av.w;
        Bs[lc + 0][lr] = bv.x; Bs[lc + 1][lr] = bv.y; Bs[lc + 2][lr] = bv.z; Bs[lc + 3][lr] = bv.w;
        __syncthreads();
        #pragma unroll
        for (int kk = 0; kk < 8; kk++) {
            float4 a0 = *(const float4*)&As[kk][ty * 4];
            float4 a1 = *(const float4*)&As[kk][64 + ty * 4];
            float4 b0 = *(const float4*)&Bs[kk][tx * 4];
            float4 b1 = *(const float4*)&Bs[kk][64 + tx * 4];
            float a[8] = {a0.x, a0.y, a0.z, a0.w, a1.x, a1.y, a1.z, a1.w};
            unsigned long long bp[4] = {pk2(b0.x, b0.y), pk2(b0.z, b0.w),
                                        pk2(b1.x, b1.y), pk2(b1.z, b1.w)};
            #pragma unroll
            for (int i = 0; i < 8; i++) {
                unsigned long long ap = pk2(a[i], a[i]);
                #pragma unroll
                for (int j = 0; j < 4; j++) fma2(acc2[i][j], ap, bp[j]);
            }
        }
        __syncthreads();
    }

    #pragma unroll
    for (int i = 0; i < 8; i++) {
        int r = bm * 128 + ((i < 4) ? (ty * 4 + i) : (64 + ty * 4 + i - 4));
        #pragma unroll
        for (int jj = 0; jj < 2; jj++) {
            int c0 = (jj == 0) ? (tx * 4) : (64 + tx * 4);
            int cg = bn * 128 + c0;
            if (cg < N) {
                float2 p0 = upk2(acc2[i][jj * 2 + 0]);
                float2 p1 = upk2(acc2[i][jj * 2 + 1]);
                float4 v = make_float4(p0.x, p0.y, p1.x, p1.y);
                if (cg < 64) {
                    *(float4*)(g_Chat + (size_t)r * 64 + cg) = v;
                } else {
                    float* P = (r < NTOK) ? g_P0 : g_P1;
                    *(float4*)(P + (size_t)(r & (NTOK - 1)) * 128 + (cg - 64)) = v;
                }
            }
        }
    }
}

// ---------------- ||Chat row|| (inflated upper bound) ----------------------------
__global__ void k_chnorm() {
    int row = blockIdx.x * 8 + (threadIdx.x >> 5);
    int lane = threadIdx.x & 31;
    float2 v = ((const float2*)(g_Chat + (size_t)row * 64))[lane];
    float s = fmaf(v.x, v.x, v.y * v.y);
    #pragma unroll
    for (int o = 16; o; o >>= 1) s += __shfl_xor_sync(0xffffffffu, s, o);
    if (!lane) g_chn[row] = sqrtf(s) * 1.0001f + 1e-20f;
}

// ---------------- stage-0 candidate set (provably sufficient) --------------------
__global__ void k_cand0() {
    __shared__ float red[256];
    int tid = threadIdx.x;
    float H = sqrtf(__uint_as_float(g_h2maxsq)) * 1.0001f;
    float mn = 3.4e38f;
    for (int n = tid; n < NTOK; n += 256)
        mn = fminf(mn, g_gam[n] + 2.f * H * g_chn[n]);
    red[tid] = mn; __syncthreads();
    for (int o = 128; o; o >>= 1) {
        if (tid < o) red[tid] = fminf(red[tid], red[tid + o]);
        __syncthreads();
    }
    if (tid == 0) {
        float thresh = red[0] + 0.05f;
        int cnt = 0;
        for (int n = 0; n < NTOK; n++) {
            if (g_gam[n] - 2.f * H * g_chn[n] <= thresh) {
                g_cand0[cnt] = n; g_slotOf[n] = cnt; cnt++;
            }
        }
        g_n0 = cnt;
    }
}

// ---------------- stage-1 per-slot bases + candidates -----------------------------
__global__ void __launch_bounds__(256) k_s1prep(const float* __restrict__ cb) {
    __shared__ float c0row[512];
    __shared__ float sbase[NTOK];
    __shared__ float red[256];
    int s = blockIdx.x, tid = threadIdx.x;
    if (s >= g_n0) return;
    int v = g_cand0[s];
    if (tid < 128) ((float4*)c0row)[tid] = ((const float4*)(cb + (size_t)v * CBD))[tid];
    __syncthreads();
    float H = sqrtf(__uint_as_float(g_h2maxsq)) * 1.0001f;
    float mn = 3.4e38f;
    for (int n = tid; n < NTOK; n += 256) {
        const float4* r1 = (const float4*)(cb + ((size_t)NTOK + n) * CBD);
        float d = 0.f;
        #pragma unroll 8
        for (int k = 0; k < 128; k++) {
            float4 a = ((const float4*)c0row)[k], b = r1[k];
            d = fmaf(a.x, b.x, d); d = fmaf(a.y, b.y, d);
            d = fmaf(a.z, b.z, d); d = fmaf(a.w, b.w, d);
        }
        float base = fmaf(2.f, d, g_gam[NTOK + n]);
        sbase[n] = base;
        mn = fminf(mn, base + 2.f * H * g_chn[NTOK + n]);
    }
    red[tid] = mn; __syncthreads();
    for (int o = 128; o; o >>= 1) {
        if (tid < o) red[tid] = fminf(red[tid], red[tid + o]);
        __syncthreads();
    }
    if (tid == 0) {
        float thresh = red[0] + 0.05f;
        int cnt = 0;
        for (int n = 0; n < NTOK; n++) {
            if (sbase[n] - 2.f * H * g_chn[NTOK + n] <= thresh) {
                g_c1idx [(size_t)s * NTOK + cnt] = n;
                g_c1base[(size_t)s * NTOK + cnt] = sbase[n];
                cnt++;
            }
        }
        g_n1[s] = cnt;
    }
}

// ---------------- M3 = W^T W, w3b = W^T b, bb = ||b||^2 --------------------------
__global__ void k_m3(const float* __restrict__ be3) {
    int blk = blockIdx.x, tid = threadIdx.x;
    if (blk < 16) {
        int idx = blk * 256 + tid;
        int i = idx >> 6, j = idx & 63;
        const float4* ri = (const float4*)(g_WT3 + (size_t)i * 512);
        const float4* rj = (const float4*)(g_WT3 + (size_t)j * 512);
        float sacc = 0.f;
        for (int k = 0; k < 128; k++) {
            float4 a = ri[k], b = rj[k];
            sacc = fmaf(a.x, b.x, sacc); sacc = fmaf(a.y, b.y, sacc);
            sacc = fmaf(a.z, b.z, sacc); sacc = fmaf(a.w, b.w, sacc);
        }
        g_M3[idx] = sacc;
    } else {
        if (tid < 64) {
            const float4* ri = (const float4*)(g_WT3 + (size_t)tid * 512);
            const float4* rb = (const float4*)be3;
            float sacc = 0.f;
            for (int k = 0; k < 128; k++) {
                float4 a = ri[k], b = rb[k];
                sacc = fmaf(a.x, b.x, sacc); sacc = fmaf(a.y, b.y, sacc);
                sacc = fmaf(a.z, b.z, sacc); sacc = fmaf(a.w, b.w, sacc);
            }
            g_w3b[tid] = sacc;
        } else if (tid == 64) {
            float sacc = 0.f;
            for (int d = 0; d < 512; d++) { float v = be3[d]; sacc = fmaf(v, v, sacc); }
            g_bb = sacc;
        }
    }
}

// ---------------- pair table: 4 decoder output samples per (slot, j) pair --------
__global__ void __launch_bounds__(256) k_ptab(const float* __restrict__ W3,
                                              const float* __restrict__ b3) {
    int s = blockIdx.y;
    if (s >= g_n0) return;
    __shared__ float Wts[64][128];    // [c][n]
    __shared__ float d1s[2][64];
    __shared__ float bd1s[128], bd2s[128], w3s[64];
    __shared__ float sred[256];
    const int tid = threadIdx.x;
    for (int e = tid; e < 8192; e += 256) {
        int n = e >> 6, c = e & 63;
        Wts[c][n] = g_Wd2m[e];
    }
    if (tid < 128) { bd1s[tid] = g_bd1x[tid]; bd2s[tid] = g_bd2x[tid]; }
    if (tid < 64) w3s[tid] = W3[tid];
    const float b3v = b3[0];
    const int n1 = g_n1[s];
    const int i0 = g_cand0[s];
    const float* P0r = g_P0 + (size_t)i0 * 128;
    __syncthreads();

    const int p = tid >> 7, n = tid & 127;
    for (int j = blockIdx.x; j < n1; j += 16) {
        int i1 = g_c1idx[(size_t)s * NTOK + j];
        if (tid < 128)
            d1s[tid >> 6][tid & 63] =
                fmaxf(P0r[tid] + g_P1[(size_t)i1 * 128 + tid] + bd1s[tid], 0.f);
        __syncthreads();
        float v = bd2s[n];
        #pragma unroll 16
        for (int c = 0; c < 64; c++) v = fmaf(d1s[p][c], Wts[c][n], v);
        v = fmaxf(v, 0.f) * w3s[n & 63];
        sred[tid] = v;
        __syncthreads();
        if ((tid & 63) < 32) {
            float x = sred[tid] + sred[tid + 32];
            #pragma unroll
            for (int o = 16; o; o >>= 1) x += __shfl_down_sync(0xffffffffu, x, o);
            if ((tid & 63) == 0)
                g_ptab[((size_t)s * NTOK + j) * 4 + (tid >> 6)] = x + b3v;
        }
        __syncthreads();
    }
}

// ---------------- per-token argmin over candidate sets + loss terms --------------
__global__ void __launch_bounds__(256) k_vq(float* __restrict__ dout) {
    int tid = threadIdx.x;
    int w = tid >> 5, lane = tid & 31;
    int n0 = g_n0;
    double a_q0x = 0, a_q1x = 0, a_c0 = 0, a_c1 = 0, a_G = 0;
    int wbase = (blockIdx.x * 8 + w) * 8;
    float* didx = dout + IDX_OFF;
    for (int r = 0; r < 8; r++) {
        int t = wbase + r;
        float2 h = ((const float2*)(g_H2 + (size_t)t * 64))[lane];
        float bs = 3.4e38f, bd0 = 0.f; int bi = 0;
        for (int j = 0; j < n0; j++) {
            int c = g_cand0[j];
            float2 cv = ((const float2*)(g_Chat + (size_t)c * 64))[lane];
            float p = fmaf(h.x, cv.x, h.y * cv.y);
            #pragma unroll
            for (int o = 16; o; o >>= 1) p += __shfl_xor_sync(0xffffffffu, p, o);
            float s = fmaf(-2.f, p, g_gam[c]);
            if (s < bs) { bs = s; bi = c; bd0 = p; }
        }
        int i0 = bi;
        int slot = g_slotOf[i0];
        int n1 = g_n1[slot];
        const int*   c1i = g_c1idx  + (size_t)slot * NTOK;
        const float* c1b = g_c1base + (size_t)slot * NTOK;
        bs = 3.4e38f; bi = 0; float bd1 = 0.f, bb1 = 0.f; int bj = 0;
        for (int j = 0; j < n1; j++) {
            int c = c1i[j]; float base = c1b[j];
            float2 cv = ((const float2*)(g_Chat + (size_t)(NTOK + c) * 64))[lane];
            float p = fmaf(h.x, cv.x, h.y * cv.y);
            #pragma unroll
            for (int o = 16; o; o >>= 1) p += __shfl_xor_sync(0xffffffffu, p, o);
            float s = fmaf(-2.f, p, base);
            if (s < bs) { bs = s; bi = c; bd1 = p; bb1 = base; bj = j; }
        }
        int i1 = bi;
        if (lane == 0) {
            g_i0[t] = i0; g_i1[t] = i1;
            g_pid[t] = slot * NTOK + bj;
            didx[2 * t] = (float)i0; didx[2 * t + 1] = (float)i1;
            a_q0x += (double)bd0 + (double)g_bcv[i0];
            a_q1x += (double)bd1 + (double)g_bcv[NTOK + i1];
            a_c0  += (double)g_cn2[i0];
            a_c1  += (double)g_cn2[NTOK + i1];
            a_G   += 0.5 * ((double)bb1 - (double)g_gam[NTOK + i1]);
        }
    }
    __shared__ double sm[8][5];
    if (lane == 0) {
        sm[w][0] = a_q0x; sm[w][1] = a_q1x; sm[w][2] = a_c0; sm[w][3] = a_c1; sm[w][4] = a_G;
    }
    __syncthreads();
    if (tid == 0) {
        double v0 = 0, v1 = 0, v2 = 0, v3 = 0, v4 = 0;
        #pragma unroll
        for (int i = 0; i < 8; i++) {
            v0 += sm[i][0]; v1 += sm[i][1]; v2 += sm[i][2]; v3 += sm[i][3]; v4 += sm[i][4];
        }
        atomicAdd(&g_acc[0], v0); atomicAdd(&g_acc[1], v1);
        atomicAdd(&g_acc[3], v2); atomicAdd(&g_acc[4], v3);
        atomicAdd(&g_acc[5], v4);
    }
}

// ---------------- partial S = H2^T H2 and sum(h2) --------------------------------
__global__ void __launch_bounds__(256) k_Spart() {
    __shared__ float sh2[8 * 64];
    int tid = threadIdx.x, blk = blockIdx.x;
    int t0 = blk * 816;
    float acc[16];
    #pragma unroll
    for (int i = 0; i < 16; i++) acc[i] = 0.f;
    float hsum = 0.f;
    int ti = tid >> 4, tj = tid & 15;
    for (int g = 0; g < 102; g++) {
        int base = t0 + g * 8;
        if (tid < 128)
            ((float4*)sh2)[tid] = ((const float4*)(g_H2 + (size_t)base * 64))[tid];
        __syncthreads();
        #pragma unroll
        for (int r = 0; r < 8; r++) {
            float4 a = *(const float4*)&sh2[r * 64 + ti * 4];
            float4 b = *(const float4*)&sh2[r * 64 + tj * 4];
            float av[4] = {a.x, a.y, a.z, a.w}, bv[4] = {b.x, b.y, b.z, b.w};
            #pragma unroll
            for (int p = 0; p < 4; p++)
                #pragma unroll
                for (int q = 0; q < 4; q++) acc[p * 4 + q] = fmaf(av[p], bv[q], acc[p * 4 + q]);
        }
        if (tid < 64) {
            #pragma unroll
            for (int r = 0; r < 8; r++) hsum += sh2[r * 64 + tid];
        }
        __syncthreads();
    }
    #pragma unroll
    for (int p = 0; p < 4; p++)
        #pragma unroll
        for (int q = 0; q < 4; q++)
            g_Sp[(size_t)blk * 4096 + (ti * 4 + p) * 64 + (tj * 4 + q)] = acc[p * 4 + q];
    if (tid < 64) g_hp[blk * 64 + tid] = hsum;
}

// ---------------- Sum ||x||^2 = <M3,S> + 2 w3b.sum(h2) + N*bb --------------------
__global__ void k_Sfinal() {
    __shared__ double red[256];
    int tid = threadIdx.x, blk = blockIdx.x;
    int c = blk * 256 + tid;
    float s = 0.f;
    for (int p = 0; p < 128; p++) s += g_Sp[(size_t)p * 4096 + c];
    double partial = (double)s * (double)g_M3[c];
    if (blk == 0) {
        if (tid < 64) {
            float sh = 0.f;
            for (int p = 0; p < 128; p++) sh += g_hp[p * 64 + tid];
            partial += 2.0 * (double)sh * (double)g_w3b[tid];
        } else if (tid == 64) {
            partial += (double)NTOKEN * (double)g_bb;
        }
    }
    red[tid] = partial; __syncthreads();
    for (int o = 128; o; o >>= 1) {
        if (tid < o) red[tid] += red[tid + o];
        __syncthreads();
    }
    if (tid == 0) atomicAdd(&g_acc[6], red[0]);
}

// ---------------- decoder output via pair gather + recon loss --------------------
__global__ void __launch_bounds__(256) k_out(const float* __restrict__ img,
                                             float* __restrict__ dout) {
    __shared__ double sd[256];
    int tid = threadIdx.x;
    int tok = blockIdx.x * 256 + tid;          // grid = 408, exact
    int pid = g_pid[tok];
    float4 v = ((const float4*)g_ptab)[pid];
    int b = tok / T2, t2 = tok - b * T2;
    size_t o = (size_t)b * TT + 4 * t2;
    *(float4*)(dout + o) = v;
    float4 iv = *(const float4*)(img + o);
    float e0 = iv.x - v.x, e1 = iv.y - v.y, e2 = iv.z - v.z, e3 = iv.w - v.w;
    sd[tid] = (double)e0 * e0 + (double)e1 * e1 + (double)e2 * e2 + (double)e3 * e3;
    __syncthreads();
    for (int o2 = 128; o2; o2 >>= 1) {
        if (tid < o2) sd[tid] += sd[tid + o2];
        __syncthreads();
    }
    if (!tid) atomicAdd(&g_acc[2], sd[0]);
}

// ---------------- quantized output, tiled transpose (coalesced both ways) --------
__global__ void __launch_bounds__(256) k_qout(const float* __restrict__ cb,
                                              float* __restrict__ dout) {
    __shared__ float sq[408 * 17];
    const int tid = threadIdx.x;
    const int d0 = blockIdx.x * 16;
    const int b = blockIdx.y;
    // load: token rows, coalesced 64B gathers per codebook row
    for (int tt = tid; tt < T2; tt += 256) {
        int tok = b * T2 + tt;
        const float4* r0 = (const float4*)(cb + (size_t)g_i0[tok] * CBD + d0);
        const float4* r1 = (const float4*)(cb + ((size_t)NTOK + g_i1[tok]) * CBD + d0);
        #pragma unroll
        for (int q = 0; q < 4; q++) {
            float4 a = r0[q], c = r1[q];
            sq[tt * 17 + q * 4 + 0] = a.x + c.x;
            sq[tt * 17 + q * 4 + 1] = a.y + c.y;
            sq[tt * 17 + q * 4 + 2] = a.z + c.z;
            sq[tt * 17 + q * 4 + 3] = a.w + c.w;
        }
    }
    __syncthreads();
    // write: per d row, 128B coalesced stores
    const int w = tid >> 5, lane = tid & 31;
    #pragma unroll
    for (int it = 0; it < 2; it++) {
        int d = it * 8 + w;
        size_t base = QOFF + ((size_t)b * CBD + d0 + d) * T2;
        #pragma unroll
        for (int j = 0; j < 13; j++) {
            int t = j * 32 + lane;
            if (t < T2) dout[base + t] = sq[t * 17 + d];
        }
    }
}

__global__ void k_scalars(float* __restrict__ dout) {
    double denom = (double)NTOKEN * CBD;
    double q0x = g_acc[0], q1x = g_acc[1], c0 = g_acc[3], c1 = g_acc[4];
    double G = g_acc[5], xsq = g_acc[6];
    dout[OUT_N + 0] = (float)(g_acc[2] / (double)OUT_N);
    dout[OUT_N + 1] = (float)((c0 - 2.0 * q0x + xsq) / denom);
    dout[OUT_N + 2] = (float)((c0 + c1 + xsq + 2.0 * G - 2.0 * q0x - 2.0 * q1x) / denom);
}

// ---------------- launch ----------------------------------------------------------
extern "C" void kernel_launch(void* const* d_in, const int* in_sizes, int n_in,
                              void* d_out, int out_size) {
    const float* img   = (const float*)d_in[0];
    const float* W_e1  = (const float*)d_in[1];
    const float* b_e1  = (const float*)d_in[2];
    const float* W_e2  = (const float*)d_in[3];
    const float* b_e2  = (const float*)d_in[4];
    const float* W_e3  = (const float*)d_in[5];
    const float* b_e3  = (const float*)d_in[6];
    const float* cb    = (const float*)d_in[7];
    const float* Wt_d1 = (const float*)d_in[8];
    const float* b_d1  = (const float*)d_in[9];
    const float* Wt_d2 = (const float*)d_in[10];
    const float* b_d2  = (const float*)d_in[11];
    const float* W_d3  = (const float*)d_in[12];
    const float* b_d3  = (const float*)d_in[13];
    float* out = (float*)d_out;

    k_init  <<<1, 32>>>();
    k_repack<<<256, 256>>>(W_e2, W_e3, Wt_d1, Wt_d2, b_d1, b_d2);
    k_stats <<<256, 256>>>(cb, b_e3);
    // fused encoder: img -> H2 (+ h2max)
    k_enc   <<<408, 256>>>(img, W_e1, b_e1, b_e2);
    // combined: Chat | P0 | P1 in one GEMM wave
    k_wgemm <<<dim3(2, 16), 256>>>(cb);
    k_chnorm<<<256, 256>>>();
    k_cand0 <<<1, 256>>>();
    k_s1prep<<<NTOK, 256>>>(cb);
    k_m3    <<<17, 256>>>(b_e3);
    // decoder pair table (per stage-1 candidate pair)
    k_ptab  <<<dim3(16, NTOK), 256>>>(W_d3, b_d3);
    // per-token argmins + index outputs + loss cross terms
    k_vq    <<<1632, 256>>>(out);
    // Sum ||x||^2 via S = H2^T H2
    k_Spart <<<128, 256>>>();
    k_Sfinal<<<16, 256>>>();
    // decoder output gather + recon loss
    k_out   <<<408, 256>>>(img, out);
    // quantized output [b][d][t]
    k_qout  <<<dim3(32, BI), 256>>>(cb, out);
    k_scalars<<<1, 1>>>(out);
}

// round 12
// speedup vs baseline: 13.6502x; 1.3020x over previous
#include <cuda_runtime.h>

#define BI   256
#define TT   1632
#define T1   816
#define T2   408
#define HIDD 64
#define CBD  512
#define NTOK 1024
#define NTOKEN (BI*T2)   /* 104448 */
#define M1     (BI*T1)   /* 208896 */

#define OUT_N   (BI*TT)                 /* 417792 */
#define IDX_OFF (OUT_N + 3)             /* 417795 */
#define QOFF    (IDX_OFF + NTOKEN*2)    /* 626691 */

// ---------------- scratch ---------------------------------------------------------
__device__ float g_H2[(size_t)NTOKEN * HIDD];
__device__ float g_Wcat[192 * 512];              // rows 0..63 = W_e3^T, 64..191 = Wd1m
__device__ float g_Chat[2 * NTOK * 64];
__device__ float g_chn [2 * NTOK];
__device__ float g_gam [2 * NTOK];
__device__ float g_cn2 [2 * NTOK];
__device__ float g_bcv [2 * NTOK];
__device__ int   g_cand0[NTOK];
__device__ int   g_n0;
__device__ int   g_slotOf[NTOK];
__device__ float g_c1full[(size_t)NTOK * NTOK];  // all stage-1 bases per slot
__device__ unsigned g_minU[NTOK];                // per-slot min upper bound (ordered uint)
__device__ int   g_c1idx [(size_t)NTOK * NTOK];
__device__ float g_c1base[(size_t)NTOK * NTOK];
__device__ int   g_n1[NTOK];
__device__ int   g_i0[NTOKEN], g_i1[NTOKEN], g_pid[NTOKEN];
__device__ unsigned g_h2maxsq;
__device__ float g_P0[NTOK * 128], g_P1[NTOK * 128];
__device__ float g_ptab[(size_t)NTOK * NTOK * 4];
__device__ float g_S[4096];                      // H2^T H2 (atomic accum)
__device__ float g_hsum[64];                     // sum h2 (atomic accum)
__device__ float g_M3[4096], g_w3b[64], g_bb;
__device__ float g_W2m [64 * 128];
__device__ float g_Wd2m[128 * 64];
__device__ float g_bd1x[128];
__device__ float g_bd2x[128];
__device__ double g_acc[8];

// ---------------- f32x2 packed helpers --------------------------------------------
__device__ __forceinline__ unsigned long long pk2(float lo, float hi) {
    unsigned long long r;
    asm("mov.b64 %0, {%1,%2};" : "=l"(r) : "f"(lo), "f"(hi));
    return r;
}
__device__ __forceinline__ float2 upk2(unsigned long long v) {
    float2 r;
    asm("mov.b64 {%0,%1}, %2;" : "=f"(r.x), "=f"(r.y) : "l"(v));
    return r;
}
__device__ __forceinline__ void fma2(unsigned long long& d,
                                     unsigned long long a, unsigned long long b) {
    asm("fma.rn.f32x2 %0, %1, %2, %0;" : "+l"(d) : "l"(a), "l"(b));
}
__device__ __forceinline__ unsigned fenc(float f) {
    unsigned u = __float_as_uint(f);
    return (u & 0x80000000u) ? ~u : (u | 0x80000000u);
}
__device__ __forceinline__ float fdec(unsigned u) {
    return __uint_as_float((u & 0x80000000u) ? (u ^ 0x80000000u) : ~u);
}

// ---------------- prep: init + repack ---------------------------------------------
__global__ void k_prep(const float* __restrict__ W_e2,
                       const float* __restrict__ W_e3,
                       const float* __restrict__ Wt_d1,
                       const float* __restrict__ Wt_d2,
                       const float* __restrict__ b_d1,
                       const float* __restrict__ b_d2) {
    int blk = blockIdx.x, tid = threadIdx.x;
    if (blk < 256) {
        int i = blk * 256 + tid;
        if (i < 64 * 128) {
            int o = i >> 7, c = i & 127, k = c >> 6, ii = c & 63;
            g_W2m[i] = W_e2[(o * 64 + ii) * 2 + k];
        }
        if (i < 64 * 512) {
            int r = i >> 9, d = i & 511;
            g_Wcat[i] = W_e3[d * 64 + r];
        }
        if (i < 128 * 512) {
            int n = i >> 9, d = i & 511;
            int k = n >> 6, o = n & 63;
            g_Wcat[64 * 512 + i] = Wt_d1[(d * 64 + o) * 2 + k];
        }
        if (i < 128 * 64) {
            int n = i >> 6, d = i & 63;
            int k = n >> 6, o = n & 63;
            g_Wd2m[i] = Wt_d2[(d * 64 + o) * 2 + k];
        }
        if (i < 128) { g_bd1x[i] = b_d1[i & 63]; g_bd2x[i] = b_d2[i & 63]; }
    } else if (blk == 256) {
        if (tid < 8) g_acc[tid] = 0.0;
        if (tid == 8) g_h2maxsq = 0u;
        #pragma unroll
        for (int q = 0; q < 4; q++) g_minU[q * 256 + tid] = 0xFFFFFFFFu;
        if (tid < 64) g_hsum[tid] = 0.f;
    } else {
        #pragma unroll
        for (int q = 0; q < 16; q++) g_S[q * 256 + tid] = 0.f;
    }
}

// =================== MEGA 1: enc | wgemm(+chnorm) | m3 | stats =====================
__global__ void __launch_bounds__(256) k_mega1(
    const float* __restrict__ img, const float* __restrict__ W_e1,
    const float* __restrict__ b_e1, const float* __restrict__ b_e2,
    const float* __restrict__ cb, const float* __restrict__ W_e3,
    const float* __restrict__ be3)
{
    __shared__ __align__(16) char sbuf[48352];
    const int tid = threadIdx.x;
    const int b = blockIdx.x;

    if (b < 408) {
        // ---------------- fused encoder ----------------
        float (*W2ts)[68] = (float(*)[68])(sbuf);                 // 34816B
        float (*As)[260]  = (float(*)[260])(sbuf + 34816);        // 8320B
        float (*imgs2)[260] = (float(*)[260])(sbuf + 43136);      // 4160B
        float* We1s = (float*)(sbuf + 47296);
        float* b1s  = (float*)(sbuf + 47808);
        float* b2s  = (float*)(sbuf + 48064);
        float* smax = (float*)(sbuf + 48320);
        const int blk = b;

        for (int e = tid; e < 8192; e += 256) {
            int o = e >> 7, c = e & 127;
            W2ts[c][o] = g_W2m[e];
        }
        if (tid < 128) We1s[tid] = W_e1[tid];
        if (tid < 64) { b1s[tid] = b_e1[tid]; b2s[tid] = b_e2[tid]; }
        {
            float4 iv = ((const float4*)img)[blk * 256 + tid];
            imgs2[0][tid] = iv.x; imgs2[1][tid] = iv.y;
            imgs2[2][tid] = iv.z; imgs2[3][tid] = iv.w;
        }
        __syncthreads();

        const int tx = tid & 7, ty = tid >> 3;
        unsigned long long acc2[8][4];
        #pragma unroll
        for (int i = 0; i < 8; i++)
            #pragma unroll
            for (int j = 0; j < 4; j++) acc2[i][j] = 0ULL;

        for (int k0 = 0; k0 < 128; k0 += 8) {
            #pragma unroll
            for (int u = 0; u < 8; u++) {
                int c = k0 + u, kp = c >> 6, ii = c & 63;
                float v = fmaf(We1s[2 * ii], imgs2[2 * kp][tid],
                         fmaf(We1s[2 * ii + 1], imgs2[2 * kp + 1][tid], b1s[ii]));
                As[u][tid] = fmaxf(v, 0.f);
            }
            __syncthreads();
            #pragma unroll
            for (int kk = 0; kk < 8; kk++) {
                int kc = k0 + kk;
                float4 a0 = *(const float4*)&As[kk][ty * 4];
                float4 a1 = *(const float4*)&As[kk][128 + ty * 4];
                float4 b0 = *(const float4*)&W2ts[kc][tx * 4];
                float4 b1v = *(const float4*)&W2ts[kc][32 + tx * 4];
                float a[8] = {a0.x, a0.y, a0.z, a0.w, a1.x, a1.y, a1.z, a1.w};
                unsigned long long bp[4] = {pk2(b0.x, b0.y), pk2(b0.z, b0.w),
                                            pk2(b1v.x, b1v.y), pk2(b1v.z, b1v.w)};
                #pragma unroll
                for (int i = 0; i < 8; i++) {
                    unsigned long long ap = pk2(a[i], a[i]);
                    #pragma unroll
                    for (int j = 0; j < 4; j++) fma2(acc2[i][j], ap, bp[j]);
                }
            }
            __syncthreads();
        }

        float mrow = 0.f;
        #pragma unroll
        for (int i = 0; i < 8; i++) {
            int rloc = (i < 4) ? (ty * 4 + i) : (128 + ty * 4 + (i - 4));
            int tok = blk * 256 + rloc;
            float ssq = 0.f;
            #pragma unroll
            for (int jj = 0; jj < 2; jj++) {
                int c0 = (jj == 0) ? (tx * 4) : (32 + tx * 4);
                float2 p0 = upk2(acc2[i][jj * 2 + 0]);
                float2 p1 = upk2(acc2[i][jj * 2 + 1]);
                float4 v;
                v.x = fmaxf(p0.x + b2s[c0 + 0], 0.f);
                v.y = fmaxf(p0.y + b2s[c0 + 1], 0.f);
                v.z = fmaxf(p1.x + b2s[c0 + 2], 0.f);
                v.w = fmaxf(p1.y + b2s[c0 + 3], 0.f);
                ssq = fmaf(v.x, v.x, ssq); ssq = fmaf(v.y, v.y, ssq);
                ssq = fmaf(v.z, v.z, ssq); ssq = fmaf(v.w, v.w, ssq);
                *(float4*)(g_H2 + (size_t)tok * 64 + c0) = v;
            }
            ssq += __shfl_xor_sync(0xffffffffu, ssq, 1);
            ssq += __shfl_xor_sync(0xffffffffu, ssq, 2);
            ssq += __shfl_xor_sync(0xffffffffu, ssq, 4);
            mrow = fmaxf(mrow, ssq);
        }
        mrow = fmaxf(mrow, __shfl_xor_sync(0xffffffffu, mrow, 8));
        mrow = fmaxf(mrow, __shfl_xor_sync(0xffffffffu, mrow, 16));
        if ((tid & 31) == 0) smax[tid >> 5] = mrow;
        __syncthreads();
        if (tid == 0) {
            float mm = smax[0];
            #pragma unroll
            for (int i = 1; i < 8; i++) mm = fmaxf(mm, smax[i]);
            atomicMax(&g_h2maxsq, __float_as_uint(mm));
        }
    } else if (b < 440) {
        // ---------------- combined weight GEMM + chnorm ----------------
        float (*As)[132] = (float(*)[132])(sbuf);          // 4224B
        float (*Bs)[132] = (float(*)[132])(sbuf + 4224);   // 4224B
        const int v = b - 408;
        const int bn = v >> 4, bm = v & 15;
        const int tx = tid & 15, ty = tid >> 4;
        const int N = 192, K = 512;

        unsigned long long acc2[8][4];
        #pragma unroll
        for (int i = 0; i < 8; i++)
            #pragma unroll
            for (int j = 0; j < 4; j++) acc2[i][j] = 0ULL;

        const int lr = tid >> 1;
        const int lc = (tid & 1) * 4;
        const float* Ap = cb + (size_t)(bm * 128 + lr) * K + lc;
        const float* Bp = g_Wcat + (size_t)(bn * 128 + lr) * K + lc;
        const bool bvalid = (bn * 128 + lr) < N;

        for (int k0 = 0; k0 < K; k0 += 8) {
            float4 av = *(const float4*)(Ap + k0);
            float4 bv = bvalid ? *(const float4*)(Bp + k0) : make_float4(0.f, 0.f, 0.f, 0.f);
            As[lc + 0][lr] = av.x; As[lc + 1][lr] = av.y; As[lc + 2][lr] = av.z; As[lc + 3][lr] = av.w;
            Bs[lc + 0][lr] = bv.x; Bs[lc + 1][lr] = bv.y; Bs[lc + 2][lr] = bv.z; Bs[lc + 3][lr] = bv.w;
            __syncthreads();
            #pragma unroll
            for (int kk = 0; kk < 8; kk++) {
                float4 a0 = *(const float4*)&As[kk][ty * 4];
                float4 a1 = *(const float4*)&As[kk][64 + ty * 4];
                float4 b0 = *(const float4*)&Bs[kk][tx * 4];
                float4 b1 = *(const float4*)&Bs[kk][64 + tx * 4];
                float a[8] = {a0.x, a0.y, a0.z, a0.w, a1.x, a1.y, a1.z, a1.w};
                unsigned long long bp[4] = {pk2(b0.x, b0.y), pk2(b0.z, b0.w),
                                            pk2(b1.x, b1.y), pk2(b1.z, b1.w)};
                #pragma unroll
                for (int i = 0; i < 8; i++) {
                    unsigned long long ap = pk2(a[i], a[i]);
                    #pragma unroll
                    for (int j = 0; j < 4; j++) fma2(acc2[i][j], ap, bp[j]);
                }
            }
            __syncthreads();
        }

        #pragma unroll
        for (int i = 0; i < 8; i++) {
            int rloc = (i < 4) ? (ty * 4 + i) : (64 + ty * 4 + i - 4);
            int r = bm * 128 + rloc;
            float ssq = 0.f;
            #pragma unroll
            for (int jj = 0; jj < 2; jj++) {
                int c0 = (jj == 0) ? (tx * 4) : (64 + tx * 4);
                int cg = bn * 128 + c0;
                if (cg < N) {
                    float2 p0 = upk2(acc2[i][jj * 2 + 0]);
                    float2 p1 = upk2(acc2[i][jj * 2 + 1]);
                    float4 vv = make_float4(p0.x, p0.y, p1.x, p1.y);
                    if (cg < 64) {
                        *(float4*)(g_Chat + (size_t)r * 64 + cg) = vv;
                        ssq = fmaf(vv.x, vv.x, ssq); ssq = fmaf(vv.y, vv.y, ssq);
                        ssq = fmaf(vv.z, vv.z, ssq); ssq = fmaf(vv.w, vv.w, ssq);
                    } else {
                        float* P = (r < NTOK) ? g_P0 : g_P1;
                        *(float4*)(P + (size_t)(r & (NTOK - 1)) * 128 + (cg - 64)) = vv;
                    }
                }
            }
            if (bn == 0) {   // chnorm: reduce ssq over tx (half-warp) and store
                ssq += __shfl_xor_sync(0xffffffffu, ssq, 1);
                ssq += __shfl_xor_sync(0xffffffffu, ssq, 2);
                ssq += __shfl_xor_sync(0xffffffffu, ssq, 4);
                ssq += __shfl_xor_sync(0xffffffffu, ssq, 8);
                if (tx == 0) g_chn[r] = sqrtf(ssq) * 1.0001f + 1e-20f;
            }
        }
    } else if (b < 457) {
        // ---------------- M3 = W^T W, w3b, bb (raw W_e3 reads) ----------------
        int v2 = b - 440;
        if (v2 < 16) {
            int idx = v2 * 256 + tid;
            int i = idx >> 6, j = idx & 63;
            float sacc = 0.f;
            for (int d = 0; d < 512; d++)
                sacc = fmaf(W_e3[d * 64 + i], W_e3[d * 64 + j], sacc);
            g_M3[idx] = sacc;
        } else {
            if (tid < 64) {
                float sacc = 0.f;
                for (int d = 0; d < 512; d++)
                    sacc = fmaf(W_e3[d * 64 + tid], be3[d], sacc);
                g_w3b[tid] = sacc;
            } else if (tid == 64) {
                float sacc = 0.f;
                for (int d = 0; d < 512; d++) { float x = be3[d]; sacc = fmaf(x, x, sacc); }
                g_bb = sacc;
            }
        }
    } else {
        // ---------------- per-code stats ----------------
        int row = (b - 457) * 8 + (tid >> 5);
        int lane = tid & 31;
        const float* r = cb + (size_t)row * CBD;
        float s = 0.f, t = 0.f;
        for (int d = lane; d < CBD; d += 32) {
            float v = r[d];
            s = fmaf(v, v, s);
            t = fmaf(v, be3[d], t);
        }
        #pragma unroll
        for (int o = 16; o; o >>= 1) {
            s += __shfl_xor_sync(0xffffffffu, s, o);
            t += __shfl_xor_sync(0xffffffffu, t, o);
        }
        if (!lane) { g_cn2[row] = s; g_bcv[row] = t; g_gam[row] = s - 2.f * t; }
    }
}

// ---------------- stage-0 candidate set -------------------------------------------
__global__ void k_cand0() {
    __shared__ float red[256];
    int tid = threadIdx.x;
    float H = sqrtf(__uint_as_float(g_h2maxsq)) * 1.0001f;
    float mn = 3.4e38f;
    for (int n = tid; n < NTOK; n += 256)
        mn = fminf(mn, g_gam[n] + 2.f * H * g_chn[n]);
    red[tid] = mn; __syncthreads();
    for (int o = 128; o; o >>= 1) {
        if (tid < o) red[tid] = fminf(red[tid], red[tid + o]);
        __syncthreads();
    }
    if (tid == 0) {
        float thresh = red[0] + 0.05f;
        int cnt = 0;
        for (int n = 0; n < NTOK; n++) {
            if (g_gam[n] - 2.f * H * g_chn[n] <= thresh) {
                g_cand0[cnt] = n; g_slotOf[n] = cnt; cnt++;
            }
        }
        g_n0 = cnt;
    }
}

// ---------------- stage-1 phase A: bases + per-slot min UB (parallel) -------------
__global__ void __launch_bounds__(256) k_s1a(const float* __restrict__ cb) {
    int s = blockIdx.y;
    if (s >= g_n0) return;
    __shared__ float c0row[512];
    __shared__ float red[128];
    const int tid = threadIdx.x;
    int v = g_cand0[s];
    if (tid < 128) ((float4*)c0row)[tid] = ((const float4*)(cb + (size_t)v * CBD))[tid];
    __syncthreads();
    float H = sqrtf(__uint_as_float(g_h2maxsq)) * 1.0001f;
    int n = blockIdx.x * 128 + (tid >> 1);
    int half = tid & 1;                         // each pair of threads splits the dot
    const float4* r1 = (const float4*)(cb + ((size_t)NTOK + n) * CBD) + half * 64;
    const float4* c0 = (const float4*)c0row + half * 64;
    float d = 0.f;
    #pragma unroll 8
    for (int k = 0; k < 64; k++) {
        float4 a = c0[k], bq = r1[k];
        d = fmaf(a.x, bq.x, d); d = fmaf(a.y, bq.y, d);
        d = fmaf(a.z, bq.z, d); d = fmaf(a.w, bq.w, d);
    }
    d += __shfl_xor_sync(0xffffffffu, d, 1);
    float mn = 3.4e38f;
    if (half == 0) {
        float base = fmaf(2.f, d, g_gam[NTOK + n]);
        g_c1full[(size_t)s * NTOK + n] = base;
        mn = base + 2.f * H * g_chn[NTOK + n];
    }
    // reduce min over even threads
    mn = fminf(mn, __shfl_xor_sync(0xffffffffu, mn, 2));
    mn = fminf(mn, __shfl_xor_sync(0xffffffffu, mn, 4));
    mn = fminf(mn, __shfl_xor_sync(0xffffffffu, mn, 8));
    mn = fminf(mn, __shfl_xor_sync(0xffffffffu, mn, 16));
    if ((tid & 31) == 0) red[tid >> 5] = mn;
    __syncthreads();
    if (tid == 0) {
        float m = red[0];
        #pragma unroll
        for (int i = 1; i < 8; i++) m = fminf(m, red[i]);
        atomicMin(&g_minU[s], fenc(m));
    }
}

// ---------------- stage-1 phase B: ordered compaction ------------------------------
__global__ void __launch_bounds__(256) k_s1b() {
    int s = blockIdx.x;
    if (s >= g_n0) return;
    __shared__ int cnt[256];
    const int tid = threadIdx.x;
    float H = sqrtf(__uint_as_float(g_h2maxsq)) * 1.0001f;
    float thresh = fdec(g_minU[s]) + 0.05f;
    float base[4]; int flag[4];
    int mycnt = 0;
    #pragma unroll
    for (int q = 0; q < 4; q++) {
        int n = tid * 4 + q;
        base[q] = g_c1full[(size_t)s * NTOK + n];
        flag[q] = (base[q] - 2.f * H * g_chn[NTOK + n] <= thresh) ? 1 : 0;
        mycnt += flag[q];
    }
    cnt[tid] = mycnt; __syncthreads();
    for (int off = 1; off < 256; off <<= 1) {
        int vv = (tid >= off) ? cnt[tid - off] : 0;
        __syncthreads();
        cnt[tid] += vv;
        __syncthreads();
    }
    int pos = cnt[tid] - mycnt;
    #pragma unroll
    for (int q = 0; q < 4; q++) {
        if (flag[q]) {
            g_c1idx [(size_t)s * NTOK + pos] = tid * 4 + q;
            g_c1base[(size_t)s * NTOK + pos] = base[q];
            pos++;
        }
    }
    if (tid == 255) g_n1[s] = cnt[255];
}

// =================== MEGA 3: vq | ptab ============================================
__global__ void __launch_bounds__(256) k_mega3(const float* __restrict__ W3,
                                               const float* __restrict__ b3,
                                               float* __restrict__ dout) {
    __shared__ __align__(16) char sbuf[35584];
    const int tid = threadIdx.x;
    const int b = blockIdx.x;

    if (b < 1632) {
        // ---------------- per-token argmin + loss terms ----------------
        double (*sm)[5] = (double(*)[5])(sbuf);
        int w = tid >> 5, lane = tid & 31;
        int n0 = g_n0;
        double a_q0x = 0, a_q1x = 0, a_c0 = 0, a_c1 = 0, a_G = 0;
        int wbase = (b * 8 + w) * 8;
        float* didx = dout + IDX_OFF;
        for (int r = 0; r < 8; r++) {
            int t = wbase + r;
            float2 h = ((const float2*)(g_H2 + (size_t)t * 64))[lane];
            float bs = 3.4e38f, bd0 = 0.f; int bi = 0;
            for (int j = 0; j < n0; j++) {
                int c = g_cand0[j];
                float2 cv = ((const float2*)(g_Chat + (size_t)c * 64))[lane];
                float p = fmaf(h.x, cv.x, h.y * cv.y);
                #pragma unroll
                for (int o = 16; o; o >>= 1) p += __shfl_xor_sync(0xffffffffu, p, o);
                float s = fmaf(-2.f, p, g_gam[c]);
                if (s < bs) { bs = s; bi = c; bd0 = p; }
            }
            int i0 = bi;
            int slot = g_slotOf[i0];
            int n1 = g_n1[slot];
            const int*   c1i = g_c1idx  + (size_t)slot * NTOK;
            const float* c1b = g_c1base + (size_t)slot * NTOK;
            bs = 3.4e38f; bi = 0; float bd1 = 0.f, bb1 = 0.f; int bj = 0;
            for (int j = 0; j < n1; j++) {
                int c = c1i[j]; float base = c1b[j];
                float2 cv = ((const float2*)(g_Chat + (size_t)(NTOK + c) * 64))[lane];
                float p = fmaf(h.x, cv.x, h.y * cv.y);
                #pragma unroll
                for (int o = 16; o; o >>= 1) p += __shfl_xor_sync(0xffffffffu, p, o);
                float s = fmaf(-2.f, p, base);
                if (s < bs) { bs = s; bi = c; bd1 = p; bb1 = base; bj = j; }
            }
            int i1 = bi;
            if (lane == 0) {
                g_i0[t] = i0; g_i1[t] = i1;
                g_pid[t] = slot * NTOK + bj;
                didx[2 * t] = (float)i0; didx[2 * t + 1] = (float)i1;
                a_q0x += (double)bd0 + (double)g_bcv[i0];
                a_q1x += (double)bd1 + (double)g_bcv[NTOK + i1];
                a_c0  += (double)g_cn2[i0];
                a_c1  += (double)g_cn2[NTOK + i1];
                a_G   += 0.5 * ((double)bb1 - (double)g_gam[NTOK + i1]);
            }
        }
        if (lane == 0) {
            sm[w][0] = a_q0x; sm[w][1] = a_q1x; sm[w][2] = a_c0; sm[w][3] = a_c1; sm[w][4] = a_G;
        }
        __syncthreads();
        if (tid == 0) {
            double v0 = 0, v1 = 0, v2 = 0, v3 = 0, v4 = 0;
            #pragma unroll
            for (int i = 0; i < 8; i++) {
                v0 += sm[i][0]; v1 += sm[i][1]; v2 += sm[i][2]; v3 += sm[i][3]; v4 += sm[i][4];
            }
            atomicAdd(&g_acc[0], v0); atomicAdd(&g_acc[1], v1);
            atomicAdd(&g_acc[3], v2); atomicAdd(&g_acc[4], v3);
            atomicAdd(&g_acc[5], v4);
        }
    } else {
        // ---------------- pair table ----------------
        int vv = b - 1632;
        int s = vv >> 4, jstart = vv & 15;
        if (s >= g_n0) return;
        float (*Wts)[128] = (float(*)[128])(sbuf);              // 32768B
        float (*d1s)[64]  = (float(*)[64])(sbuf + 32768);       // 512B
        float* bd1s = (float*)(sbuf + 33280);
        float* bd2s = (float*)(sbuf + 33792);
        float* w3s  = (float*)(sbuf + 34304);
        float* sred = (float*)(sbuf + 34560);
        for (int e = tid; e < 8192; e += 256) {
            int n = e >> 6, c = e & 63;
            Wts[c][n] = g_Wd2m[e];
        }
        if (tid < 128) { bd1s[tid] = g_bd1x[tid]; bd2s[tid] = g_bd2x[tid]; }
        if (tid < 64) w3s[tid] = W3[tid];
        const float b3v = b3[0];
        const int n1 = g_n1[s];
        const int i0 = g_cand0[s];
        const float* P0r = g_P0 + (size_t)i0 * 128;
        __syncthreads();

        const int p = tid >> 7, n = tid & 127;
        for (int j = jstart; j < n1; j += 16) {
            int i1 = g_c1idx[(size_t)s * NTOK + j];
            if (tid < 128)
                d1s[tid >> 6][tid & 63] =
                    fmaxf(P0r[tid] + g_P1[(size_t)i1 * 128 + tid] + bd1s[tid], 0.f);
            __syncthreads();
            float v = bd2s[n];
            #pragma unroll 16
            for (int c = 0; c < 64; c++) v = fmaf(d1s[p][c], Wts[c][n], v);
            v = fmaxf(v, 0.f) * w3s[n & 63];
            sred[tid] = v;
            __syncthreads();
            if ((tid & 63) < 32) {
                float x = sred[tid] + sred[tid + 32];
                #pragma unroll
                for (int o = 16; o; o >>= 1) x += __shfl_down_sync(0xffffffffu, x, o);
                if ((tid & 63) == 0)
                    g_ptab[((size_t)s * NTOK + j) * 4 + (tid >> 6)] = x + b3v;
            }
            __syncthreads();
        }
    }
}

// =================== MEGA 2: qout | out | Spart ===================================
__global__ void __launch_bounds__(256) k_mega2(const float* __restrict__ cb,
                                               const float* __restrict__ img,
                                               float* __restrict__ dout) {
    __shared__ __align__(16) char sbuf[27744];
    const int tid = threadIdx.x;
    const int b = blockIdx.x;

    if (b < 8192) {
        // ---------------- quantized output, tiled transpose ----------------
        float* sq = (float*)sbuf;                 // 408*17 floats
        const int d0 = (b & 31) * 16;
        const int bb = b >> 5;
        for (int tt = tid; tt < T2; tt += 256) {
            int tok = bb * T2 + tt;
            const float4* r0 = (const float4*)(cb + (size_t)g_i0[tok] * CBD + d0);
            const float4* r1 = (const float4*)(cb + ((size_t)NTOK + g_i1[tok]) * CBD + d0);
            #pragma unroll
            for (int q = 0; q < 4; q++) {
                float4 a = r0[q], c = r1[q];
                sq[tt * 17 + q * 4 + 0] = a.x + c.x;
                sq[tt * 17 + q * 4 + 1] = a.y + c.y;
                sq[tt * 17 + q * 4 + 2] = a.z + c.z;
                sq[tt * 17 + q * 4 + 3] = a.w + c.w;
            }
        }
        __syncthreads();
        const int w = tid >> 5, lane = tid & 31;
        #pragma unroll
        for (int it = 0; it < 2; it++) {
            int d = it * 8 + w;
            size_t base = QOFF + ((size_t)bb * CBD + d0 + d) * T2;
            #pragma unroll
            for (int j = 0; j < 13; j++) {
                int t = j * 32 + lane;
                if (t < T2) dout[base + t] = sq[t * 17 + d];
            }
        }
    } else if (b < 8600) {
        // ---------------- decoder output gather + recon loss ----------------
        double* sd = (double*)sbuf;
        int tok = (b - 8192) * 256 + tid;
        int pid = g_pid[tok];
        float4 v = ((const float4*)g_ptab)[pid];
        int bb = tok / T2, t2 = tok - bb * T2;
        size_t o = (size_t)bb * TT + 4 * t2;
        *(float4*)(dout + o) = v;
        float4 iv = *(const float4*)(img + o);
        float e0 = iv.x - v.x, e1 = iv.y - v.y, e2 = iv.z - v.z, e3 = iv.w - v.w;
        sd[tid] = (double)e0 * e0 + (double)e1 * e1 + (double)e2 * e2 + (double)e3 * e3;
        __syncthreads();
        for (int o2 = 128; o2; o2 >>= 1) {
            if (tid < o2) sd[tid] += sd[tid + o2];
            __syncthreads();
        }
        if (!tid) atomicAdd(&g_acc[2], sd[0]);
    } else {
        // ---------------- partial S = H2^T H2 (atomic accumulate) ----------------
        float* sh2 = (float*)sbuf;                // 8*64 floats
        int blk = b - 8600;
        int t0 = blk * 816;
        float acc[16];
        #pragma unroll
        for (int i = 0; i < 16; i++) acc[i] = 0.f;
        float hs = 0.f;
        int ti = tid >> 4, tj = tid & 15;
        for (int g = 0; g < 102; g++) {
            int base = t0 + g * 8;
            if (tid < 128)
                ((float4*)sh2)[tid] = ((const float4*)(g_H2 + (size_t)base * 64))[tid];
            __syncthreads();
            #pragma unroll
            for (int r = 0; r < 8; r++) {
                float4 a = *(const float4*)&sh2[r * 64 + ti * 4];
                float4 bq = *(const float4*)&sh2[r * 64 + tj * 4];
                float av[4] = {a.x, a.y, a.z, a.w}, bv[4] = {bq.x, bq.y, bq.z, bq.w};
                #pragma unroll
                for (int p = 0; p < 4; p++)
                    #pragma unroll
                    for (int q = 0; q < 4; q++) acc[p * 4 + q] = fmaf(av[p], bv[q], acc[p * 4 + q]);
            }
            if (tid < 64) {
                #pragma unroll
                for (int r = 0; r < 8; r++) hs += sh2[r * 64 + tid];
            }
            __syncthreads();
        }
        #pragma unroll
        for (int p = 0; p < 4; p++)
            #pragma unroll
            for (int q = 0; q < 4; q++)
                atomicAdd(&g_S[(ti * 4 + p) * 64 + (tj * 4 + q)], acc[p * 4 + q]);
        if (tid < 64) atomicAdd(&g_hsum[tid], hs);
    }
}

// ---------------- fin: Sfinal + scalars -------------------------------------------
__global__ void k_fin(float* __restrict__ dout) {
    __shared__ double red[256];
    int tid = threadIdx.x;
    double partial = 0.0;
    for (int c = tid; c < 4096; c += 256)
        partial += (double)g_S[c] * (double)g_M3[c];
    if (tid < 64) partial += 2.0 * (double)g_hsum[tid] * (double)g_w3b[tid];
    if (tid == 64) partial += (double)NTOKEN * (double)g_bb;
    red[tid] = partial; __syncthreads();
    for (int o = 128; o; o >>= 1) {
        if (tid < o) red[tid] += red[tid + o];
        __syncthreads();
    }
    if (tid == 0) {
        double xsq = red[0];
        double denom = (double)NTOKEN * CBD;
        double q0x = g_acc[0], q1x = g_acc[1], c0 = g_acc[3], c1 = g_acc[4];
        double G = g_acc[5];
        dout[OUT_N + 0] = (float)(g_acc[2] / (double)OUT_N);
        dout[OUT_N + 1] = (float)((c0 - 2.0 * q0x + xsq) / denom);
        dout[OUT_N + 2] = (float)((c0 + c1 + xsq + 2.0 * G - 2.0 * q0x - 2.0 * q1x) / denom);
    }
}

// ---------------- launch -----------------------------------------------------------
extern "C" void kernel_launch(void* const* d_in, const int* in_sizes, int n_in,
                              void* d_out, int out_size) {
    const float* img   = (const float*)d_in[0];
    const float* W_e1  = (const float*)d_in[1];
    const float* b_e1  = (const float*)d_in[2];
    const float* W_e2  = (const float*)d_in[3];
    const float* b_e2  = (const float*)d_in[4];
    const float* W_e3  = (const float*)d_in[5];
    const float* b_e3  = (const float*)d_in[6];
    const float* cb    = (const float*)d_in[7];
    const float* Wt_d1 = (const float*)d_in[8];
    const float* b_d1  = (const float*)d_in[9];
    const float* Wt_d2 = (const float*)d_in[10];
    const float* b_d2  = (const float*)d_in[11];
    const float* W_d3  = (const float*)d_in[12];
    const float* b_d3  = (const float*)d_in[13];
    float* out = (float*)d_out;

    k_prep <<<258, 256>>>(W_e2, W_e3, Wt_d1, Wt_d2, b_d1, b_d2);
    k_mega1<<<713, 256>>>(img, W_e1, b_e1, b_e2, cb, W_e3, b_e3);
    k_cand0<<<1, 256>>>();
    k_s1a  <<<dim3(8, NTOK), 256>>>(cb);
    k_s1b  <<<NTOK, 256>>>();
    k_mega3<<<1632 + 1024, 256>>>(W_d3, b_d3, out);
    k_mega2<<<8192 + 408 + 128, 256>>>(cb, img, out);
    k_fin  <<<1, 256>>>(out);
}

// round 13
// speedup vs baseline: 13.7837x; 1.0098x over previous
#include <cuda_runtime.h>

#define BI   256
#define TT   1632
#define T1   816
#define T2   408
#define HIDD 64
#define CBD  512
#define NTOK 1024
#define NTOKEN (BI*T2)   /* 104448 */
#define M1     (BI*T1)   /* 208896 */

#define OUT_N   (BI*TT)                 /* 417792 */
#define IDX_OFF (OUT_N + 3)             /* 417795 */
#define QOFF    (IDX_OFF + NTOKEN*2)    /* 626691 */

// ---------------- scratch ---------------------------------------------------------
__device__ float g_H2[(size_t)NTOKEN * HIDD];
__device__ float g_Wcat[192 * 512];              // rows 0..63 = W_e3^T, 64..191 = Wd1m
__device__ float g_Chat[2 * NTOK * 64];
__device__ float g_chn [2 * NTOK];
__device__ float g_gam [2 * NTOK];
__device__ float g_cn2 [2 * NTOK];
__device__ float g_bcv [2 * NTOK];
__device__ int   g_cand0[NTOK];
__device__ int   g_n0;
__device__ int   g_slotOf[NTOK];
__device__ float g_c1full[(size_t)NTOK * NTOK];  // all stage-1 bases per slot
__device__ unsigned g_minU[NTOK];                // per-slot min upper bound (ordered uint)
__device__ int   g_c1idx [(size_t)NTOK * NTOK];
__device__ float g_c1base[(size_t)NTOK * NTOK];
__device__ int   g_n1[NTOK];
__device__ int   g_i0[NTOKEN], g_i1[NTOKEN], g_pid[NTOKEN];
__device__ unsigned g_h2maxsq;
__device__ float g_P0[NTOK * 128], g_P1[NTOK * 128];
__device__ float g_ptab[(size_t)NTOK * NTOK * 4];
__device__ float g_S[4096];                      // H2^T H2 (atomic accum)
__device__ float g_hsum[64];                     // sum h2 (atomic accum)
__device__ float g_M3[4096], g_w3b[64], g_bb;
__device__ float g_W2m [64 * 128];
__device__ float g_Wd2m[128 * 64];
__device__ float g_bd1x[128];
__device__ float g_bd2x[128];
__device__ double g_acc[8];

// ---------------- f32x2 packed helpers --------------------------------------------
__device__ __forceinline__ unsigned long long pk2(float lo, float hi) {
    unsigned long long r;
    asm("mov.b64 %0, {%1,%2};" : "=l"(r) : "f"(lo), "f"(hi));
    return r;
}
__device__ __forceinline__ float2 upk2(unsigned long long v) {
    float2 r;
    asm("mov.b64 {%0,%1}, %2;" : "=f"(r.x), "=f"(r.y) : "l"(v));
    return r;
}
__device__ __forceinline__ void fma2(unsigned long long& d,
                                     unsigned long long a, unsigned long long b) {
    asm("fma.rn.f32x2 %0, %1, %2, %0;" : "+l"(d) : "l"(a), "l"(b));
}
__device__ __forceinline__ unsigned fenc(float f) {
    unsigned u = __float_as_uint(f);
    return (u & 0x80000000u) ? ~u : (u | 0x80000000u);
}
__device__ __forceinline__ float fdec(unsigned u) {
    return __uint_as_float((u & 0x80000000u) ? (u ^ 0x80000000u) : ~u);
}

// ---------------- prep: init + repack ---------------------------------------------
__global__ void k_prep(const float* __restrict__ W_e2,
                       const float* __restrict__ W_e3,
                       const float* __restrict__ Wt_d1,
                       const float* __restrict__ Wt_d2,
                       const float* __restrict__ b_d1,
                       const float* __restrict__ b_d2) {
    int blk = blockIdx.x, tid = threadIdx.x;
    if (blk < 256) {
        int i = blk * 256 + tid;
        if (i < 64 * 128) {
            int o = i >> 7, c = i & 127, k = c >> 6, ii = c & 63;
            g_W2m[i] = W_e2[(o * 64 + ii) * 2 + k];
        }
        if (i < 64 * 512) {
            int r = i >> 9, d = i & 511;
            g_Wcat[i] = W_e3[d * 64 + r];
        }
        if (i < 128 * 512) {
            int n = i >> 9, d = i & 511;
            int k = n >> 6, o = n & 63;
            g_Wcat[64 * 512 + i] = Wt_d1[(d * 64 + o) * 2 + k];
        }
        if (i < 128 * 64) {
            int n = i >> 6, d = i & 63;
            int k = n >> 6, o = n & 63;
            g_Wd2m[i] = Wt_d2[(d * 64 + o) * 2 + k];
        }
        if (i < 128) { g_bd1x[i] = b_d1[i & 63]; g_bd2x[i] = b_d2[i & 63]; }
    } else if (blk == 256) {
        if (tid < 8) g_acc[tid] = 0.0;
        if (tid == 8) g_h2maxsq = 0u;
        #pragma unroll
        for (int q = 0; q < 4; q++) g_minU[q * 256 + tid] = 0xFFFFFFFFu;
        if (tid < 64) g_hsum[tid] = 0.f;
    } else {
        #pragma unroll
        for (int q = 0; q < 16; q++) g_S[q * 256 + tid] = 0.f;
    }
}

// =================== MEGA 1: enc | wgemm(+chnorm) | m3 | stats =====================
__global__ void __launch_bounds__(256) k_mega1(
    const float* __restrict__ img, const float* __restrict__ W_e1,
    const float* __restrict__ b_e1, const float* __restrict__ b_e2,
    const float* __restrict__ cb, const float* __restrict__ W_e3,
    const float* __restrict__ be3)
{
    __shared__ __align__(16) char sbuf[48352];
    const int tid = threadIdx.x;
    const int b = blockIdx.x;

    if (b < 408) {
        // ---------------- fused encoder ----------------
        float (*W2ts)[68] = (float(*)[68])(sbuf);                 // 34816B
        float (*As)[260]  = (float(*)[260])(sbuf + 34816);        // 8320B
        float (*imgs2)[260] = (float(*)[260])(sbuf + 43136);      // 4160B
        float* We1s = (float*)(sbuf + 47296);
        float* b1s  = (float*)(sbuf + 47808);
        float* b2s  = (float*)(sbuf + 48064);
        float* smax = (float*)(sbuf + 48320);
        const int blk = b;

        for (int e = tid; e < 8192; e += 256) {
            int o = e >> 7, c = e & 127;
            W2ts[c][o] = g_W2m[e];
        }
        if (tid < 128) We1s[tid] = W_e1[tid];
        if (tid < 64) { b1s[tid] = b_e1[tid]; b2s[tid] = b_e2[tid]; }
        {
            float4 iv = ((const float4*)img)[blk * 256 + tid];
            imgs2[0][tid] = iv.x; imgs2[1][tid] = iv.y;
            imgs2[2][tid] = iv.z; imgs2[3][tid] = iv.w;
        }
        __syncthreads();

        const int tx = tid & 7, ty = tid >> 3;
        unsigned long long acc2[8][4];
        #pragma unroll
        for (int i = 0; i < 8; i++)
            #pragma unroll
            for (int j = 0; j < 4; j++) acc2[i][j] = 0ULL;

        for (int k0 = 0; k0 < 128; k0 += 8) {
            #pragma unroll
            for (int u = 0; u < 8; u++) {
                int c = k0 + u, kp = c >> 6, ii = c & 63;
                float v = fmaf(We1s[2 * ii], imgs2[2 * kp][tid],
                         fmaf(We1s[2 * ii + 1], imgs2[2 * kp + 1][tid], b1s[ii]));
                As[u][tid] = fmaxf(v, 0.f);
            }
            __syncthreads();
            #pragma unroll
            for (int kk = 0; kk < 8; kk++) {
                int kc = k0 + kk;
                float4 a0 = *(const float4*)&As[kk][ty * 4];
                float4 a1 = *(const float4*)&As[kk][128 + ty * 4];
                float4 b0 = *(const float4*)&W2ts[kc][tx * 4];
                float4 b1v = *(const float4*)&W2ts[kc][32 + tx * 4];
                float a[8] = {a0.x, a0.y, a0.z, a0.w, a1.x, a1.y, a1.z, a1.w};
                unsigned long long bp[4] = {pk2(b0.x, b0.y), pk2(b0.z, b0.w),
                                            pk2(b1v.x, b1v.y), pk2(b1v.z, b1v.w)};
                #pragma unroll
                for (int i = 0; i < 8; i++) {
                    unsigned long long ap = pk2(a[i], a[i]);
                    #pragma unroll
                    for (int j = 0; j < 4; j++) fma2(acc2[i][j], ap, bp[j]);
                }
            }
            __syncthreads();
        }

        float mrow = 0.f;
        #pragma unroll
        for (int i = 0; i < 8; i++) {
            int rloc = (i < 4) ? (ty * 4 + i) : (128 + ty * 4 + (i - 4));
            int tok = blk * 256 + rloc;
            float ssq = 0.f;
            #pragma unroll
            for (int jj = 0; jj < 2; jj++) {
                int c0 = (jj == 0) ? (tx * 4) : (32 + tx * 4);
                float2 p0 = upk2(acc2[i][jj * 2 + 0]);
                float2 p1 = upk2(acc2[i][jj * 2 + 1]);
                float4 v;
                v.x = fmaxf(p0.x + b2s[c0 + 0], 0.f);
                v.y = fmaxf(p0.y + b2s[c0 + 1], 0.f);
                v.z = fmaxf(p1.x + b2s[c0 + 2], 0.f);
                v.w = fmaxf(p1.y + b2s[c0 + 3], 0.f);
                ssq = fmaf(v.x, v.x, ssq); ssq = fmaf(v.y, v.y, ssq);
                ssq = fmaf(v.z, v.z, ssq); ssq = fmaf(v.w, v.w, ssq);
                *(float4*)(g_H2 + (size_t)tok * 64 + c0) = v;
            }
            ssq += __shfl_xor_sync(0xffffffffu, ssq, 1);
            ssq += __shfl_xor_sync(0xffffffffu, ssq, 2);
            ssq += __shfl_xor_sync(0xffffffffu, ssq, 4);
            mrow = fmaxf(mrow, ssq);
        }
        mrow = fmaxf(mrow, __shfl_xor_sync(0xffffffffu, mrow, 8));
        mrow = fmaxf(mrow, __shfl_xor_sync(0xffffffffu, mrow, 16));
        if ((tid & 31) == 0) smax[tid >> 5] = mrow;
        __syncthreads();
        if (tid == 0) {
            float mm = smax[0];
            #pragma unroll
            for (int i = 1; i < 8; i++) mm = fmaxf(mm, smax[i]);
            atomicMax(&g_h2maxsq, __float_as_uint(mm));
        }
    } else if (b < 440) {
        // ---------------- combined weight GEMM + chnorm ----------------
        float (*As)[132] = (float(*)[132])(sbuf);          // 4224B
        float (*Bs)[132] = (float(*)[132])(sbuf + 4224);   // 4224B
        const int v = b - 408;
        const int bn = v >> 4, bm = v & 15;
        const int tx = tid & 15, ty = tid >> 4;
        const int N = 192, K = 512;

        unsigned long long acc2[8][4];
        #pragma unroll
        for (int i = 0; i < 8; i++)
            #pragma unroll
            for (int j = 0; j < 4; j++) acc2[i][j] = 0ULL;

        const int lr = tid >> 1;
        const int lc = (tid & 1) * 4;
        const float* Ap = cb + (size_t)(bm * 128 + lr) * K + lc;
        const float* Bp = g_Wcat + (size_t)(bn * 128 + lr) * K + lc;
        const bool bvalid = (bn * 128 + lr) < N;

        for (int k0 = 0; k0 < K; k0 += 8) {
            float4 av = *(const float4*)(Ap + k0);
            float4 bv = bvalid ? *(const float4*)(Bp + k0) : make_float4(0.f, 0.f, 0.f, 0.f);
            As[lc + 0][lr] = av.x; As[lc + 1][lr] = av.y; As[lc + 2][lr] = av.z; As[lc + 3][lr] = av.w;
            Bs[lc + 0][lr] = bv.x; Bs[lc + 1][lr] = bv.y; Bs[lc + 2][lr] = bv.z; Bs[lc + 3][lr] = bv.w;
            __syncthreads();
            #pragma unroll
            for (int kk = 0; kk < 8; kk++) {
                float4 a0 = *(const float4*)&As[kk][ty * 4];
                float4 a1 = *(const float4*)&As[kk][64 + ty * 4];
                float4 b0 = *(const float4*)&Bs[kk][tx * 4];
                float4 b1 = *(const float4*)&Bs[kk][64 + tx * 4];
                float a[8] = {a0.x, a0.y, a0.z, a0.w, a1.x, a1.y, a1.z, a1.w};
                unsigned long long bp[4] = {pk2(b0.x, b0.y), pk2(b0.z, b0.w),
                                            pk2(b1.x, b1.y), pk2(b1.z, b1.w)};
                #pragma unroll
                for (int i = 0; i < 8; i++) {
                    unsigned long long ap = pk2(a[i], a[i]);
                    #pragma unroll
                    for (int j = 0; j < 4; j++) fma2(acc2[i][j], ap, bp[j]);
                }
            }
            __syncthreads();
        }

        #pragma unroll
        for (int i = 0; i < 8; i++) {
            int rloc = (i < 4) ? (ty * 4 + i) : (64 + ty * 4 + i - 4);
            int r = bm * 128 + rloc;
            float ssq = 0.f;
            #pragma unroll
            for (int jj = 0; jj < 2; jj++) {
                int c0 = (jj == 0) ? (tx * 4) : (64 + tx * 4);
                int cg = bn * 128 + c0;
                if (cg < N) {
                    float2 p0 = upk2(acc2[i][jj * 2 + 0]);
                    float2 p1 = upk2(acc2[i][jj * 2 + 1]);
                    float4 vv = make_float4(p0.x, p0.y, p1.x, p1.y);
                    if (cg < 64) {
                        *(float4*)(g_Chat + (size_t)r * 64 + cg) = vv;
                        ssq = fmaf(vv.x, vv.x, ssq); ssq = fmaf(vv.y, vv.y, ssq);
                        ssq = fmaf(vv.z, vv.z, ssq); ssq = fmaf(vv.w, vv.w, ssq);
                    } else {
                        float* P = (r < NTOK) ? g_P0 : g_P1;
                        *(float4*)(P + (size_t)(r & (NTOK - 1)) * 128 + (cg - 64)) = vv;
                    }
                }
            }
            if (bn == 0) {   // chnorm: reduce ssq over tx (half-warp) and store
                ssq += __shfl_xor_sync(0xffffffffu, ssq, 1);
                ssq += __shfl_xor_sync(0xffffffffu, ssq, 2);
                ssq += __shfl_xor_sync(0xffffffffu, ssq, 4);
                ssq += __shfl_xor_sync(0xffffffffu, ssq, 8);
                if (tx == 0) g_chn[r] = sqrtf(ssq) * 1.0001f + 1e-20f;
            }
        }
    } else if (b < 457) {
        // ---------------- M3 = W^T W, w3b, bb (raw W_e3 reads) ----------------
        int v2 = b - 440;
        if (v2 < 16) {
            int idx = v2 * 256 + tid;
            int i = idx >> 6, j = idx & 63;
            float sacc = 0.f;
            for (int d = 0; d < 512; d++)
                sacc = fmaf(W_e3[d * 64 + i], W_e3[d * 64 + j], sacc);
            g_M3[idx] = sacc;
        } else {
            if (tid < 64) {
                float sacc = 0.f;
                for (int d = 0; d < 512; d++)
                    sacc = fmaf(W_e3[d * 64 + tid], be3[d], sacc);
                g_w3b[tid] = sacc;
            } else if (tid == 64) {
                float sacc = 0.f;
                for (int d = 0; d < 512; d++) { float x = be3[d]; sacc = fmaf(x, x, sacc); }
                g_bb = sacc;
            }
        }
    } else {
        // ---------------- per-code stats ----------------
        int row = (b - 457) * 8 + (tid >> 5);
        int lane = tid & 31;
        const float* r = cb + (size_t)row * CBD;
        float s = 0.f, t = 0.f;
        for (int d = lane; d < CBD; d += 32) {
            float v = r[d];
            s = fmaf(v, v, s);
            t = fmaf(v, be3[d], t);
        }
        #pragma unroll
        for (int o = 16; o; o >>= 1) {
            s += __shfl_xor_sync(0xffffffffu, s, o);
            t += __shfl_xor_sync(0xffffffffu, t, o);
        }
        if (!lane) { g_cn2[row] = s; g_bcv[row] = t; g_gam[row] = s - 2.f * t; }
    }
}

// ---------------- stage-0 candidate set -------------------------------------------
__global__ void k_cand0() {
    __shared__ float red[256];
    int tid = threadIdx.x;
    float H = sqrtf(__uint_as_float(g_h2maxsq)) * 1.0001f;
    float mn = 3.4e38f;
    for (int n = tid; n < NTOK; n += 256)
        mn = fminf(mn, g_gam[n] + 2.f * H * g_chn[n]);
    red[tid] = mn; __syncthreads();
    for (int o = 128; o; o >>= 1) {
        if (tid < o) red[tid] = fminf(red[tid], red[tid + o]);
        __syncthreads();
    }
    if (tid == 0) {
        float thresh = red[0] + 0.05f;
        int cnt = 0;
        for (int n = 0; n < NTOK; n++) {
            if (g_gam[n] - 2.f * H * g_chn[n] <= thresh) {
                g_cand0[cnt] = n; g_slotOf[n] = cnt; cnt++;
            }
        }
        g_n0 = cnt;
    }
}

// ---------------- stage-1 phase A: bases + per-slot min UB (parallel) -------------
__global__ void __launch_bounds__(256) k_s1a(const float* __restrict__ cb) {
    int s = blockIdx.y;
    if (s >= g_n0) return;
    __shared__ float c0row[512];
    __shared__ float red[128];
    const int tid = threadIdx.x;
    int v = g_cand0[s];
    if (tid < 128) ((float4*)c0row)[tid] = ((const float4*)(cb + (size_t)v * CBD))[tid];
    __syncthreads();
    float H = sqrtf(__uint_as_float(g_h2maxsq)) * 1.0001f;
    int n = blockIdx.x * 128 + (tid >> 1);
    int half = tid & 1;                         // each pair of threads splits the dot
    const float4* r1 = (const float4*)(cb + ((size_t)NTOK + n) * CBD) + half * 64;
    const float4* c0 = (const float4*)c0row + half * 64;
    float d = 0.f;
    #pragma unroll 8
    for (int k = 0; k < 64; k++) {
        float4 a = c0[k], bq = r1[k];
        d = fmaf(a.x, bq.x, d); d = fmaf(a.y, bq.y, d);
        d = fmaf(a.z, bq.z, d); d = fmaf(a.w, bq.w, d);
    }
    d += __shfl_xor_sync(0xffffffffu, d, 1);
    float mn = 3.4e38f;
    if (half == 0) {
        float base = fmaf(2.f, d, g_gam[NTOK + n]);
        g_c1full[(size_t)s * NTOK + n] = base;
        mn = base + 2.f * H * g_chn[NTOK + n];
    }
    // reduce min over even threads
    mn = fminf(mn, __shfl_xor_sync(0xffffffffu, mn, 2));
    mn = fminf(mn, __shfl_xor_sync(0xffffffffu, mn, 4));
    mn = fminf(mn, __shfl_xor_sync(0xffffffffu, mn, 8));
    mn = fminf(mn, __shfl_xor_sync(0xffffffffu, mn, 16));
    if ((tid & 31) == 0) red[tid >> 5] = mn;
    __syncthreads();
    if (tid == 0) {
        float m = red[0];
        #pragma unroll
        for (int i = 1; i < 8; i++) m = fminf(m, red[i]);
        atomicMin(&g_minU[s], fenc(m));
    }
}

// ---------------- stage-1 phase B: ordered compaction ------------------------------
__global__ void __launch_bounds__(256) k_s1b() {
    int s = blockIdx.x;
    if (s >= g_n0) return;
    __shared__ int cnt[256];
    const int tid = threadIdx.x;
    float H = sqrtf(__uint_as_float(g_h2maxsq)) * 1.0001f;
    float thresh = fdec(g_minU[s]) + 0.05f;
    float base[4]; int flag[4];
    int mycnt = 0;
    #pragma unroll
    for (int q = 0; q < 4; q++) {
        int n = tid * 4 + q;
        base[q] = g_c1full[(size_t)s * NTOK + n];
        flag[q] = (base[q] - 2.f * H * g_chn[NTOK + n] <= thresh) ? 1 : 0;
        mycnt += flag[q];
    }
    cnt[tid] = mycnt; __syncthreads();
    for (int off = 1; off < 256; off <<= 1) {
        int vv = (tid >= off) ? cnt[tid - off] : 0;
        __syncthreads();
        cnt[tid] += vv;
        __syncthreads();
    }
    int pos = cnt[tid] - mycnt;
    #pragma unroll
    for (int q = 0; q < 4; q++) {
        if (flag[q]) {
            g_c1idx [(size_t)s * NTOK + pos] = tid * 4 + q;
            g_c1base[(size_t)s * NTOK + pos] = base[q];
            pos++;
        }
    }
    if (tid == 255) g_n1[s] = cnt[255];
}

// =================== MEGA 3: vq | ptab ============================================
__global__ void __launch_bounds__(256) k_mega3(const float* __restrict__ W3,
                                               const float* __restrict__ b3,
                                               float* __restrict__ dout) {
    __shared__ __align__(16) char sbuf[35584];
    const int tid = threadIdx.x;
    const int b = blockIdx.x;

    if (b < 1632) {
        // ---------------- per-token argmin + loss terms ----------------
        double (*sm)[5] = (double(*)[5])(sbuf);
        int w = tid >> 5, lane = tid & 31;
        int n0 = g_n0;
        double a_q0x = 0, a_q1x = 0, a_c0 = 0, a_c1 = 0, a_G = 0;
        int wbase = (b * 8 + w) * 8;
        float* didx = dout + IDX_OFF;
        for (int r = 0; r < 8; r++) {
            int t = wbase + r;
            float2 h = ((const float2*)(g_H2 + (size_t)t * 64))[lane];
            float bs = 3.4e38f, bd0 = 0.f; int bi = 0;
            for (int j = 0; j < n0; j++) {
                int c = g_cand0[j];
                float2 cv = ((const float2*)(g_Chat + (size_t)c * 64))[lane];
                float p = fmaf(h.x, cv.x, h.y * cv.y);
                #pragma unroll
                for (int o = 16; o; o >>= 1) p += __shfl_xor_sync(0xffffffffu, p, o);
                float s = fmaf(-2.f, p, g_gam[c]);
                if (s < bs) { bs = s; bi = c; bd0 = p; }
            }
            int i0 = bi;
            int slot = g_slotOf[i0];
            int n1 = g_n1[slot];
            const int*   c1i = g_c1idx  + (size_t)slot * NTOK;
            const float* c1b = g_c1base + (size_t)slot * NTOK;
            bs = 3.4e38f; bi = 0; float bd1 = 0.f, bb1 = 0.f; int bj = 0;
            for (int j = 0; j < n1; j++) {
                int c = c1i[j]; float base = c1b[j];
                float2 cv = ((const float2*)(g_Chat + (size_t)(NTOK + c) * 64))[lane];
                float p = fmaf(h.x, cv.x, h.y * cv.y);
                #pragma unroll
                for (int o = 16; o; o >>= 1) p += __shfl_xor_sync(0xffffffffu, p, o);
                float s = fmaf(-2.f, p, base);
                if (s < bs) { bs = s; bi = c; bd1 = p; bb1 = base; bj = j; }
            }
            int i1 = bi;
            if (lane == 0) {
                g_i0[t] = i0; g_i1[t] = i1;
                g_pid[t] = slot * NTOK + bj;
                didx[2 * t] = (float)i0; didx[2 * t + 1] = (float)i1;
                a_q0x += (double)bd0 + (double)g_bcv[i0];
                a_q1x += (double)bd1 + (double)g_bcv[NTOK + i1];
                a_c0  += (double)g_cn2[i0];
                a_c1  += (double)g_cn2[NTOK + i1];
                a_G   += 0.5 * ((double)bb1 - (double)g_gam[NTOK + i1]);
            }
        }
        if (lane == 0) {
            sm[w][0] = a_q0x; sm[w][1] = a_q1x; sm[w][2] = a_c0; sm[w][3] = a_c1; sm[w][4] = a_G;
        }
        __syncthreads();
        if (tid == 0) {
            double v0 = 0, v1 = 0, v2 = 0, v3 = 0, v4 = 0;
            #pragma unroll
            for (int i = 0; i < 8; i++) {
                v0 += sm[i][0]; v1 += sm[i][1]; v2 += sm[i][2]; v3 += sm[i][3]; v4 += sm[i][4];
            }
            atomicAdd(&g_acc[0], v0); atomicAdd(&g_acc[1], v1);
            atomicAdd(&g_acc[3], v2); atomicAdd(&g_acc[4], v3);
            atomicAdd(&g_acc[5], v4);
        }
    } else {
        // ---------------- pair table ----------------
        int vv = b - 1632;
        int s = vv >> 4, jstart = vv & 15;
        if (s >= g_n0) return;
        float (*Wts)[128] = (float(*)[128])(sbuf);              // 32768B
        float (*d1s)[64]  = (float(*)[64])(sbuf + 32768);       // 512B
        float* bd1s = (float*)(sbuf + 33280);
        float* bd2s = (float*)(sbuf + 33792);
        float* w3s  = (float*)(sbuf + 34304);
        float* sred = (float*)(sbuf + 34560);
        for (int e = tid; e < 8192; e += 256) {
            int n = e >> 6, c = e & 63;
            Wts[c][n] = g_Wd2m[e];
        }
        if (tid < 128) { bd1s[tid] = g_bd1x[tid]; bd2s[tid] = g_bd2x[tid]; }
        if (tid < 64) w3s[tid] = W3[tid];
        const float b3v = b3[0];
        const int n1 = g_n1[s];
        const int i0 = g_cand0[s];
        const float* P0r = g_P0 + (size_t)i0 * 128;
        __syncthreads();

        const int p = tid >> 7, n = tid & 127;
        for (int j = jstart; j < n1; j += 16) {
            int i1 = g_c1idx[(size_t)s * NTOK + j];
            if (tid < 128)
                d1s[tid >> 6][tid & 63] =
                    fmaxf(P0r[tid] + g_P1[(size_t)i1 * 128 + tid] + bd1s[tid], 0.f);
            __syncthreads();
            float v = bd2s[n];
            #pragma unroll 16
            for (int c = 0; c < 64; c++) v = fmaf(d1s[p][c], Wts[c][n], v);
            v = fmaxf(v, 0.f) * w3s[n & 63];
            sred[tid] = v;
            __syncthreads();
            if ((tid & 63) < 32) {
                float x = sred[tid] + sred[tid + 32];
                #pragma unroll
                for (int o = 16; o; o >>= 1) x += __shfl_down_sync(0xffffffffu, x, o);
                if ((tid & 63) == 0)
                    g_ptab[((size_t)s * NTOK + j) * 4 + (tid >> 6)] = x + b3v;
            }
            __syncthreads();
        }
    }
}

// =================== MEGA 2: qout | out | Spart ===================================
__global__ void __launch_bounds__(256) k_mega2(const float* __restrict__ cb,
                                               const float* __restrict__ img,
                                               float* __restrict__ dout) {
    __shared__ __align__(16) char sbuf[27744];
    const int tid = threadIdx.x;
    const int b = blockIdx.x;

    if (b < 8192) {
        // ---------------- quantized output, tiled transpose ----------------
        float* sq = (float*)sbuf;                 // 408*17 floats
        const int d0 = (b & 31) * 16;
        const int bb = b >> 5;
        for (int tt = tid; tt < T2; tt += 256) {
            int tok = bb * T2 + tt;
            const float4* r0 = (const float4*)(cb + (size_t)g_i0[tok] * CBD + d0);
            const float4* r1 = (const float4*)(cb + ((size_t)NTOK + g_i1[tok]) * CBD + d0);
            #pragma unroll
            for (int q = 0; q < 4; q++) {
                float4 a = r0[q], c = r1[q];
                sq[tt * 17 + q * 4 + 0] = a.x + c.x;
                sq[tt * 17 + q * 4 + 1] = a.y + c.y;
                sq[tt * 17 + q * 4 + 2] = a.z + c.z;
                sq[tt * 17 + q * 4 + 3] = a.w + c.w;
            }
        }
        __syncthreads();
        const int w = tid >> 5, lane = tid & 31;
        #pragma unroll
        for (int it = 0; it < 2; it++) {
            int d = it * 8 + w;
            size_t base = QOFF + ((size_t)bb * CBD + d0 + d) * T2;
            #pragma unroll
            for (int j = 0; j < 13; j++) {
                int t = j * 32 + lane;
                if (t < T2) dout[base + t] = sq[t * 17 + d];
            }
        }
    } else if (b < 8600) {
        // ---------------- decoder output gather + recon loss ----------------
        double* sd = (double*)sbuf;
        int tok = (b - 8192) * 256 + tid;
        int pid = g_pid[tok];
        float4 v = ((const float4*)g_ptab)[pid];
        int bb = tok / T2, t2 = tok - bb * T2;
        size_t o = (size_t)bb * TT + 4 * t2;
        *(float4*)(dout + o) = v;
        float4 iv = *(const float4*)(img + o);
        float e0 = iv.x - v.x, e1 = iv.y - v.y, e2 = iv.z - v.z, e3 = iv.w - v.w;
        sd[tid] = (double)e0 * e0 + (double)e1 * e1 + (double)e2 * e2 + (double)e3 * e3;
        __syncthreads();
        for (int o2 = 128; o2; o2 >>= 1) {
            if (tid < o2) sd[tid] += sd[tid + o2];
            __syncthreads();
        }
        if (!tid) atomicAdd(&g_acc[2], sd[0]);
    } else {
        // ---------------- partial S = H2^T H2 (atomic accumulate) ----------------
        float* sh2 = (float*)sbuf;                // 8*64 floats
        int blk = b - 8600;
        int t0 = blk * 816;
        float acc[16];
        #pragma unroll
        for (int i = 0; i < 16; i++) acc[i] = 0.f;
        float hs = 0.f;
        int ti = tid >> 4, tj = tid & 15;
        for (int g = 0; g < 102; g++) {
            int base = t0 + g * 8;
            if (tid < 128)
                ((float4*)sh2)[tid] = ((const float4*)(g_H2 + (size_t)base * 64))[tid];
            __syncthreads();
            #pragma unroll
            for (int r = 0; r < 8; r++) {
                float4 a = *(const float4*)&sh2[r * 64 + ti * 4];
                float4 bq = *(const float4*)&sh2[r * 64 + tj * 4];
                float av[4] = {a.x, a.y, a.z, a.w}, bv[4] = {bq.x, bq.y, bq.z, bq.w};
                #pragma unroll
                for (int p = 0; p < 4; p++)
                    #pragma unroll
                    for (int q = 0; q < 4; q++) acc[p * 4 + q] = fmaf(av[p], bv[q], acc[p * 4 + q]);
            }
            if (tid < 64) {
                #pragma unroll
                for (int r = 0; r < 8; r++) hs += sh2[r * 64 + tid];
            }
            __syncthreads();
        }
        #pragma unroll
        for (int p = 0; p < 4; p++)
            #pragma unroll
            for (int q = 0; q < 4; q++)
                atomicAdd(&g_S[(ti * 4 + p) * 64 + (tj * 4 + q)], acc[p * 4 + q]);
        if (tid < 64) atomicAdd(&g_hsum[tid], hs);
    }
}

// ---------------- fin: Sfinal + scalars -------------------------------------------
__global__ void k_fin(float* __restrict__ dout) {
    __shared__ double red[256];
    int tid = threadIdx.x;
    double partial = 0.0;
    for (int c = tid; c < 4096; c += 256)
        partial += (double)g_S[c] * (double)g_M3[c];
    if (tid < 64) partial += 2.0 * (double)g_hsum[tid] * (double)g_w3b[tid];
    if (tid == 64) partial += (double)NTOKEN * (double)g_bb;
    red[tid] = partial; __syncthreads();
    for (int o = 128; o; o >>= 1) {
        if (tid < o) red[tid] += red[tid + o];
        __syncthreads();
    }
    if (tid == 0) {
        double xsq = red[0];
        double denom = (double)NTOKEN * CBD;
        double q0x = g_acc[0], q1x = g_acc[1], c0 = g_acc[3], c1 = g_acc[4];
        double G = g_acc[5];
        dout[OUT_N + 0] = (float)(g_acc[2] / (double)OUT_N);
        dout[OUT_N + 1] = (float)((c0 - 2.0 * q0x + xsq) / denom);
        dout[OUT_N + 2] = (float)((c0 + c1 + xsq + 2.0 * G - 2.0 * q0x - 2.0 * q1x) / denom);
    }
}

// ---------------- launch -----------------------------------------------------------
extern "C" void kernel_launch(void* const* d_in, const int* in_sizes, int n_in,
                              void* d_out, int out_size) {
    const float* img   = (const float*)d_in[0];
    const float* W_e1  = (const float*)d_in[1];
    const float* b_e1  = (const float*)d_in[2];
    const float* W_e2  = (const float*)d_in[3];
    const float* b_e2  = (const float*)d_in[4];
    const float* W_e3  = (const float*)d_in[5];
    const float* b_e3  = (const float*)d_in[6];
    const float* cb    = (const float*)d_in[7];
    const float* Wt_d1 = (const float*)d_in[8];
    const float* b_d1  = (const float*)d_in[9];
    const float* Wt_d2 = (const float*)d_in[10];
    const float* b_d2  = (const float*)d_in[11];
    const float* W_d3  = (const float*)d_in[12];
    const float* b_d3  = (const float*)d_in[13];
    float* out = (float*)d_out;

    k_prep <<<258, 256>>>(W_e2, W_e3, Wt_d1, Wt_d2, b_d1, b_d2);
    k_mega1<<<713, 256>>>(img, W_e1, b_e1, b_e2, cb, W_e3, b_e3);
    k_cand0<<<1, 256>>>();
    k_s1a  <<<dim3(8, NTOK), 256>>>(cb);
    k_s1b  <<<NTOK, 256>>>();
    k_mega3<<<1632 + 1024, 256>>>(W_d3, b_d3, out);
    k_mega2<<<8192 + 408 + 128, 256>>>(cb, img, out);
    k_fin  <<<1, 256>>>(out);
}